// round 8
// baseline (speedup 1.0000x reference)
#include <cuda_runtime.h>
#include <cuda_bf16.h>
#include <stdint.h>
#include <math.h>

// ===================== constants =====================
static const int B = 4;

// ===================== device scratch =====================
__device__ float g_feat[4L*195*512*32];      // fp32 feat (both stages)
__device__ float g_X  [4L*192*2048*32];
__device__ float g_X2 [4L*192*2048*32];
__device__ float g_cf [4L*192*512];
__device__ float g_maxR [4L*192*2048];
__device__ float g_maxR2[4L*192*2048];
__device__ float g_P2  [4L*192*2048];
__device__ int   g_idx [4*2048];
__device__ int   g_gidx[4*2048*32];
__device__ float g_mean[4*384], g_rstd[4*384], g_S[4*384], g_g[4*384];
__device__ float g_WL[4L*384*384];
__device__ __nv_bfloat16 g_WRhi[4L*384*384], g_WRlo[4L*384*384];   // padded [b, Mpad, O]
__device__ __nv_bfloat16 g_W1hi[384L*256],   g_W1lo[384L*256];     // stage1 w1 padded [384,256]

// ===================== small helpers =====================
__device__ __forceinline__ float dist2f(float ax,float ay,float az,float bx,float by,float bz){
    float dx=__fsub_rn(ax,bx), dy=__fsub_rn(ay,by), dz=__fsub_rn(az,bz);
    return __fadd_rn(__fadd_rn(__fmul_rn(dx,dx),__fmul_rn(dy,dy)),__fmul_rn(dz,dz));
}
__device__ __forceinline__ uint32_t smem_u32(const void* p){
    uint32_t a; asm("{ .reg .u64 t; cvta.to.shared.u64 t, %1; cvt.u32.u64 %0, t; }":"=r"(a):"l"(p));
    return a;
}
__device__ __forceinline__ void ldsm4(uint32_t* r, uint32_t addr){
    asm volatile("ldmatrix.sync.aligned.m8n8.x4.shared.b16 {%0,%1,%2,%3}, [%4];"
        :"=r"(r[0]),"=r"(r[1]),"=r"(r[2]),"=r"(r[3]):"r"(addr));
}
__device__ __forceinline__ void ldsm4t(uint32_t* r, uint32_t addr){
    asm volatile("ldmatrix.sync.aligned.m8n8.x4.trans.shared.b16 {%0,%1,%2,%3}, [%4];"
        :"=r"(r[0]),"=r"(r[1]),"=r"(r[2]),"=r"(r[3]):"r"(addr));
}
__device__ __forceinline__ void mma16816(float* d, const uint32_t* a, const uint32_t* b){
    asm volatile("mma.sync.aligned.m16n8k16.row.col.f32.bf16.bf16.f32 "
        "{%0,%1,%2,%3}, {%4,%5,%6,%7}, {%8,%9}, {%0,%1,%2,%3};"
        : "+f"(d[0]),"+f"(d[1]),"+f"(d[2]),"+f"(d[3])
        : "r"(a[0]),"r"(a[1]),"r"(a[2]),"r"(a[3]),"r"(b[0]),"r"(b[1]));
}
__device__ __forceinline__ void bf16split(float v, __nv_bfloat16& h, __nv_bfloat16& l){
    h = __float2bfloat16_rn(v);
    l = __float2bfloat16_rn(v - __bfloat162float(h));
}

// ===================== FPS (2-barrier, coords carried through reduction) =====================
template<int N, int M>
__global__ __launch_bounds__(1024) void fps_kernel(const float* __restrict__ p, int* __restrict__ outIdx)
{
    constexpr int NPT = N/1024;
    const int b = blockIdx.x, t = threadIdx.x;
    const float* pb = p + (long)b*N*3;
    float px[NPT],py[NPT],pz[NPT],dd[NPT];
#pragma unroll
    for(int j=0;j<NPT;j++){
        int gidx = t*NPT+j;
        px[j]=pb[3*gidx]; py[j]=pb[3*gidx+1]; pz[j]=pb[3*gidx+2];
        dd[j]=1e10f;
    }
    __shared__ float swv[32], swx[32], swy[32], swz[32];
    __shared__ int   swi[32];
    __shared__ float sc[3];
    if(t==0) outIdx[(long)b*M]=0;
    float lx=pb[0], ly=pb[1], lz=pb[2];
    for(int s=1;s<M;s++){
        float bv=-1e30f, bx=0.f, by=0.f, bz=0.f; int bi=0x7fffffff;
#pragma unroll
        for(int j=0;j<NPT;j++){
            float d = dist2f(px[j],py[j],pz[j],lx,ly,lz);
            float dm = fminf(dd[j], d);
            dd[j]=dm;
            if(dm>bv){ bv=dm; bi=t*NPT+j; bx=px[j]; by=py[j]; bz=pz[j]; }
        }
#pragma unroll
        for(int off=16;off>0;off>>=1){
            float ov=__shfl_down_sync(0xffffffffu,bv,off);
            int   oi=__shfl_down_sync(0xffffffffu,bi,off);
            float ox=__shfl_down_sync(0xffffffffu,bx,off);
            float oy=__shfl_down_sync(0xffffffffu,by,off);
            float oz=__shfl_down_sync(0xffffffffu,bz,off);
            if(ov>bv || (ov==bv && oi<bi)){ bv=ov; bi=oi; bx=ox; by=oy; bz=oz; }
        }
        if((t&31)==0){ swv[t>>5]=bv; swi[t>>5]=bi; swx[t>>5]=bx; swy[t>>5]=by; swz[t>>5]=bz; }
        __syncthreads();
        if(t<32){
            bv=swv[t]; bi=swi[t]; bx=swx[t]; by=swy[t]; bz=swz[t];
#pragma unroll
            for(int off=16;off>0;off>>=1){
                float ov=__shfl_down_sync(0xffffffffu,bv,off);
                int   oi=__shfl_down_sync(0xffffffffu,bi,off);
                float ox=__shfl_down_sync(0xffffffffu,bx,off);
                float oy=__shfl_down_sync(0xffffffffu,by,off);
                float oz=__shfl_down_sync(0xffffffffu,bz,off);
                if(ov>bv || (ov==bv && oi<bi)){ bv=ov; bi=oi; bx=ox; by=oy; bz=oz; }
            }
            if(t==0){ outIdx[(long)b*M+s]=bi; sc[0]=bx; sc[1]=by; sc[2]=bz; }
        }
        __syncthreads();
        lx=sc[0]; ly=sc[1]; lz=sc[2];
    }
}

// ===================== gather =====================
__global__ void gather_kernel(const float* __restrict__ p, const float* __restrict__ f,
                              const int* __restrict__ idx, float* __restrict__ cp,
                              float* __restrict__ cf, int N, int M, int C)
{
    int b = blockIdx.y;
    int i = blockIdx.x*blockDim.x + threadIdx.x;
    if(i>=M) return;
    int j = idx[(long)b*M+i];
    cp[((long)b*M+i)*3+0] = p[((long)b*N+j)*3+0];
    cp[((long)b*M+i)*3+1] = p[((long)b*N+j)*3+1];
    cp[((long)b*M+i)*3+2] = p[((long)b*N+j)*3+2];
    for(int c=0;c<C;c++)
        cf[((long)b*C+c)*M+i] = f[((long)b*C+c)*N+j];
}

// ===================== ball query =====================
template<int N>
__global__ void ballq_kernel(const float* __restrict__ pts, const float* __restrict__ ctr,
                             int* __restrict__ gidx, int M)
{
    extern __shared__ float4 sp[];
    int b = blockIdx.y;
    const float* pb = pts + (long)b*N*3;
    for(int j=threadIdx.x;j<N;j+=blockDim.x)
        sp[j] = make_float4(pb[3*j],pb[3*j+1],pb[3*j+2],0.f);
    __syncthreads();
    int i = blockIdx.x*blockDim.x + threadIdx.x;
    if(i>=M) return;
    float cx=ctr[((long)b*M+i)*3], cy=ctr[((long)b*M+i)*3+1], cz=ctr[((long)b*M+i)*3+2];
    int* out = gidx + ((long)b*M+i)*32;
    const float R2 = (float)(0.1*0.1);
    int cnt=0, first=0;
    for(int j=0;j<N;j++){
        float4 q = sp[j];
        float d2 = dist2f(cx,cy,cz,q.x,q.y,q.z);
        if(d2 < R2){
            if(cnt<32) out[cnt]=j;
            if(cnt==0) first=j;
            cnt++;
            if(cnt>=32) break;
        }
    }
    for(int k=cnt;k<32;k++) out[k]=first;
}

// ===================== feature build (fp32) =====================
__global__ void featbuild_kernel(const float* __restrict__ p, const float* __restrict__ f,
                                 const float* __restrict__ cp, const float* __restrict__ cf,
                                 const int* __restrict__ gidx, float* __restrict__ feat,
                                 int N, int M, int C)
{
    int b = blockIdx.y;
    int gi = blockIdx.x*blockDim.x + threadIdx.x;
    int i = gi>>5, kk = gi&31;
    if(i>=M) return;
    int j = gidx[((long)b*M+i)*32+kk];
    long CH = C+3;
    float dx = __fsub_rn(p[((long)b*N+j)*3+0], cp[((long)b*M+i)*3+0]);
    float dy = __fsub_rn(p[((long)b*N+j)*3+1], cp[((long)b*M+i)*3+1]);
    float dz = __fsub_rn(p[((long)b*N+j)*3+2], cp[((long)b*M+i)*3+2]);
    feat[(((long)b*CH+0)*M+i)*32+kk] = dx;
    feat[(((long)b*CH+1)*M+i)*32+kk] = dy;
    feat[(((long)b*CH+2)*M+i)*32+kk] = dz;
    const float* fb  = f  + (long)b*C*N;
    const float* cfb = cf + (long)b*C*M;
    for(int c=0;c<C;c++)
        feat[(((long)b*CH+3+c)*M+i)*32+kk] = __fsub_rn(fb[(long)c*N+j], cfb[(long)c*M+i]);
}

// ===================== FFMA SGEMM (small GEMMs: conv1 s0, P2) =====================
template<int BM, int MR>
__global__ __launch_bounds__(256) void sgemm2_kernel(
    const float* __restrict__ A, long aStride,
    const float* __restrict__ X, float* __restrict__ C,
    const float* __restrict__ bias,
    const float* __restrict__ nmean, const float* __restrict__ nrstd,
    int Msz, int Ksz, int Nsz)
{
    __shared__ float As[2][16][BM];
    __shared__ float Xs[2][16][128];
    constexpr int AL = BM/16;
    int b = blockIdx.z, m0 = blockIdx.y*BM, n0 = blockIdx.x*128;
    const float* Ab = A + (long)b*aStride;
    const float* Xb = X + (long)b*(long)Ksz*Nsz;
    const float* mp = nmean ? nmean + (long)b*Ksz : nullptr;
    const float* rp = nrstd ? nrstd + (long)b*Ksz : nullptr;
    int t = threadIdx.x, tx = t&15, ty = t>>4;
    float acc[MR][8];
#pragma unroll
    for(int r=0;r<MR;r++)
#pragma unroll
        for(int c=0;c<8;c++) acc[r][c]=0.f;
    float  aR[AL];
    float4 xR[2];
    int nk = (Ksz+15)>>4;
    auto LOAD = [&](int k0){
#pragma unroll
        for(int i=0;i<AL;i++){
            int e=t+i*256, m=e%BM, k=e/BM;
            aR[i] = (k0+k<Ksz) ? Ab[(long)(m0+m)*Ksz + k0+k] : 0.f;
        }
#pragma unroll
        for(int j=0;j<2;j++){
            int e=t+j*256, k=e>>5, n4=e&31;
            if(k0+k<Ksz){
                float4 v = *(const float4*)(Xb + (long)(k0+k)*Nsz + n0 + n4*4);
                if(mp){
                    float mn=mp[k0+k], rs=rp[k0+k];
                    v.x=fmaxf((v.x-mn)*rs,0.f); v.y=fmaxf((v.y-mn)*rs,0.f);
                    v.z=fmaxf((v.z-mn)*rs,0.f); v.w=fmaxf((v.w-mn)*rs,0.f);
                }
                xR[j]=v;
            } else xR[j]=make_float4(0.f,0.f,0.f,0.f);
        }
    };
    auto STORE = [&](int buf){
#pragma unroll
        for(int i=0;i<AL;i++){ int e=t+i*256; As[buf][e/BM][e%BM]=aR[i]; }
#pragma unroll
        for(int j=0;j<2;j++){ int e=t+j*256; *(float4*)&Xs[buf][e>>5][(e&31)*4] = xR[j]; }
    };
    auto COMP = [&](int buf){
#pragma unroll
        for(int kk=0;kk<16;kk++){
            float a[MR];
#pragma unroll
            for(int r=0;r<MR;r++) a[r]=As[buf][kk][ty*MR+r];
            float4 b0 = *(float4*)&Xs[buf][kk][tx*8];
            float4 b1 = *(float4*)&Xs[buf][kk][tx*8+4];
            float bb[8] = {b0.x,b0.y,b0.z,b0.w,b1.x,b1.y,b1.z,b1.w};
#pragma unroll
            for(int r=0;r<MR;r++)
#pragma unroll
                for(int c=0;c<8;c++) acc[r][c] += a[r]*bb[c];
        }
    };
    LOAD(0); STORE(0); __syncthreads();
    for(int kt=0;kt<nk;kt++){
        int cur=kt&1;
        if(kt+1<nk) LOAD((kt+1)*16);
        COMP(cur);
        if(kt+1<nk){ STORE(cur^1); __syncthreads(); }
    }
#pragma unroll
    for(int r=0;r<MR;r++){
        int row=m0+ty*MR+r, col=n0+tx*8;
        float o[8];
#pragma unroll
        for(int c=0;c<8;c++) o[c]=acc[r][c];
        if(bias){
            const float* bb = bias + ((long)b*Msz+row)*(Nsz>>5);
#pragma unroll
            for(int c=0;c<8;c++) o[c] += bb[(col+c)>>5];
        }
        *(float4*)&C[((long)b*Msz+row)*(long)Nsz+col]   = make_float4(o[0],o[1],o[2],o[3]);
        *(float4*)&C[((long)b*Msz+row)*(long)Nsz+col+4] = make_float4(o[4],o[5],o[6],o[7]);
    }
}

// ===================== mma.sync bf16 GEMM (fused norm+split B build) =====================
__global__ __launch_bounds__(256) void hmma_kernel(
    const __nv_bfloat16* __restrict__ Ahi, const __nv_bfloat16* __restrict__ Alo,
    long aStride, int Kpad,
    const float* __restrict__ X, const float* __restrict__ nmean, const float* __restrict__ nrstd,
    const float* __restrict__ bias, float* __restrict__ Cout,
    int Msz, int Ksz, int Nsz)
{
    extern __shared__ char sm[];
    const uint32_t oAhi=0, oAlo=16384, oBhi=32768, oBlo=49152;
    uint32_t sbase = smem_u32(sm);

    int t = threadIdx.x, lane = t&31, w = t>>5;
    int wm = (w&1)*64, wn = (w>>1)*32;
    int bz = blockIdx.z, m0 = blockIdx.y*128, n0 = blockIdx.x*128;
    const __nv_bfloat16* Ah = Ahi + (long)bz*aStride;
    const __nv_bfloat16* Al = Alo + (long)bz*aStride;
    const float* Xb = X + (long)bz*(long)Ksz*Nsz;

    float acc[4][4][4];
#pragma unroll
    for(int i=0;i<4;i++)
#pragma unroll
        for(int j=0;j<4;j++)
#pragma unroll
            for(int q=0;q<4;q++) acc[i][j][q]=0.f;

    int ar = t>>1, ah = t&1;          // A: row 0..127, 64B half
    int bk = t>>2, bn = (t&3)*32;     // B: k row 0..63, 32-float n block

    int nch = Kpad/64;
    for(int c=0;c<nch;c++){
        int k0 = c*64;
        // ---- A tiles (hi/lo), SW128 swizzle ----
        {
            const uint4* gh = (const uint4*)(Ah + (long)(m0+ar)*Kpad + k0 + ah*32);
            const uint4* gl = (const uint4*)(Al + (long)(m0+ar)*Kpad + k0 + ah*32);
#pragma unroll
            for(int q=0;q<4;q++){
                uint32_t off = (uint32_t)ar*128u + (uint32_t)ah*64u + (uint32_t)q*16u;
                uint32_t sw = off ^ ((off>>3)&0x70u);
                *(uint4*)(sm + oAhi + sw) = gh[q];
                *(uint4*)(sm + oAlo + sw) = gl[q];
            }
        }
        // ---- B tiles: X[k][n], act, bf16 split ----
        {
            int kg = k0 + bk;
            bool valid = (kg < Ksz);
            float mn=0.f, rs=1.f;
            bool doact = (nmean != nullptr);
            if(doact && valid){ mn = nmean[(long)bz*Ksz+kg]; rs = nrstd[(long)bz*Ksz+kg]; }
            const float4* xr = (const float4*)(Xb + (long)kg*Nsz + n0 + bn);
#pragma unroll
            for(int q=0;q<4;q++){
                float xv[8];
                if(valid){
                    float4 v0 = xr[q*2], v1 = xr[q*2+1];
                    xv[0]=v0.x; xv[1]=v0.y; xv[2]=v0.z; xv[3]=v0.w;
                    xv[4]=v1.x; xv[5]=v1.y; xv[6]=v1.z; xv[7]=v1.w;
                    if(doact){
#pragma unroll
                        for(int j=0;j<8;j++) xv[j]=fmaxf((xv[j]-mn)*rs,0.f);
                    }
                } else {
#pragma unroll
                    for(int j=0;j<8;j++) xv[j]=0.f;
                }
                uint32_t hw[4], lw[4];
#pragma unroll
                for(int pq=0;pq<4;pq++){
                    float a=xv[pq*2], b2=xv[pq*2+1];
                    __nv_bfloat16 ha,la,hb,lb;
                    bf16split(a,ha,la); bf16split(b2,hb,lb);
                    __nv_bfloat162 hp=__halves2bfloat162(ha,hb);
                    __nv_bfloat162 lp=__halves2bfloat162(la,lb);
                    hw[pq]=*(uint32_t*)&hp;
                    lw[pq]=*(uint32_t*)&lp;
                }
                uint32_t off = (uint32_t)bk*256u + (uint32_t)bn*2u + (uint32_t)q*16u;
                uint32_t sw = off ^ ((off>>4)&0xF0u);
                *(uint4*)(sm + oBhi + sw) = make_uint4(hw[0],hw[1],hw[2],hw[3]);
                *(uint4*)(sm + oBlo + sw) = make_uint4(lw[0],lw[1],lw[2],lw[3]);
            }
        }
        __syncthreads();
#pragma unroll
        for(int kk=0;kk<4;kk++){
            uint32_t afh[4][4], afl[4][4];
#pragma unroll
            for(int mi=0;mi<4;mi++){
                uint32_t off = (uint32_t)(wm+mi*16+(lane&15))*128u + (uint32_t)kk*32u + (uint32_t)(lane>>4)*16u;
                uint32_t sw = off ^ ((off>>3)&0x70u);
                ldsm4(afh[mi], sbase + oAhi + sw);
                ldsm4(afl[mi], sbase + oAlo + sw);
            }
            uint32_t bfh[2][4], bfl[2][4];
#pragma unroll
            for(int nj=0;nj<2;nj++){
                uint32_t off = (uint32_t)(kk*16+(lane&15))*256u + (uint32_t)(wn+nj*16+(lane>>4)*8)*2u;
                uint32_t sw = off ^ ((off>>4)&0xF0u);
                ldsm4t(bfh[nj], sbase + oBhi + sw);
                ldsm4t(bfl[nj], sbase + oBlo + sw);
            }
#pragma unroll
            for(int mi=0;mi<4;mi++){
#pragma unroll
                for(int n8=0;n8<4;n8++){
                    const uint32_t* bh = &bfh[n8>>1][(n8&1)*2];
                    const uint32_t* bl = &bfl[n8>>1][(n8&1)*2];
                    mma16816(acc[mi][n8], afh[mi], bh);
                    mma16816(acc[mi][n8], afh[mi], bl);
                    mma16816(acc[mi][n8], afl[mi], bh);
                }
            }
        }
        __syncthreads();
    }

    int rbase = m0 + wm + (lane>>2);
    int cbase = n0 + wn + (lane&3)*2;
    int bcol = (n0 + wn) >> 5;
#pragma unroll
    for(int mi=0;mi<4;mi++){
        int r1 = rbase + mi*16;
        int r2 = r1 + 8;
        float bv1=0.f, bv2=0.f;
        if(bias){
            if(r1<Msz) bv1 = bias[((long)bz*Msz+r1)*(Nsz>>5) + bcol];
            if(r2<Msz) bv2 = bias[((long)bz*Msz+r2)*(Nsz>>5) + bcol];
        }
#pragma unroll
        for(int n8=0;n8<4;n8++){
            int col = cbase + n8*8;
            if(r1<Msz){
                float2 v = make_float2(acc[mi][n8][0]+bv1, acc[mi][n8][1]+bv1);
                *(float2*)&Cout[((long)bz*Msz+r1)*(long)Nsz+col] = v;
            }
            if(r2<Msz){
                float2 v = make_float2(acc[mi][n8][2]+bv2, acc[mi][n8][3]+bv2);
                *(float2*)&Cout[((long)bz*Msz+r2)*(long)Nsz+col] = v;
            }
        }
    }
}

// ===================== reductions =====================
__device__ __forceinline__ void blockReduce2(float& a, float& bsum){
    __shared__ float sa[32], sb[32];
    unsigned mm=0xffffffffu;
    for(int o=16;o;o>>=1){ a+=__shfl_down_sync(mm,a,o); bsum+=__shfl_down_sync(mm,bsum,o); }
    int w=threadIdx.x>>5, l=threadIdx.x&31;
    if(l==0){ sa[w]=a; sb[w]=bsum; }
    __syncthreads();
    int nw=(blockDim.x+31)>>5;
    if(threadIdx.x<32){
        a    = (threadIdx.x<nw)?sa[threadIdx.x]:0.f;
        bsum = (threadIdx.x<nw)?sb[threadIdx.x]:0.f;
        for(int o=16;o;o>>=1){ a+=__shfl_down_sync(mm,a,o); bsum+=__shfl_down_sync(mm,bsum,o); }
    }
}

__global__ void stats_kernel(const float* __restrict__ X, float* __restrict__ mean,
                             float* __restrict__ rstd, float* __restrict__ maxRaw, int M)
{
    int bo = blockIdx.x;
    const float* xb = X + (long)bo*M*32;
    float s=0.f, s2=0.f;
    for(int i=threadIdx.x;i<M;i+=blockDim.x){
        const float4* row = (const float4*)(xb + (long)i*32);
        float mx=-1e30f;
#pragma unroll
        for(int q=0;q<8;q++){
            float4 v = row[q];
            s  += v.x+v.y+v.z+v.w;
            s2 += v.x*v.x+v.y*v.y+v.z*v.z+v.w*v.w;
            mx = fmaxf(mx, fmaxf(fmaxf(v.x,v.y), fmaxf(v.z,v.w)));
        }
        maxRaw[(long)bo*M+i]=mx;
    }
    blockReduce2(s,s2);
    if(threadIdx.x==0){
        float Cnt = (float)(M*32);
        float mn = s/Cnt;
        float var = s2/Cnt - mn*mn;
        mean[bo]=mn;
        rstd[bo]=rsqrtf(var+1e-5f);
    }
}

__global__ void spass_kernel(const float* __restrict__ X, const float* __restrict__ mean,
                             const float* __restrict__ rstd, float* __restrict__ S, int Cnt)
{
    int bo = blockIdx.x;
    float mn=mean[bo], rs=rstd[bo];
    const float4* xb = (const float4*)(X + (long)bo*Cnt);
    float s=0.f;
    for(int i=threadIdx.x;i<(Cnt>>2);i+=blockDim.x){
        float4 v = xb[i];
        s += fmaxf((v.x-mn)*rs,0.f)+fmaxf((v.y-mn)*rs,0.f)
           + fmaxf((v.z-mn)*rs,0.f)+fmaxf((v.w-mn)*rs,0.f);
    }
    float d=0.f;
    blockReduce2(s,d);
    if(threadIdx.x==0) S[bo]=s;
}

__global__ void attn_kernel(const float* __restrict__ S, const float* __restrict__ w1,
                            const float* __restrict__ w2, float* __restrict__ g,
                            int O, int H, int Cnt)
{
    int b = blockIdx.x, t = threadIdx.x;
    __shared__ float ss[384], hh[96];
    if(t<O) ss[t] = S[(long)b*O+t] / (float)Cnt;
    __syncthreads();
    if(t<H){
        float a=0.f;
        for(int o=0;o<O;o++) a += w1[(long)t*O+o]*ss[o];
        hh[t]=fmaxf(a,0.f);
    }
    __syncthreads();
    if(t<O){
        float a=0.f;
        for(int j=0;j<H;j++) a += w2[(long)t*H+j]*hh[j];
        g[(long)b*O+t] = 1.f/(1.f+expf(-a));
    }
}

__global__ void wprep_kernel(const float* __restrict__ w2, const float* __restrict__ g,
                             float* __restrict__ WL, __nv_bfloat16* __restrict__ WRhi,
                             __nv_bfloat16* __restrict__ WRlo, int O, int Mpad)
{
    int b = blockIdx.y;
    int e = blockIdx.x*blockDim.x + threadIdx.x;
    if(e>=Mpad*O) return;
    int o=e/O, c=e%O;
    float vr = 0.f;
    if(o<O){
        float gg = g[(long)b*O+c];
        WL[(long)b*O*O + (long)o*O + c] = __fmul_rn(w2[(long)o*2*O + c], gg);
        vr = __fmul_rn(w2[(long)o*2*O + O + c], gg);
    }
    __nv_bfloat16 h,l; bf16split(vr,h,l);
    WRhi[(long)b*Mpad*O+e] = h;
    WRlo[(long)b*Mpad*O+e] = l;
}

__global__ void wsplit_kernel(const float* __restrict__ w, __nv_bfloat16* __restrict__ hi,
                              __nv_bfloat16* __restrict__ lo, int O, int K, int Mpad, int Kpad)
{
    int e = blockIdx.x*blockDim.x + threadIdx.x;
    if(e>=Mpad*Kpad) return;
    int r=e/Kpad, c=e%Kpad;
    float v = (r<O && c<K) ? w[(long)r*K+c] : 0.f;
    __nv_bfloat16 h,l; bf16split(v,h,l);
    hi[e]=h; lo[e]=l;
}

__global__ void final_kernel(const float* __restrict__ maxRaw2, const float* __restrict__ mean,
                             const float* __restrict__ rstd, const float* __restrict__ g,
                             float* __restrict__ out, long total, int Mctr)
{
    long e = (long)blockIdx.x*blockDim.x + threadIdx.x;
    if(e>=total) return;
    long bo = e/Mctr;
    float y = fmaxf((maxRaw2[e]-mean[bo])*rstd[bo], 0.f);
    out[e] = __fmul_rn(g[bo], y);
}

// ===================== host-side drivers =====================
static const int HM_SMEM = 65536;

template<int BM, int MR>
static void run_stage_gemms(int M, int C, int O, int H, int Mpad, int stage,
                      const float* w1, const float* a1w1, const float* a1w2,
                      const float* w2, const float* a2w1, const float* a2w2,
                      float* f_out,
                      float* feat, float* X, float* X2,
                      float* maxR, float* maxR2, float* P2,
                      float* mean, float* rstd, float* S, float* gAtt,
                      float* WL, __nv_bfloat16* WRhi, __nv_bfloat16* WRlo,
                      __nv_bfloat16* W1hi, __nv_bfloat16* W1lo)
{
    int NN = M*32;
    if(stage==0){
        sgemm2_kernel<BM,MR><<<dim3(NN/128,O/BM,B),256>>>(w1,0,feat,X,nullptr,nullptr,nullptr,O,C+3,NN);
    } else {
        hmma_kernel<<<dim3(NN/128,Mpad/128,B),256,HM_SMEM>>>(
            W1hi, W1lo, 0, 256, feat, nullptr, nullptr, nullptr, X, O, C+3, NN);
    }
    stats_kernel<<<B*O,256>>>(X, mean, rstd, maxR, M);
    spass_kernel<<<B*O,256>>>(X, mean, rstd, S, NN);
    attn_kernel<<<B,384>>>(S, a1w1, a1w2, gAtt, O, H, NN);
    wprep_kernel<<<dim3((Mpad*O+255)/256,B),256>>>(w2, gAtt, WL, WRhi, WRlo, O, Mpad);
    sgemm2_kernel<BM,MR><<<dim3(M/128,O/BM,B),256>>>(WL,(long)O*O,maxR,P2,nullptr,mean,rstd,O,O,M);
    hmma_kernel<<<dim3(NN/128,Mpad/128,B),256,HM_SMEM>>>(
        WRhi, WRlo, (long)Mpad*O, O, X, mean, rstd, P2, X2, O, O, NN);
    stats_kernel<<<B*O,256>>>(X2, mean, rstd, maxR2, M);
    spass_kernel<<<B*O,256>>>(X2, mean, rstd, S, NN);
    attn_kernel<<<B,384>>>(S, a2w1, a2w2, gAtt, O, H, NN);
    final_kernel<<<(int)(((long)B*O*M+255)/256),256>>>(maxR2, mean, rstd, gAtt, f_out, (long)B*O*M, M);
}

extern "C" void kernel_launch(void* const* d_in, const int* in_sizes, int n_in,
                              void* d_out, int out_size)
{
    const float* p      = (const float*)d_in[0];
    const float* f      = (const float*)d_in[1];
    const float* s0_w1  = (const float*)d_in[2];
    const float* s0_a1w1= (const float*)d_in[3];
    const float* s0_a1w2= (const float*)d_in[4];
    const float* s0_w2  = (const float*)d_in[5];
    const float* s0_a2w1= (const float*)d_in[6];
    const float* s0_a2w2= (const float*)d_in[7];
    const float* s1_w1  = (const float*)d_in[8];
    const float* s1_a1w1= (const float*)d_in[9];
    const float* s1_a1w2= (const float*)d_in[10];
    const float* s1_w2  = (const float*)d_in[11];
    const float* s1_a2w1= (const float*)d_in[12];
    const float* s1_a2w2= (const float*)d_in[13];

    float* out   = (float*)d_out;
    float* o_p   = out;
    float* o_cp1 = out + 98304;
    float* o_cp2 = out + 122880;
    float* o_f   = out + 129024;
    float* o_f1  = out + 227328;
    float* o_f2  = out + 1800192;

    cudaFuncSetAttribute(ballq_kernel<8192>, cudaFuncAttributeMaxDynamicSharedMemorySize, 8192*16);
    cudaFuncSetAttribute(hmma_kernel, cudaFuncAttributeMaxDynamicSharedMemorySize, HM_SMEM);

    void *vfeat,*vX,*vX2,*vcf,*vmr,*vmr2,*vp2,*vidx,*vgidx,*vmean,*vrstd,*vS,*vg,*vwl,*vwrh,*vwrl,*vw1h,*vw1l;
    cudaGetSymbolAddress(&vfeat, g_feat);
    cudaGetSymbolAddress(&vX,    g_X);
    cudaGetSymbolAddress(&vX2,   g_X2);
    cudaGetSymbolAddress(&vcf,   g_cf);
    cudaGetSymbolAddress(&vmr,   g_maxR);
    cudaGetSymbolAddress(&vmr2,  g_maxR2);
    cudaGetSymbolAddress(&vp2,   g_P2);
    cudaGetSymbolAddress(&vidx,  g_idx);
    cudaGetSymbolAddress(&vgidx, g_gidx);
    cudaGetSymbolAddress(&vmean, g_mean);
    cudaGetSymbolAddress(&vrstd, g_rstd);
    cudaGetSymbolAddress(&vS,    g_S);
    cudaGetSymbolAddress(&vg,    g_g);
    cudaGetSymbolAddress(&vwl,   g_WL);
    cudaGetSymbolAddress(&vwrh,  g_WRhi);
    cudaGetSymbolAddress(&vwrl,  g_WRlo);
    cudaGetSymbolAddress(&vw1h,  g_W1hi);
    cudaGetSymbolAddress(&vw1l,  g_W1lo);

    // ---- launch head: 5 independent launches so fps_kernel is ncu launch #5 ----
    wsplit_kernel<<<(384*256+255)/256,256>>>(s1_w1,(__nv_bfloat16*)vw1h,(__nv_bfloat16*)vw1l,
        384, 195, 384, 256);                                                     // 0
    cudaMemcpyAsync(o_p,         p,         49152*sizeof(float), cudaMemcpyDeviceToDevice, 0); // 1
    cudaMemcpyAsync(o_p + 49152, p + 49152, 49152*sizeof(float), cudaMemcpyDeviceToDevice, 0); // 2
    cudaMemcpyAsync(o_f,         f,         49152*sizeof(float), cudaMemcpyDeviceToDevice, 0); // 3
    cudaMemcpyAsync(o_f + 49152, f + 49152, 49152*sizeof(float), cudaMemcpyDeviceToDevice, 0); // 4

    // ---------- stage 0: N=8192 -> M=2048, C=3, O=192 (Mpad 256), H=48 ----------
    {
        int N=8192, M=2048, C=3;
        fps_kernel<8192,2048><<<B,1024>>>(p, (int*)vidx);                        // 5 <- profiled
        gather_kernel<<<dim3(M/256,B),256>>>(p,f,(int*)vidx,o_cp1,(float*)vcf,N,M,C);
        ballq_kernel<8192><<<dim3(M/128,B),128,8192*16>>>(p,o_cp1,(int*)vgidx,M);
        featbuild_kernel<<<dim3(M*32/256,B),256>>>(p,f,o_cp1,(float*)vcf,(int*)vgidx,(float*)vfeat,N,M,C);
        run_stage_gemms<96,6>(M,C,192,48,256,0,
            s0_w1,s0_a1w1,s0_a1w2,s0_w2,s0_a2w1,s0_a2w2, o_f1,
            (float*)vfeat,(float*)vX,(float*)vX2,(float*)vmr,(float*)vmr2,(float*)vp2,
            (float*)vmean,(float*)vrstd,(float*)vS,(float*)vg,
            (float*)vwl,(__nv_bfloat16*)vwrh,(__nv_bfloat16*)vwrl,
            (__nv_bfloat16*)vw1h,(__nv_bfloat16*)vw1l);
    }
    // ---------- stage 1: N=2048 -> M=512, C=192, O=384 (Mpad 384), H=96 ----------
    {
        int N=2048, M=512, C=192;
        fps_kernel<2048,512><<<B,1024>>>(o_cp1, (int*)vidx);
        gather_kernel<<<dim3(M/256,B),256>>>(o_cp1,o_f1,(int*)vidx,o_cp2,(float*)vcf,N,M,C);
        ballq_kernel<2048><<<dim3(M/128,B),128,2048*16>>>(o_cp1,o_cp2,(int*)vgidx,M);
        featbuild_kernel<<<dim3(M*32/256,B),256>>>(o_cp1,o_f1,o_cp2,(float*)vcf,(int*)vgidx,(float*)vfeat,N,M,C);
        run_stage_gemms<128,8>(M,C,384,96,384,1,
            s1_w1,s1_a1w1,s1_a1w2,s1_w2,s1_a2w1,s1_a2w2, o_f2,
            (float*)vfeat,(float*)vX,(float*)vX2,(float*)vmr,(float*)vmr2,(float*)vp2,
            (float*)vmean,(float*)vrstd,(float*)vS,(float*)vg,
            (float*)vwl,(__nv_bfloat16*)vwrh,(__nv_bfloat16*)vwrl,
            (__nv_bfloat16*)vw1h,(__nv_bfloat16*)vw1l);
    }
}

// round 9
// speedup vs baseline: 1.1577x; 1.1577x over previous
#include <cuda_runtime.h>
#include <cuda_bf16.h>
#include <stdint.h>
#include <math.h>

// ===================== constants =====================
static const int B = 4;

// ===================== device scratch =====================
__device__ float g_feat[4L*195*512*32];
__device__ float g_X  [4L*192*2048*32];
__device__ float g_X2 [4L*192*2048*32];
__device__ float g_cf [4L*192*512];
__device__ float g_maxR [4L*192*2048];
__device__ float g_maxR2[4L*192*2048];
__device__ float g_P2  [4L*192*2048];
__device__ int   g_idx [4*2048];
__device__ int   g_gidx[4*2048*32];
__device__ float g_mean[4*384], g_rstd[4*384], g_S[4*384], g_g[4*384];
__device__ float g_WL[4L*384*384];
__device__ __nv_bfloat16 g_WRhi[4L*384*384], g_WRlo[4L*384*384];
__device__ __nv_bfloat16 g_W1hi[384L*256],   g_W1lo[384L*256];

// ===================== small helpers =====================
__device__ __forceinline__ float dist2f(float ax,float ay,float az,float bx,float by,float bz){
    float dx=__fsub_rn(ax,bx), dy=__fsub_rn(ay,by), dz=__fsub_rn(az,bz);
    return __fadd_rn(__fadd_rn(__fmul_rn(dx,dx),__fmul_rn(dy,dy)),__fmul_rn(dz,dz));
}
__device__ __forceinline__ uint32_t smem_u32(const void* p){
    uint32_t a; asm("{ .reg .u64 t; cvta.to.shared.u64 t, %1; cvt.u32.u64 %0, t; }":"=r"(a):"l"(p));
    return a;
}
__device__ __forceinline__ void ldsm4(uint32_t* r, uint32_t addr){
    asm volatile("ldmatrix.sync.aligned.m8n8.x4.shared.b16 {%0,%1,%2,%3}, [%4];"
        :"=r"(r[0]),"=r"(r[1]),"=r"(r[2]),"=r"(r[3]):"r"(addr));
}
__device__ __forceinline__ void ldsm4t(uint32_t* r, uint32_t addr){
    asm volatile("ldmatrix.sync.aligned.m8n8.x4.trans.shared.b16 {%0,%1,%2,%3}, [%4];"
        :"=r"(r[0]),"=r"(r[1]),"=r"(r[2]),"=r"(r[3]):"r"(addr));
}
__device__ __forceinline__ void mma16816(float* d, const uint32_t* a, const uint32_t* b){
    asm volatile("mma.sync.aligned.m16n8k16.row.col.f32.bf16.bf16.f32 "
        "{%0,%1,%2,%3}, {%4,%5,%6,%7}, {%8,%9}, {%0,%1,%2,%3};"
        : "+f"(d[0]),"+f"(d[1]),"+f"(d[2]),"+f"(d[3])
        : "r"(a[0]),"r"(a[1]),"r"(a[2]),"r"(a[3]),"r"(b[0]),"r"(b[1]));
}
__device__ __forceinline__ void bf16split(float v, __nv_bfloat16& h, __nv_bfloat16& l){
    h = __float2bfloat16_rn(v);
    l = __float2bfloat16_rn(v - __bfloat162float(h));
}

// ===================== FPS (R5 3-barrier version — proven fastest) =====================
template<int N, int M>
__global__ __launch_bounds__(1024) void fps_kernel(const float* __restrict__ p, int* __restrict__ outIdx)
{
    constexpr int NPT = N/1024;
    const int b = blockIdx.x, t = threadIdx.x;
    const float* pb = p + (long)b*N*3;
    float px[NPT],py[NPT],pz[NPT],dd[NPT];
#pragma unroll
    for(int j=0;j<NPT;j++){
        int gidx = t*NPT+j;
        px[j]=pb[3*gidx]; py[j]=pb[3*gidx+1]; pz[j]=pb[3*gidx+2];
        dd[j]=1e10f;
    }
    __shared__ float swv[32];
    __shared__ int   swi[32];
    __shared__ float sc[3];
    __shared__ int   sBi;
    if(t==0){ outIdx[(long)b*M]=0; sc[0]=pb[0]; sc[1]=pb[1]; sc[2]=pb[2]; }
    __syncthreads();
    float lx=sc[0], ly=sc[1], lz=sc[2];
    for(int s=1;s<M;s++){
        float bv=-1e30f; int bi=0x7fffffff;
#pragma unroll
        for(int j=0;j<NPT;j++){
            float d = dist2f(px[j],py[j],pz[j],lx,ly,lz);
            float dm = fminf(dd[j], d);
            dd[j]=dm;
            if(dm>bv){ bv=dm; bi=t*NPT+j; }
        }
#pragma unroll
        for(int off=16;off>0;off>>=1){
            float ov=__shfl_down_sync(0xffffffffu,bv,off);
            int   oi=__shfl_down_sync(0xffffffffu,bi,off);
            if(ov>bv || (ov==bv && oi<bi)){ bv=ov; bi=oi; }
        }
        if((t&31)==0){ swv[t>>5]=bv; swi[t>>5]=bi; }
        __syncthreads();
        if(t<32){
            bv=swv[t]; bi=swi[t];
#pragma unroll
            for(int off=16;off>0;off>>=1){
                float ov=__shfl_down_sync(0xffffffffu,bv,off);
                int   oi=__shfl_down_sync(0xffffffffu,bi,off);
                if(ov>bv || (ov==bv && oi<bi)){ bv=ov; bi=oi; }
            }
            if(t==0){ sBi=bi; outIdx[(long)b*M+s]=bi; }
        }
        __syncthreads();
        int w = sBi;
        if(t == w/NPT){ int j=w-t*NPT; sc[0]=px[j]; sc[1]=py[j]; sc[2]=pz[j]; }
        __syncthreads();
        lx=sc[0]; ly=sc[1]; lz=sc[2];
    }
}

// ===================== gather =====================
__global__ void gather_kernel(const float* __restrict__ p, const float* __restrict__ f,
                              const int* __restrict__ idx, float* __restrict__ cp,
                              float* __restrict__ cf, int N, int M, int C)
{
    int b = blockIdx.y;
    int i = blockIdx.x*blockDim.x + threadIdx.x;
    if(i>=M) return;
    int j = idx[(long)b*M+i];
    cp[((long)b*M+i)*3+0] = p[((long)b*N+j)*3+0];
    cp[((long)b*M+i)*3+1] = p[((long)b*N+j)*3+1];
    cp[((long)b*M+i)*3+2] = p[((long)b*N+j)*3+2];
    for(int c=0;c<C;c++)
        cf[((long)b*C+c)*M+i] = f[((long)b*C+c)*N+j];
}

// ===================== ball query v2: warp-per-center, ballot compaction =====================
// CPB centers per block (8 warps -> CPB/8 centers per warp, scanned sequentially).
template<int N, int CPB>
__global__ __launch_bounds__(256) void ballq2_kernel(
    const float* __restrict__ pts, const float* __restrict__ ctr,
    int* __restrict__ gidx, int M)
{
    extern __shared__ float4 sp[];
    int b = blockIdx.y;
    const float* pb = pts + (long)b*N*3;
    for(int j=threadIdx.x;j<N;j+=blockDim.x)
        sp[j] = make_float4(pb[3*j],pb[3*j+1],pb[3*j+2],0.f);
    __syncthreads();
    int wid = threadIdx.x>>5, lane = threadIdx.x&31;
    constexpr int CPW = CPB/8;
    int base = blockIdx.x*CPB + wid*CPW;
    const float R2 = (float)(0.1*0.1);
    for(int c=0;c<CPW;c++){
        int i = base + c;
        float cx=ctr[((long)b*M+i)*3], cy=ctr[((long)b*M+i)*3+1], cz=ctr[((long)b*M+i)*3+2];
        int* out = gidx + ((long)b*M+i)*32;
        int cnt=0, first=0;
        for(int j0=0;j0<N;j0+=32){
            float4 q = sp[j0+lane];
            float d2 = dist2f(cx,cy,cz,q.x,q.y,q.z);
            bool in = (d2 < R2);
            unsigned mask = __ballot_sync(0xffffffffu, in);
            if(mask){
                if(cnt==0) first = j0 + __ffs(mask) - 1;
                int pos = cnt + __popc(mask & ((1u<<lane)-1u));
                if(in && pos<32) out[pos] = j0+lane;
                cnt += __popc(mask);
                if(cnt>=32) break;
            }
        }
        if(cnt<32){
            for(int k=cnt+lane;k<32;k+=32) out[k]=first;
        }
    }
}

// ===================== feature build (fp32) =====================
__global__ void featbuild_kernel(const float* __restrict__ p, const float* __restrict__ f,
                                 const float* __restrict__ cp, const float* __restrict__ cf,
                                 const int* __restrict__ gidx, float* __restrict__ feat,
                                 int N, int M, int C)
{
    int b = blockIdx.y;
    int gi = blockIdx.x*blockDim.x + threadIdx.x;
    int i = gi>>5, kk = gi&31;
    if(i>=M) return;
    int j = gidx[((long)b*M+i)*32+kk];
    long CH = C+3;
    float dx = __fsub_rn(p[((long)b*N+j)*3+0], cp[((long)b*M+i)*3+0]);
    float dy = __fsub_rn(p[((long)b*N+j)*3+1], cp[((long)b*M+i)*3+1]);
    float dz = __fsub_rn(p[((long)b*N+j)*3+2], cp[((long)b*M+i)*3+2]);
    feat[(((long)b*CH+0)*M+i)*32+kk] = dx;
    feat[(((long)b*CH+1)*M+i)*32+kk] = dy;
    feat[(((long)b*CH+2)*M+i)*32+kk] = dz;
    const float* fb  = f  + (long)b*C*N;
    const float* cfb = cf + (long)b*C*M;
    for(int c=0;c<C;c++)
        feat[(((long)b*CH+3+c)*M+i)*32+kk] = __fsub_rn(fb[(long)c*N+j], cfb[(long)c*M+i]);
}

// ===================== FFMA SGEMM (small GEMMs: conv1 s0, P2) =====================
template<int BM, int MR>
__global__ __launch_bounds__(256) void sgemm2_kernel(
    const float* __restrict__ A, long aStride,
    const float* __restrict__ X, float* __restrict__ C,
    const float* __restrict__ bias,
    const float* __restrict__ nmean, const float* __restrict__ nrstd,
    int Msz, int Ksz, int Nsz)
{
    __shared__ float As[2][16][BM];
    __shared__ float Xs[2][16][128];
    constexpr int AL = BM/16;
    int b = blockIdx.z, m0 = blockIdx.y*BM, n0 = blockIdx.x*128;
    const float* Ab = A + (long)b*aStride;
    const float* Xb = X + (long)b*(long)Ksz*Nsz;
    const float* mp = nmean ? nmean + (long)b*Ksz : nullptr;
    const float* rp = nrstd ? nrstd + (long)b*Ksz : nullptr;
    int t = threadIdx.x, tx = t&15, ty = t>>4;
    float acc[MR][8];
#pragma unroll
    for(int r=0;r<MR;r++)
#pragma unroll
        for(int c=0;c<8;c++) acc[r][c]=0.f;
    float  aR[AL];
    float4 xR[2];
    int nk = (Ksz+15)>>4;
    auto LOAD = [&](int k0){
#pragma unroll
        for(int i=0;i<AL;i++){
            int e=t+i*256, m=e%BM, k=e/BM;
            aR[i] = (k0+k<Ksz) ? Ab[(long)(m0+m)*Ksz + k0+k] : 0.f;
        }
#pragma unroll
        for(int j=0;j<2;j++){
            int e=t+j*256, k=e>>5, n4=e&31;
            if(k0+k<Ksz){
                float4 v = *(const float4*)(Xb + (long)(k0+k)*Nsz + n0 + n4*4);
                if(mp){
                    float mn=mp[k0+k], rs=rp[k0+k];
                    v.x=fmaxf((v.x-mn)*rs,0.f); v.y=fmaxf((v.y-mn)*rs,0.f);
                    v.z=fmaxf((v.z-mn)*rs,0.f); v.w=fmaxf((v.w-mn)*rs,0.f);
                }
                xR[j]=v;
            } else xR[j]=make_float4(0.f,0.f,0.f,0.f);
        }
    };
    auto STORE = [&](int buf){
#pragma unroll
        for(int i=0;i<AL;i++){ int e=t+i*256; As[buf][e/BM][e%BM]=aR[i]; }
#pragma unroll
        for(int j=0;j<2;j++){ int e=t+j*256; *(float4*)&Xs[buf][e>>5][(e&31)*4] = xR[j]; }
    };
    auto COMP = [&](int buf){
#pragma unroll
        for(int kk=0;kk<16;kk++){
            float a[MR];
#pragma unroll
            for(int r=0;r<MR;r++) a[r]=As[buf][kk][ty*MR+r];
            float4 b0 = *(float4*)&Xs[buf][kk][tx*8];
            float4 b1 = *(float4*)&Xs[buf][kk][tx*8+4];
            float bb[8] = {b0.x,b0.y,b0.z,b0.w,b1.x,b1.y,b1.z,b1.w};
#pragma unroll
            for(int r=0;r<MR;r++)
#pragma unroll
                for(int c=0;c<8;c++) acc[r][c] += a[r]*bb[c];
        }
    };
    LOAD(0); STORE(0); __syncthreads();
    for(int kt=0;kt<nk;kt++){
        int cur=kt&1;
        if(kt+1<nk) LOAD((kt+1)*16);
        COMP(cur);
        if(kt+1<nk){ STORE(cur^1); __syncthreads(); }
    }
#pragma unroll
    for(int r=0;r<MR;r++){
        int row=m0+ty*MR+r, col=n0+tx*8;
        float o[8];
#pragma unroll
        for(int c=0;c<8;c++) o[c]=acc[r][c];
        if(bias){
            const float* bb = bias + ((long)b*Msz+row)*(Nsz>>5);
#pragma unroll
            for(int c=0;c<8;c++) o[c] += bb[(col+c)>>5];
        }
        *(float4*)&C[((long)b*Msz+row)*(long)Nsz+col]   = make_float4(o[0],o[1],o[2],o[3]);
        *(float4*)&C[((long)b*Msz+row)*(long)Nsz+col+4] = make_float4(o[4],o[5],o[6],o[7]);
    }
}

// ===================== mma.sync bf16 GEMM (fused norm+split B build) =====================
__global__ __launch_bounds__(256) void hmma_kernel(
    const __nv_bfloat16* __restrict__ Ahi, const __nv_bfloat16* __restrict__ Alo,
    long aStride, int Kpad,
    const float* __restrict__ X, const float* __restrict__ nmean, const float* __restrict__ nrstd,
    const float* __restrict__ bias, float* __restrict__ Cout,
    int Msz, int Ksz, int Nsz)
{
    extern __shared__ char sm[];
    const uint32_t oAhi=0, oAlo=16384, oBhi=32768, oBlo=49152;
    uint32_t sbase = smem_u32(sm);

    int t = threadIdx.x, lane = t&31, w = t>>5;
    int wm = (w&1)*64, wn = (w>>1)*32;
    int bz = blockIdx.z, m0 = blockIdx.y*128, n0 = blockIdx.x*128;
    const __nv_bfloat16* Ah = Ahi + (long)bz*aStride;
    const __nv_bfloat16* Al = Alo + (long)bz*aStride;
    const float* Xb = X + (long)bz*(long)Ksz*Nsz;

    float acc[4][4][4];
#pragma unroll
    for(int i=0;i<4;i++)
#pragma unroll
        for(int j=0;j<4;j++)
#pragma unroll
            for(int q=0;q<4;q++) acc[i][j][q]=0.f;

    int ar = t>>1, ah = t&1;
    int bk = t>>2, bn = (t&3)*32;

    int nch = Kpad/64;
    for(int c=0;c<nch;c++){
        int k0 = c*64;
        {
            const uint4* gh = (const uint4*)(Ah + (long)(m0+ar)*Kpad + k0 + ah*32);
            const uint4* gl = (const uint4*)(Al + (long)(m0+ar)*Kpad + k0 + ah*32);
#pragma unroll
            for(int q=0;q<4;q++){
                uint32_t off = (uint32_t)ar*128u + (uint32_t)ah*64u + (uint32_t)q*16u;
                uint32_t sw = off ^ ((off>>3)&0x70u);
                *(uint4*)(sm + oAhi + sw) = gh[q];
                *(uint4*)(sm + oAlo + sw) = gl[q];
            }
        }
        {
            int kg = k0 + bk;
            bool valid = (kg < Ksz);
            float mn=0.f, rs=1.f;
            bool doact = (nmean != nullptr);
            if(doact && valid){ mn = nmean[(long)bz*Ksz+kg]; rs = nrstd[(long)bz*Ksz+kg]; }
            const float4* xr = (const float4*)(Xb + (long)kg*Nsz + n0 + bn);
#pragma unroll
            for(int q=0;q<4;q++){
                float xv[8];
                if(valid){
                    float4 v0 = xr[q*2], v1 = xr[q*2+1];
                    xv[0]=v0.x; xv[1]=v0.y; xv[2]=v0.z; xv[3]=v0.w;
                    xv[4]=v1.x; xv[5]=v1.y; xv[6]=v1.z; xv[7]=v1.w;
                    if(doact){
#pragma unroll
                        for(int j=0;j<8;j++) xv[j]=fmaxf((xv[j]-mn)*rs,0.f);
                    }
                } else {
#pragma unroll
                    for(int j=0;j<8;j++) xv[j]=0.f;
                }
                uint32_t hw[4], lw[4];
#pragma unroll
                for(int pq=0;pq<4;pq++){
                    float a=xv[pq*2], b2=xv[pq*2+1];
                    __nv_bfloat16 ha,la,hb,lb;
                    bf16split(a,ha,la); bf16split(b2,hb,lb);
                    __nv_bfloat162 hp=__halves2bfloat162(ha,hb);
                    __nv_bfloat162 lp=__halves2bfloat162(la,lb);
                    hw[pq]=*(uint32_t*)&hp;
                    lw[pq]=*(uint32_t*)&lp;
                }
                uint32_t off = (uint32_t)bk*256u + (uint32_t)bn*2u + (uint32_t)q*16u;
                uint32_t sw = off ^ ((off>>4)&0xF0u);
                *(uint4*)(sm + oBhi + sw) = make_uint4(hw[0],hw[1],hw[2],hw[3]);
                *(uint4*)(sm + oBlo + sw) = make_uint4(lw[0],lw[1],lw[2],lw[3]);
            }
        }
        __syncthreads();
#pragma unroll
        for(int kk=0;kk<4;kk++){
            uint32_t afh[4][4], afl[4][4];
#pragma unroll
            for(int mi=0;mi<4;mi++){
                uint32_t off = (uint32_t)(wm+mi*16+(lane&15))*128u + (uint32_t)kk*32u + (uint32_t)(lane>>4)*16u;
                uint32_t sw = off ^ ((off>>3)&0x70u);
                ldsm4(afh[mi], sbase + oAhi + sw);
                ldsm4(afl[mi], sbase + oAlo + sw);
            }
            uint32_t bfh[2][4], bfl[2][4];
#pragma unroll
            for(int nj=0;nj<2;nj++){
                uint32_t off = (uint32_t)(kk*16+(lane&15))*256u + (uint32_t)(wn+nj*16+(lane>>4)*8)*2u;
                uint32_t sw = off ^ ((off>>4)&0xF0u);
                ldsm4t(bfh[nj], sbase + oBhi + sw);
                ldsm4t(bfl[nj], sbase + oBlo + sw);
            }
#pragma unroll
            for(int mi=0;mi<4;mi++){
#pragma unroll
                for(int n8=0;n8<4;n8++){
                    const uint32_t* bh = &bfh[n8>>1][(n8&1)*2];
                    const uint32_t* bl = &bfl[n8>>1][(n8&1)*2];
                    mma16816(acc[mi][n8], afh[mi], bh);
                    mma16816(acc[mi][n8], afh[mi], bl);
                    mma16816(acc[mi][n8], afl[mi], bh);
                }
            }
        }
        __syncthreads();
    }

    int rbase = m0 + wm + (lane>>2);
    int cbase = n0 + wn + (lane&3)*2;
    int bcol = (n0 + wn) >> 5;
#pragma unroll
    for(int mi=0;mi<4;mi++){
        int r1 = rbase + mi*16;
        int r2 = r1 + 8;
        float bv1=0.f, bv2=0.f;
        if(bias){
            if(r1<Msz) bv1 = bias[((long)bz*Msz+r1)*(Nsz>>5) + bcol];
            if(r2<Msz) bv2 = bias[((long)bz*Msz+r2)*(Nsz>>5) + bcol];
        }
#pragma unroll
        for(int n8=0;n8<4;n8++){
            int col = cbase + n8*8;
            if(r1<Msz){
                float2 v = make_float2(acc[mi][n8][0]+bv1, acc[mi][n8][1]+bv1);
                *(float2*)&Cout[((long)bz*Msz+r1)*(long)Nsz+col] = v;
            }
            if(r2<Msz){
                float2 v = make_float2(acc[mi][n8][2]+bv2, acc[mi][n8][3]+bv2);
                *(float2*)&Cout[((long)bz*Msz+r2)*(long)Nsz+col] = v;
            }
        }
    }
}

// ===================== reductions =====================
__device__ __forceinline__ void blockReduce2(float& a, float& bsum){
    __shared__ float sa[32], sb[32];
    unsigned mm=0xffffffffu;
    for(int o=16;o;o>>=1){ a+=__shfl_down_sync(mm,a,o); bsum+=__shfl_down_sync(mm,bsum,o); }
    int w=threadIdx.x>>5, l=threadIdx.x&31;
    if(l==0){ sa[w]=a; sb[w]=bsum; }
    __syncthreads();
    int nw=(blockDim.x+31)>>5;
    if(threadIdx.x<32){
        a    = (threadIdx.x<nw)?sa[threadIdx.x]:0.f;
        bsum = (threadIdx.x<nw)?sb[threadIdx.x]:0.f;
        for(int o=16;o;o>>=1){ a+=__shfl_down_sync(mm,a,o); bsum+=__shfl_down_sync(mm,bsum,o); }
    }
}

__global__ void stats_kernel(const float* __restrict__ X, float* __restrict__ mean,
                             float* __restrict__ rstd, float* __restrict__ maxRaw, int M)
{
    int bo = blockIdx.x;
    const float* xb = X + (long)bo*M*32;
    float s=0.f, s2=0.f;
    for(int i=threadIdx.x;i<M;i+=blockDim.x){
        const float4* row = (const float4*)(xb + (long)i*32);
        float mx=-1e30f;
#pragma unroll
        for(int q=0;q<8;q++){
            float4 v = row[q];
            s  += v.x+v.y+v.z+v.w;
            s2 += v.x*v.x+v.y*v.y+v.z*v.z+v.w*v.w;
            mx = fmaxf(mx, fmaxf(fmaxf(v.x,v.y), fmaxf(v.z,v.w)));
        }
        maxRaw[(long)bo*M+i]=mx;
    }
    blockReduce2(s,s2);
    if(threadIdx.x==0){
        float Cnt = (float)(M*32);
        float mn = s/Cnt;
        float var = s2/Cnt - mn*mn;
        mean[bo]=mn;
        rstd[bo]=rsqrtf(var+1e-5f);
    }
}

__global__ void spass_kernel(const float* __restrict__ X, const float* __restrict__ mean,
                             const float* __restrict__ rstd, float* __restrict__ S, int Cnt)
{
    int bo = blockIdx.x;
    float mn=mean[bo], rs=rstd[bo];
    const float4* xb = (const float4*)(X + (long)bo*Cnt);
    float s=0.f;
    for(int i=threadIdx.x;i<(Cnt>>2);i+=blockDim.x){
        float4 v = xb[i];
        s += fmaxf((v.x-mn)*rs,0.f)+fmaxf((v.y-mn)*rs,0.f)
           + fmaxf((v.z-mn)*rs,0.f)+fmaxf((v.w-mn)*rs,0.f);
    }
    float d=0.f;
    blockReduce2(s,d);
    if(threadIdx.x==0) S[bo]=s;
}

__global__ void attn_kernel(const float* __restrict__ S, const float* __restrict__ w1,
                            const float* __restrict__ w2, float* __restrict__ g,
                            int O, int H, int Cnt)
{
    int b = blockIdx.x, t = threadIdx.x;
    __shared__ float ss[384], hh[96];
    if(t<O) ss[t] = S[(long)b*O+t] / (float)Cnt;
    __syncthreads();
    if(t<H){
        float a=0.f;
        for(int o=0;o<O;o++) a += w1[(long)t*O+o]*ss[o];
        hh[t]=fmaxf(a,0.f);
    }
    __syncthreads();
    if(t<O){
        float a=0.f;
        for(int j=0;j<H;j++) a += w2[(long)t*H+j]*hh[j];
        g[(long)b*O+t] = 1.f/(1.f+expf(-a));
    }
}

__global__ void wprep_kernel(const float* __restrict__ w2, const float* __restrict__ g,
                             float* __restrict__ WL, __nv_bfloat16* __restrict__ WRhi,
                             __nv_bfloat16* __restrict__ WRlo, int O, int Mpad)
{
    int b = blockIdx.y;
    int e = blockIdx.x*blockDim.x + threadIdx.x;
    if(e>=Mpad*O) return;
    int o=e/O, c=e%O;
    float vr = 0.f;
    if(o<O){
        float gg = g[(long)b*O+c];
        WL[(long)b*O*O + (long)o*O + c] = __fmul_rn(w2[(long)o*2*O + c], gg);
        vr = __fmul_rn(w2[(long)o*2*O + O + c], gg);
    }
    __nv_bfloat16 h,l; bf16split(vr,h,l);
    WRhi[(long)b*Mpad*O+e] = h;
    WRlo[(long)b*Mpad*O+e] = l;
}

__global__ void wsplit_kernel(const float* __restrict__ w, __nv_bfloat16* __restrict__ hi,
                              __nv_bfloat16* __restrict__ lo, int O, int K, int Mpad, int Kpad)
{
    int e = blockIdx.x*blockDim.x + threadIdx.x;
    if(e>=Mpad*Kpad) return;
    int r=e/Kpad, c=e%Kpad;
    float v = (r<O && c<K) ? w[(long)r*K+c] : 0.f;
    __nv_bfloat16 h,l; bf16split(v,h,l);
    hi[e]=h; lo[e]=l;
}

__global__ void final_kernel(const float* __restrict__ maxRaw2, const float* __restrict__ mean,
                             const float* __restrict__ rstd, const float* __restrict__ g,
                             float* __restrict__ out, long total, int Mctr)
{
    long e = (long)blockIdx.x*blockDim.x + threadIdx.x;
    if(e>=total) return;
    long bo = e/Mctr;
    float y = fmaxf((maxRaw2[e]-mean[bo])*rstd[bo], 0.f);
    out[e] = __fmul_rn(g[bo], y);
}

// ===================== host-side drivers =====================
static const int HM_SMEM = 65536;

template<int BM, int MR>
static void run_stage_gemms(int M, int C, int O, int H, int Mpad, int stage,
                      const float* w1, const float* a1w1, const float* a1w2,
                      const float* w2, const float* a2w1, const float* a2w2,
                      float* f_out,
                      float* feat, float* X, float* X2,
                      float* maxR, float* maxR2, float* P2,
                      float* mean, float* rstd, float* S, float* gAtt,
                      float* WL, __nv_bfloat16* WRhi, __nv_bfloat16* WRlo,
                      __nv_bfloat16* W1hi, __nv_bfloat16* W1lo)
{
    int NN = M*32;
    if(stage==0){
        sgemm2_kernel<BM,MR><<<dim3(NN/128,O/BM,B),256>>>(w1,0,feat,X,nullptr,nullptr,nullptr,O,C+3,NN);
    } else {
        hmma_kernel<<<dim3(NN/128,Mpad/128,B),256,HM_SMEM>>>(
            W1hi, W1lo, 0, 256, feat, nullptr, nullptr, nullptr, X, O, C+3, NN);
    }
    stats_kernel<<<B*O,256>>>(X, mean, rstd, maxR, M);
    spass_kernel<<<B*O,256>>>(X, mean, rstd, S, NN);
    attn_kernel<<<B,384>>>(S, a1w1, a1w2, gAtt, O, H, NN);
    wprep_kernel<<<dim3((Mpad*O+255)/256,B),256>>>(w2, gAtt, WL, WRhi, WRlo, O, Mpad);
    sgemm2_kernel<BM,MR><<<dim3(M/128,O/BM,B),256>>>(WL,(long)O*O,maxR,P2,nullptr,mean,rstd,O,O,M);
    hmma_kernel<<<dim3(NN/128,Mpad/128,B),256,HM_SMEM>>>(
        WRhi, WRlo, (long)Mpad*O, O, X, mean, rstd, P2, X2, O, O, NN);
    stats_kernel<<<B*O,256>>>(X2, mean, rstd, maxR2, M);
    spass_kernel<<<B*O,256>>>(X2, mean, rstd, S, NN);
    attn_kernel<<<B,384>>>(S, a2w1, a2w2, gAtt, O, H, NN);
    final_kernel<<<(int)(((long)B*O*M+255)/256),256>>>(maxR2, mean, rstd, gAtt, f_out, (long)B*O*M, M);
}

extern "C" void kernel_launch(void* const* d_in, const int* in_sizes, int n_in,
                              void* d_out, int out_size)
{
    const float* p      = (const float*)d_in[0];
    const float* f      = (const float*)d_in[1];
    const float* s0_w1  = (const float*)d_in[2];
    const float* s0_a1w1= (const float*)d_in[3];
    const float* s0_a1w2= (const float*)d_in[4];
    const float* s0_w2  = (const float*)d_in[5];
    const float* s0_a2w1= (const float*)d_in[6];
    const float* s0_a2w2= (const float*)d_in[7];
    const float* s1_w1  = (const float*)d_in[8];
    const float* s1_a1w1= (const float*)d_in[9];
    const float* s1_a1w2= (const float*)d_in[10];
    const float* s1_w2  = (const float*)d_in[11];
    const float* s1_a2w1= (const float*)d_in[12];
    const float* s1_a2w2= (const float*)d_in[13];

    float* out   = (float*)d_out;
    float* o_p   = out;
    float* o_cp1 = out + 98304;
    float* o_cp2 = out + 122880;
    float* o_f   = out + 129024;
    float* o_f1  = out + 227328;
    float* o_f2  = out + 1800192;

    cudaFuncSetAttribute(ballq2_kernel<8192,64>, cudaFuncAttributeMaxDynamicSharedMemorySize, 8192*16);
    cudaFuncSetAttribute(hmma_kernel, cudaFuncAttributeMaxDynamicSharedMemorySize, HM_SMEM);

    void *vfeat,*vX,*vX2,*vcf,*vmr,*vmr2,*vp2,*vidx,*vgidx,*vmean,*vrstd,*vS,*vg,*vwl,*vwrh,*vwrl,*vw1h,*vw1l;
    cudaGetSymbolAddress(&vfeat, g_feat);
    cudaGetSymbolAddress(&vX,    g_X);
    cudaGetSymbolAddress(&vX2,   g_X2);
    cudaGetSymbolAddress(&vcf,   g_cf);
    cudaGetSymbolAddress(&vmr,   g_maxR);
    cudaGetSymbolAddress(&vmr2,  g_maxR2);
    cudaGetSymbolAddress(&vp2,   g_P2);
    cudaGetSymbolAddress(&vidx,  g_idx);
    cudaGetSymbolAddress(&vgidx, g_gidx);
    cudaGetSymbolAddress(&vmean, g_mean);
    cudaGetSymbolAddress(&vrstd, g_rstd);
    cudaGetSymbolAddress(&vS,    g_S);
    cudaGetSymbolAddress(&vg,    g_g);
    cudaGetSymbolAddress(&vwl,   g_WL);
    cudaGetSymbolAddress(&vwrh,  g_WRhi);
    cudaGetSymbolAddress(&vwrl,  g_WRlo);
    cudaGetSymbolAddress(&vw1h,  g_W1hi);
    cudaGetSymbolAddress(&vw1l,  g_W1lo);

    // ---- head: 3 launches; fps=3, gather=4, ballq2=5 (profiled) ----
    wsplit_kernel<<<(384*256+255)/256,256>>>(s1_w1,(__nv_bfloat16*)vw1h,(__nv_bfloat16*)vw1l,
        384, 195, 384, 256);                                                     // 0
    cudaMemcpyAsync(o_p, p, 98304*sizeof(float), cudaMemcpyDeviceToDevice, 0);   // 1
    cudaMemcpyAsync(o_f, f, 98304*sizeof(float), cudaMemcpyDeviceToDevice, 0);   // 2

    // ---------- stage 0: N=8192 -> M=2048, C=3, O=192 (Mpad 256), H=48 ----------
    {
        int N=8192, M=2048, C=3;
        fps_kernel<8192,2048><<<B,1024>>>(p, (int*)vidx);                        // 3
        gather_kernel<<<dim3(M/256,B),256>>>(p,f,(int*)vidx,o_cp1,(float*)vcf,N,M,C); // 4
        ballq2_kernel<8192,64><<<dim3(M/64,B),256,8192*16>>>(p,o_cp1,(int*)vgidx,M);  // 5 <- profiled
        featbuild_kernel<<<dim3(M*32/256,B),256>>>(p,f,o_cp1,(float*)vcf,(int*)vgidx,(float*)vfeat,N,M,C);
        run_stage_gemms<96,6>(M,C,192,48,256,0,
            s0_w1,s0_a1w1,s0_a1w2,s0_w2,s0_a2w1,s0_a2w2, o_f1,
            (float*)vfeat,(float*)vX,(float*)vX2,(float*)vmr,(float*)vmr2,(float*)vp2,
            (float*)vmean,(float*)vrstd,(float*)vS,(float*)vg,
            (float*)vwl,(__nv_bfloat16*)vwrh,(__nv_bfloat16*)vwrl,
            (__nv_bfloat16*)vw1h,(__nv_bfloat16*)vw1l);
    }
    // ---------- stage 1: N=2048 -> M=512, C=192, O=384 (Mpad 384), H=96 ----------
    {
        int N=2048, M=512, C=192;
        fps_kernel<2048,512><<<B,1024>>>(o_cp1, (int*)vidx);
        gather_kernel<<<dim3(M/256,B),256>>>(o_cp1,o_f1,(int*)vidx,o_cp2,(float*)vcf,N,M,C);
        ballq2_kernel<2048,16><<<dim3(M/16,B),256,2048*16>>>(o_cp1,o_cp2,(int*)vgidx,M);
        featbuild_kernel<<<dim3(M*32/256,B),256>>>(o_cp1,o_f1,o_cp2,(float*)vcf,(int*)vgidx,(float*)vfeat,N,M,C);
        run_stage_gemms<128,8>(M,C,384,96,384,1,
            s1_w1,s1_a1w1,s1_a1w2,s1_w2,s1_a2w1,s1_a2w2, o_f2,
            (float*)vfeat,(float*)vX,(float*)vX2,(float*)vmr,(float*)vmr2,(float*)vp2,
            (float*)vmean,(float*)vrstd,(float*)vS,(float*)vg,
            (float*)vwl,(__nv_bfloat16*)vwrh,(__nv_bfloat16*)vwrl,
            (__nv_bfloat16*)vw1h,(__nv_bfloat16*)vw1l);
    }
}

// round 10
// speedup vs baseline: 1.1649x; 1.0062x over previous
#include <cuda_runtime.h>
#include <cuda_bf16.h>
#include <stdint.h>
#include <math.h>

// ===================== constants =====================
static const int B = 4;

// ===================== device scratch =====================
__device__ float g_feat[4L*195*512*32];
__device__ float g_X  [4L*192*2048*32];
__device__ float g_X2 [4L*192*2048*32];
__device__ float g_cf [4L*192*512];
__device__ float g_maxR [4L*192*2048];
__device__ float g_maxR2[4L*192*2048];
__device__ float g_P2  [4L*192*2048];
__device__ int   g_idx [4*2048];
__device__ int   g_gidx[4*2048*32];
__device__ float g_mean[4*384], g_rstd[4*384], g_S[4*384], g_g[4*384];
__device__ float g_WL[4L*384*384];
__device__ __nv_bfloat16 g_WRhi[4L*384*384], g_WRlo[4L*384*384];
__device__ __nv_bfloat16 g_W1hi[384L*256],   g_W1lo[384L*256];

// ===================== small helpers =====================
__device__ __forceinline__ float dist2f(float ax,float ay,float az,float bx,float by,float bz){
    float dx=__fsub_rn(ax,bx), dy=__fsub_rn(ay,by), dz=__fsub_rn(az,bz);
    return __fadd_rn(__fadd_rn(__fmul_rn(dx,dx),__fmul_rn(dy,dy)),__fmul_rn(dz,dz));
}
__device__ __forceinline__ uint32_t smem_u32(const void* p){
    uint32_t a; asm("{ .reg .u64 t; cvta.to.shared.u64 t, %1; cvt.u32.u64 %0, t; }":"=r"(a):"l"(p));
    return a;
}
__device__ __forceinline__ void ldsm4(uint32_t* r, uint32_t addr){
    asm volatile("ldmatrix.sync.aligned.m8n8.x4.shared.b16 {%0,%1,%2,%3}, [%4];"
        :"=r"(r[0]),"=r"(r[1]),"=r"(r[2]),"=r"(r[3]):"r"(addr));
}
__device__ __forceinline__ void ldsm4t(uint32_t* r, uint32_t addr){
    asm volatile("ldmatrix.sync.aligned.m8n8.x4.trans.shared.b16 {%0,%1,%2,%3}, [%4];"
        :"=r"(r[0]),"=r"(r[1]),"=r"(r[2]),"=r"(r[3]):"r"(addr));
}
__device__ __forceinline__ void mma16816(float* d, const uint32_t* a, const uint32_t* b){
    asm volatile("mma.sync.aligned.m16n8k16.row.col.f32.bf16.bf16.f32 "
        "{%0,%1,%2,%3}, {%4,%5,%6,%7}, {%8,%9}, {%0,%1,%2,%3};"
        : "+f"(d[0]),"+f"(d[1]),"+f"(d[2]),"+f"(d[3])
        : "r"(a[0]),"r"(a[1]),"r"(a[2]),"r"(a[3]),"r"(b[0]),"r"(b[1]));
}
__device__ __forceinline__ void bf16split(float v, __nv_bfloat16& h, __nv_bfloat16& l){
    h = __float2bfloat16_rn(v);
    l = __float2bfloat16_rn(v - __bfloat162float(h));
}

// ===================== FPS (3-barrier, proven fastest) =====================
template<int N, int M>
__global__ __launch_bounds__(1024) void fps_kernel(const float* __restrict__ p, int* __restrict__ outIdx)
{
    constexpr int NPT = N/1024;
    const int b = blockIdx.x, t = threadIdx.x;
    const float* pb = p + (long)b*N*3;
    float px[NPT],py[NPT],pz[NPT],dd[NPT];
#pragma unroll
    for(int j=0;j<NPT;j++){
        int gidx = t*NPT+j;
        px[j]=pb[3*gidx]; py[j]=pb[3*gidx+1]; pz[j]=pb[3*gidx+2];
        dd[j]=1e10f;
    }
    __shared__ float swv[32];
    __shared__ int   swi[32];
    __shared__ float sc[3];
    __shared__ int   sBi;
    if(t==0){ outIdx[(long)b*M]=0; sc[0]=pb[0]; sc[1]=pb[1]; sc[2]=pb[2]; }
    __syncthreads();
    float lx=sc[0], ly=sc[1], lz=sc[2];
    for(int s=1;s<M;s++){
        float bv=-1e30f; int bi=0x7fffffff;
#pragma unroll
        for(int j=0;j<NPT;j++){
            float d = dist2f(px[j],py[j],pz[j],lx,ly,lz);
            float dm = fminf(dd[j], d);
            dd[j]=dm;
            if(dm>bv){ bv=dm; bi=t*NPT+j; }
        }
#pragma unroll
        for(int off=16;off>0;off>>=1){
            float ov=__shfl_down_sync(0xffffffffu,bv,off);
            int   oi=__shfl_down_sync(0xffffffffu,bi,off);
            if(ov>bv || (ov==bv && oi<bi)){ bv=ov; bi=oi; }
        }
        if((t&31)==0){ swv[t>>5]=bv; swi[t>>5]=bi; }
        __syncthreads();
        if(t<32){
            bv=swv[t]; bi=swi[t];
#pragma unroll
            for(int off=16;off>0;off>>=1){
                float ov=__shfl_down_sync(0xffffffffu,bv,off);
                int   oi=__shfl_down_sync(0xffffffffu,bi,off);
                if(ov>bv || (ov==bv && oi<bi)){ bv=ov; bi=oi; }
            }
            if(t==0){ sBi=bi; outIdx[(long)b*M+s]=bi; }
        }
        __syncthreads();
        int w = sBi;
        if(t == w/NPT){ int j=w-t*NPT; sc[0]=px[j]; sc[1]=py[j]; sc[2]=pz[j]; }
        __syncthreads();
        lx=sc[0]; ly=sc[1]; lz=sc[2];
    }
}

// ===================== gather =====================
__global__ void gather_kernel(const float* __restrict__ p, const float* __restrict__ f,
                              const int* __restrict__ idx, float* __restrict__ cp,
                              float* __restrict__ cf, int N, int M, int C)
{
    int b = blockIdx.y;
    int i = blockIdx.x*blockDim.x + threadIdx.x;
    if(i>=M) return;
    int j = idx[(long)b*M+i];
    cp[((long)b*M+i)*3+0] = p[((long)b*N+j)*3+0];
    cp[((long)b*M+i)*3+1] = p[((long)b*N+j)*3+1];
    cp[((long)b*M+i)*3+2] = p[((long)b*N+j)*3+2];
    for(int c=0;c<C;c++)
        cf[((long)b*C+c)*M+i] = f[((long)b*C+c)*N+j];
}

// ===================== ball query v3: warp-per-center, 4-chunk pipelined ballot =====================
// CPB centers/block, 256 threads (8 warps). N multiple of 128.
template<int N, int CPB>
__global__ __launch_bounds__(256) void ballq3_kernel(
    const float* __restrict__ pts, const float* __restrict__ ctr,
    int* __restrict__ gidx, int M)
{
    extern __shared__ float4 sp[];
    int b = blockIdx.y;
    const float* pb = pts + (long)b*N*3;
    for(int j=threadIdx.x;j<N;j+=blockDim.x)
        sp[j] = make_float4(pb[3*j],pb[3*j+1],pb[3*j+2],0.f);
    __syncthreads();
    int wid = threadIdx.x>>5, lane = threadIdx.x&31;
    constexpr int CPW = CPB/8;
    int base = blockIdx.x*CPB + wid*CPW;
    const float R2 = (float)(0.1*0.1);
#pragma unroll
    for(int c=0;c<CPW;c++){
        int i = base + c;
        float cx=ctr[((long)b*M+i)*3], cy=ctr[((long)b*M+i)*3+1], cz=ctr[((long)b*M+i)*3+2];
        int* out = gidx + ((long)b*M+i)*32;
        int cnt=0, first=0;
        for(int j0=0;j0<N;j0+=128){
            bool in[4];
            unsigned m[4];
#pragma unroll
            for(int q=0;q<4;q++){
                float4 pt = sp[j0+q*32+lane];
                in[q] = dist2f(cx,cy,cz,pt.x,pt.y,pt.z) < R2;
            }
#pragma unroll
            for(int q=0;q<4;q++) m[q] = __ballot_sync(0xffffffffu, in[q]);
#pragma unroll
            for(int q=0;q<4;q++){
                if(m[q] && cnt<32){
                    if(cnt==0) first = j0+q*32 + __ffs(m[q]) - 1;
                    int pos = cnt + __popc(m[q] & ((1u<<lane)-1u));
                    if(in[q] && pos<32) out[pos] = j0+q*32+lane;
                    cnt += __popc(m[q]);
                }
            }
            if(cnt>=32) break;
        }
        if(cnt<32){
            for(int k=cnt+lane;k<32;k+=32) out[k]=first;
        }
    }
}

// ===================== feature build (fp32) =====================
__global__ void featbuild_kernel(const float* __restrict__ p, const float* __restrict__ f,
                                 const float* __restrict__ cp, const float* __restrict__ cf,
                                 const int* __restrict__ gidx, float* __restrict__ feat,
                                 int N, int M, int C)
{
    int b = blockIdx.y;
    int gi = blockIdx.x*blockDim.x + threadIdx.x;
    int i = gi>>5, kk = gi&31;
    if(i>=M) return;
    int j = gidx[((long)b*M+i)*32+kk];
    long CH = C+3;
    float dx = __fsub_rn(p[((long)b*N+j)*3+0], cp[((long)b*M+i)*3+0]);
    float dy = __fsub_rn(p[((long)b*N+j)*3+1], cp[((long)b*M+i)*3+1]);
    float dz = __fsub_rn(p[((long)b*N+j)*3+2], cp[((long)b*M+i)*3+2]);
    feat[(((long)b*CH+0)*M+i)*32+kk] = dx;
    feat[(((long)b*CH+1)*M+i)*32+kk] = dy;
    feat[(((long)b*CH+2)*M+i)*32+kk] = dz;
    const float* fb  = f  + (long)b*C*N;
    const float* cfb = cf + (long)b*C*M;
    for(int c=0;c<C;c++)
        feat[(((long)b*CH+3+c)*M+i)*32+kk] = __fsub_rn(fb[(long)c*N+j], cfb[(long)c*M+i]);
}

// ===================== FFMA SGEMM (small GEMMs: conv1 s0, P2) =====================
template<int BM, int MR>
__global__ __launch_bounds__(256) void sgemm2_kernel(
    const float* __restrict__ A, long aStride,
    const float* __restrict__ X, float* __restrict__ C,
    const float* __restrict__ bias,
    const float* __restrict__ nmean, const float* __restrict__ nrstd,
    int Msz, int Ksz, int Nsz)
{
    __shared__ float As[2][16][BM];
    __shared__ float Xs[2][16][128];
    constexpr int AL = BM/16;
    int b = blockIdx.z, m0 = blockIdx.y*BM, n0 = blockIdx.x*128;
    const float* Ab = A + (long)b*aStride;
    const float* Xb = X + (long)b*(long)Ksz*Nsz;
    const float* mp = nmean ? nmean + (long)b*Ksz : nullptr;
    const float* rp = nrstd ? nrstd + (long)b*Ksz : nullptr;
    int t = threadIdx.x, tx = t&15, ty = t>>4;
    float acc[MR][8];
#pragma unroll
    for(int r=0;r<MR;r++)
#pragma unroll
        for(int c=0;c<8;c++) acc[r][c]=0.f;
    float  aR[AL];
    float4 xR[2];
    int nk = (Ksz+15)>>4;
    auto LOAD = [&](int k0){
#pragma unroll
        for(int i=0;i<AL;i++){
            int e=t+i*256, m=e%BM, k=e/BM;
            aR[i] = (k0+k<Ksz) ? Ab[(long)(m0+m)*Ksz + k0+k] : 0.f;
        }
#pragma unroll
        for(int j=0;j<2;j++){
            int e=t+j*256, k=e>>5, n4=e&31;
            if(k0+k<Ksz){
                float4 v = *(const float4*)(Xb + (long)(k0+k)*Nsz + n0 + n4*4);
                if(mp){
                    float mn=mp[k0+k], rs=rp[k0+k];
                    v.x=fmaxf((v.x-mn)*rs,0.f); v.y=fmaxf((v.y-mn)*rs,0.f);
                    v.z=fmaxf((v.z-mn)*rs,0.f); v.w=fmaxf((v.w-mn)*rs,0.f);
                }
                xR[j]=v;
            } else xR[j]=make_float4(0.f,0.f,0.f,0.f);
        }
    };
    auto STORE = [&](int buf){
#pragma unroll
        for(int i=0;i<AL;i++){ int e=t+i*256; As[buf][e/BM][e%BM]=aR[i]; }
#pragma unroll
        for(int j=0;j<2;j++){ int e=t+j*256; *(float4*)&Xs[buf][e>>5][(e&31)*4] = xR[j]; }
    };
    auto COMP = [&](int buf){
#pragma unroll
        for(int kk=0;kk<16;kk++){
            float a[MR];
#pragma unroll
            for(int r=0;r<MR;r++) a[r]=As[buf][kk][ty*MR+r];
            float4 b0 = *(float4*)&Xs[buf][kk][tx*8];
            float4 b1 = *(float4*)&Xs[buf][kk][tx*8+4];
            float bb[8] = {b0.x,b0.y,b0.z,b0.w,b1.x,b1.y,b1.z,b1.w};
#pragma unroll
            for(int r=0;r<MR;r++)
#pragma unroll
                for(int c=0;c<8;c++) acc[r][c] += a[r]*bb[c];
        }
    };
    LOAD(0); STORE(0); __syncthreads();
    for(int kt=0;kt<nk;kt++){
        int cur=kt&1;
        if(kt+1<nk) LOAD((kt+1)*16);
        COMP(cur);
        if(kt+1<nk){ STORE(cur^1); __syncthreads(); }
    }
#pragma unroll
    for(int r=0;r<MR;r++){
        int row=m0+ty*MR+r, col=n0+tx*8;
        float o[8];
#pragma unroll
        for(int c=0;c<8;c++) o[c]=acc[r][c];
        if(bias){
            const float* bb = bias + ((long)b*Msz+row)*(Nsz>>5);
#pragma unroll
            for(int c=0;c<8;c++) o[c] += bb[(col+c)>>5];
        }
        *(float4*)&C[((long)b*Msz+row)*(long)Nsz+col]   = make_float4(o[0],o[1],o[2],o[3]);
        *(float4*)&C[((long)b*Msz+row)*(long)Nsz+col+4] = make_float4(o[4],o[5],o[6],o[7]);
    }
}

// ===================== mma.sync bf16 GEMM (fused norm+split B build) =====================
__global__ __launch_bounds__(256) void hmma_kernel(
    const __nv_bfloat16* __restrict__ Ahi, const __nv_bfloat16* __restrict__ Alo,
    long aStride, int Kpad,
    const float* __restrict__ X, const float* __restrict__ nmean, const float* __restrict__ nrstd,
    const float* __restrict__ bias, float* __restrict__ Cout,
    int Msz, int Ksz, int Nsz)
{
    extern __shared__ char sm[];
    const uint32_t oAhi=0, oAlo=16384, oBhi=32768, oBlo=49152;
    uint32_t sbase = smem_u32(sm);

    int t = threadIdx.x, lane = t&31, w = t>>5;
    int wm = (w&1)*64, wn = (w>>1)*32;
    int bz = blockIdx.z, m0 = blockIdx.y*128, n0 = blockIdx.x*128;
    const __nv_bfloat16* Ah = Ahi + (long)bz*aStride;
    const __nv_bfloat16* Al = Alo + (long)bz*aStride;
    const float* Xb = X + (long)bz*(long)Ksz*Nsz;

    float acc[4][4][4];
#pragma unroll
    for(int i=0;i<4;i++)
#pragma unroll
        for(int j=0;j<4;j++)
#pragma unroll
            for(int q=0;q<4;q++) acc[i][j][q]=0.f;

    int ar = t>>1, ah = t&1;
    int bk = t>>2, bn = (t&3)*32;

    int nch = Kpad/64;
    for(int c=0;c<nch;c++){
        int k0 = c*64;
        {
            const uint4* gh = (const uint4*)(Ah + (long)(m0+ar)*Kpad + k0 + ah*32);
            const uint4* gl = (const uint4*)(Al + (long)(m0+ar)*Kpad + k0 + ah*32);
#pragma unroll
            for(int q=0;q<4;q++){
                uint32_t off = (uint32_t)ar*128u + (uint32_t)ah*64u + (uint32_t)q*16u;
                uint32_t sw = off ^ ((off>>3)&0x70u);
                *(uint4*)(sm + oAhi + sw) = gh[q];
                *(uint4*)(sm + oAlo + sw) = gl[q];
            }
        }
        {
            int kg = k0 + bk;
            bool valid = (kg < Ksz);
            float mn=0.f, rs=1.f;
            bool doact = (nmean != nullptr);
            if(doact && valid){ mn = nmean[(long)bz*Ksz+kg]; rs = nrstd[(long)bz*Ksz+kg]; }
            const float4* xr = (const float4*)(Xb + (long)kg*Nsz + n0 + bn);
#pragma unroll
            for(int q=0;q<4;q++){
                float xv[8];
                if(valid){
                    float4 v0 = xr[q*2], v1 = xr[q*2+1];
                    xv[0]=v0.x; xv[1]=v0.y; xv[2]=v0.z; xv[3]=v0.w;
                    xv[4]=v1.x; xv[5]=v1.y; xv[6]=v1.z; xv[7]=v1.w;
                    if(doact){
#pragma unroll
                        for(int j=0;j<8;j++) xv[j]=fmaxf((xv[j]-mn)*rs,0.f);
                    }
                } else {
#pragma unroll
                    for(int j=0;j<8;j++) xv[j]=0.f;
                }
                uint32_t hw[4], lw[4];
#pragma unroll
                for(int pq=0;pq<4;pq++){
                    float a=xv[pq*2], b2=xv[pq*2+1];
                    __nv_bfloat16 ha,la,hb,lb;
                    bf16split(a,ha,la); bf16split(b2,hb,lb);
                    __nv_bfloat162 hp=__halves2bfloat162(ha,hb);
                    __nv_bfloat162 lp=__halves2bfloat162(la,lb);
                    hw[pq]=*(uint32_t*)&hp;
                    lw[pq]=*(uint32_t*)&lp;
                }
                uint32_t off = (uint32_t)bk*256u + (uint32_t)bn*2u + (uint32_t)q*16u;
                uint32_t sw = off ^ ((off>>4)&0xF0u);
                *(uint4*)(sm + oBhi + sw) = make_uint4(hw[0],hw[1],hw[2],hw[3]);
                *(uint4*)(sm + oBlo + sw) = make_uint4(lw[0],lw[1],lw[2],lw[3]);
            }
        }
        __syncthreads();
#pragma unroll
        for(int kk=0;kk<4;kk++){
            uint32_t afh[4][4], afl[4][4];
#pragma unroll
            for(int mi=0;mi<4;mi++){
                uint32_t off = (uint32_t)(wm+mi*16+(lane&15))*128u + (uint32_t)kk*32u + (uint32_t)(lane>>4)*16u;
                uint32_t sw = off ^ ((off>>3)&0x70u);
                ldsm4(afh[mi], sbase + oAhi + sw);
                ldsm4(afl[mi], sbase + oAlo + sw);
            }
            uint32_t bfh[2][4], bfl[2][4];
#pragma unroll
            for(int nj=0;nj<2;nj++){
                uint32_t off = (uint32_t)(kk*16+(lane&15))*256u + (uint32_t)(wn+nj*16+(lane>>4)*8)*2u;
                uint32_t sw = off ^ ((off>>4)&0xF0u);
                ldsm4t(bfh[nj], sbase + oBhi + sw);
                ldsm4t(bfl[nj], sbase + oBlo + sw);
            }
#pragma unroll
            for(int mi=0;mi<4;mi++){
#pragma unroll
                for(int n8=0;n8<4;n8++){
                    const uint32_t* bh = &bfh[n8>>1][(n8&1)*2];
                    const uint32_t* bl = &bfl[n8>>1][(n8&1)*2];
                    mma16816(acc[mi][n8], afh[mi], bh);
                    mma16816(acc[mi][n8], afh[mi], bl);
                    mma16816(acc[mi][n8], afl[mi], bh);
                }
            }
        }
        __syncthreads();
    }

    int rbase = m0 + wm + (lane>>2);
    int cbase = n0 + wn + (lane&3)*2;
    int bcol = (n0 + wn) >> 5;
#pragma unroll
    for(int mi=0;mi<4;mi++){
        int r1 = rbase + mi*16;
        int r2 = r1 + 8;
        float bv1=0.f, bv2=0.f;
        if(bias){
            if(r1<Msz) bv1 = bias[((long)bz*Msz+r1)*(Nsz>>5) + bcol];
            if(r2<Msz) bv2 = bias[((long)bz*Msz+r2)*(Nsz>>5) + bcol];
        }
#pragma unroll
        for(int n8=0;n8<4;n8++){
            int col = cbase + n8*8;
            if(r1<Msz){
                float2 v = make_float2(acc[mi][n8][0]+bv1, acc[mi][n8][1]+bv1);
                *(float2*)&Cout[((long)bz*Msz+r1)*(long)Nsz+col] = v;
            }
            if(r2<Msz){
                float2 v = make_float2(acc[mi][n8][2]+bv2, acc[mi][n8][3]+bv2);
                *(float2*)&Cout[((long)bz*Msz+r2)*(long)Nsz+col] = v;
            }
        }
    }
}

// ===================== reductions =====================
__device__ __forceinline__ void blockReduce2(float& a, float& bsum){
    __shared__ float sa[32], sb[32];
    unsigned mm=0xffffffffu;
    for(int o=16;o;o>>=1){ a+=__shfl_down_sync(mm,a,o); bsum+=__shfl_down_sync(mm,bsum,o); }
    int w=threadIdx.x>>5, l=threadIdx.x&31;
    if(l==0){ sa[w]=a; sb[w]=bsum; }
    __syncthreads();
    int nw=(blockDim.x+31)>>5;
    if(threadIdx.x<32){
        a    = (threadIdx.x<nw)?sa[threadIdx.x]:0.f;
        bsum = (threadIdx.x<nw)?sb[threadIdx.x]:0.f;
        for(int o=16;o;o>>=1){ a+=__shfl_down_sync(mm,a,o); bsum+=__shfl_down_sync(mm,bsum,o); }
    }
}

// fused: mean/rstd/maxRaw + S (relu-sum) in one kernel; phase-2 re-read hits L1/L2
__global__ void stats2_kernel(const float* __restrict__ X, float* __restrict__ mean,
                              float* __restrict__ rstd, float* __restrict__ maxRaw,
                              float* __restrict__ S, int M)
{
    __shared__ float bc[2];
    int bo = blockIdx.x;
    const float* xb = X + (long)bo*M*32;
    float s=0.f, s2=0.f;
    for(int i=threadIdx.x;i<M;i+=blockDim.x){
        const float4* row = (const float4*)(xb + (long)i*32);
        float mx=-1e30f;
#pragma unroll
        for(int q=0;q<8;q++){
            float4 v = row[q];
            s  += v.x+v.y+v.z+v.w;
            s2 += v.x*v.x+v.y*v.y+v.z*v.z+v.w*v.w;
            mx = fmaxf(mx, fmaxf(fmaxf(v.x,v.y), fmaxf(v.z,v.w)));
        }
        maxRaw[(long)bo*M+i]=mx;
    }
    blockReduce2(s,s2);
    if(threadIdx.x==0){
        float Cnt = (float)(M*32);
        float mn = s/Cnt;
        float var = s2/Cnt - mn*mn;
        float rs = rsqrtf(var+1e-5f);
        mean[bo]=mn; rstd[bo]=rs;
        bc[0]=mn; bc[1]=rs;
    }
    __syncthreads();
    float mn = bc[0], rs = bc[1];
    const float4* xv = (const float4*)xb;
    float sr=0.f;
    for(int i=threadIdx.x;i<M*8;i+=blockDim.x){
        float4 v = xv[i];
        sr += fmaxf((v.x-mn)*rs,0.f)+fmaxf((v.y-mn)*rs,0.f)
            + fmaxf((v.z-mn)*rs,0.f)+fmaxf((v.w-mn)*rs,0.f);
    }
    float d=0.f;
    blockReduce2(sr,d);
    if(threadIdx.x==0) S[bo]=sr;
}

__global__ void attn_kernel(const float* __restrict__ S, const float* __restrict__ w1,
                            const float* __restrict__ w2, float* __restrict__ g,
                            int O, int H, int Cnt)
{
    int b = blockIdx.x, t = threadIdx.x;
    __shared__ float ss[384], hh[96];
    if(t<O) ss[t] = S[(long)b*O+t] / (float)Cnt;
    __syncthreads();
    if(t<H){
        float a=0.f;
        for(int o=0;o<O;o++) a += w1[(long)t*O+o]*ss[o];
        hh[t]=fmaxf(a,0.f);
    }
    __syncthreads();
    if(t<O){
        float a=0.f;
        for(int j=0;j<H;j++) a += w2[(long)t*H+j]*hh[j];
        g[(long)b*O+t] = 1.f/(1.f+expf(-a));
    }
}

__global__ void wprep_kernel(const float* __restrict__ w2, const float* __restrict__ g,
                             float* __restrict__ WL, __nv_bfloat16* __restrict__ WRhi,
                             __nv_bfloat16* __restrict__ WRlo, int O, int Mpad)
{
    int b = blockIdx.y;
    int e = blockIdx.x*blockDim.x + threadIdx.x;
    if(e>=Mpad*O) return;
    int o=e/O, c=e%O;
    float vr = 0.f;
    if(o<O){
        float gg = g[(long)b*O+c];
        WL[(long)b*O*O + (long)o*O + c] = __fmul_rn(w2[(long)o*2*O + c], gg);
        vr = __fmul_rn(w2[(long)o*2*O + O + c], gg);
    }
    __nv_bfloat16 h,l; bf16split(vr,h,l);
    WRhi[(long)b*Mpad*O+e] = h;
    WRlo[(long)b*Mpad*O+e] = l;
}

__global__ void wsplit_kernel(const float* __restrict__ w, __nv_bfloat16* __restrict__ hi,
                              __nv_bfloat16* __restrict__ lo, int O, int K, int Mpad, int Kpad)
{
    int e = blockIdx.x*blockDim.x + threadIdx.x;
    if(e>=Mpad*Kpad) return;
    int r=e/Kpad, c=e%Kpad;
    float v = (r<O && c<K) ? w[(long)r*K+c] : 0.f;
    __nv_bfloat16 h,l; bf16split(v,h,l);
    hi[e]=h; lo[e]=l;
}

__global__ void final_kernel(const float* __restrict__ maxRaw2, const float* __restrict__ mean,
                             const float* __restrict__ rstd, const float* __restrict__ g,
                             float* __restrict__ out, long total, int Mctr)
{
    long e = (long)blockIdx.x*blockDim.x + threadIdx.x;
    if(e>=total) return;
    long bo = e/Mctr;
    float y = fmaxf((maxRaw2[e]-mean[bo])*rstd[bo], 0.f);
    out[e] = __fmul_rn(g[bo], y);
}

// ===================== host-side drivers =====================
static const int HM_SMEM = 65536;

template<int BM, int MR>
static void run_stage_gemms(int M, int C, int O, int H, int Mpad, int stage,
                      const float* w1, const float* a1w1, const float* a1w2,
                      const float* w2, const float* a2w1, const float* a2w2,
                      float* f_out,
                      float* feat, float* X, float* X2,
                      float* maxR, float* maxR2, float* P2,
                      float* mean, float* rstd, float* S, float* gAtt,
                      float* WL, __nv_bfloat16* WRhi, __nv_bfloat16* WRlo,
                      __nv_bfloat16* W1hi, __nv_bfloat16* W1lo)
{
    int NN = M*32;
    if(stage==0){
        sgemm2_kernel<BM,MR><<<dim3(NN/128,O/BM,B),256>>>(w1,0,feat,X,nullptr,nullptr,nullptr,O,C+3,NN);
    } else {
        hmma_kernel<<<dim3(NN/128,Mpad/128,B),256,HM_SMEM>>>(
            W1hi, W1lo, 0, 256, feat, nullptr, nullptr, nullptr, X, O, C+3, NN);
    }
    stats2_kernel<<<B*O,256>>>(X, mean, rstd, maxR, S, M);
    attn_kernel<<<B,384>>>(S, a1w1, a1w2, gAtt, O, H, NN);
    wprep_kernel<<<dim3((Mpad*O+255)/256,B),256>>>(w2, gAtt, WL, WRhi, WRlo, O, Mpad);
    sgemm2_kernel<BM,MR><<<dim3(M/128,O/BM,B),256>>>(WL,(long)O*O,maxR,P2,nullptr,mean,rstd,O,O,M);
    hmma_kernel<<<dim3(NN/128,Mpad/128,B),256,HM_SMEM>>>(
        WRhi, WRlo, (long)Mpad*O, O, X, mean, rstd, P2, X2, O, O, NN);
    stats2_kernel<<<B*O,256>>>(X2, mean, rstd, maxR2, S, M);
    attn_kernel<<<B,384>>>(S, a2w1, a2w2, gAtt, O, H, NN);
    final_kernel<<<(int)(((long)B*O*M+255)/256),256>>>(maxR2, mean, rstd, gAtt, f_out, (long)B*O*M, M);
}

extern "C" void kernel_launch(void* const* d_in, const int* in_sizes, int n_in,
                              void* d_out, int out_size)
{
    const float* p      = (const float*)d_in[0];
    const float* f      = (const float*)d_in[1];
    const float* s0_w1  = (const float*)d_in[2];
    const float* s0_a1w1= (const float*)d_in[3];
    const float* s0_a1w2= (const float*)d_in[4];
    const float* s0_w2  = (const float*)d_in[5];
    const float* s0_a2w1= (const float*)d_in[6];
    const float* s0_a2w2= (const float*)d_in[7];
    const float* s1_w1  = (const float*)d_in[8];
    const float* s1_a1w1= (const float*)d_in[9];
    const float* s1_a1w2= (const float*)d_in[10];
    const float* s1_w2  = (const float*)d_in[11];
    const float* s1_a2w1= (const float*)d_in[12];
    const float* s1_a2w2= (const float*)d_in[13];

    float* out   = (float*)d_out;
    float* o_p   = out;
    float* o_cp1 = out + 98304;
    float* o_cp2 = out + 122880;
    float* o_f   = out + 129024;
    float* o_f1  = out + 227328;
    float* o_f2  = out + 1800192;

    cudaFuncSetAttribute(ballq3_kernel<8192,16>, cudaFuncAttributeMaxDynamicSharedMemorySize, 8192*16);
    cudaFuncSetAttribute(hmma_kernel, cudaFuncAttributeMaxDynamicSharedMemorySize, HM_SMEM);

    void *vfeat,*vX,*vX2,*vcf,*vmr,*vmr2,*vp2,*vidx,*vgidx,*vmean,*vrstd,*vS,*vg,*vwl,*vwrh,*vwrl,*vw1h,*vw1l;
    cudaGetSymbolAddress(&vfeat, g_feat);
    cudaGetSymbolAddress(&vX,    g_X);
    cudaGetSymbolAddress(&vX2,   g_X2);
    cudaGetSymbolAddress(&vcf,   g_cf);
    cudaGetSymbolAddress(&vmr,   g_maxR);
    cudaGetSymbolAddress(&vmr2,  g_maxR2);
    cudaGetSymbolAddress(&vp2,   g_P2);
    cudaGetSymbolAddress(&vidx,  g_idx);
    cudaGetSymbolAddress(&vgidx, g_gidx);
    cudaGetSymbolAddress(&vmean, g_mean);
    cudaGetSymbolAddress(&vrstd, g_rstd);
    cudaGetSymbolAddress(&vS,    g_S);
    cudaGetSymbolAddress(&vg,    g_g);
    cudaGetSymbolAddress(&vwl,   g_WL);
    cudaGetSymbolAddress(&vwrh,  g_WRhi);
    cudaGetSymbolAddress(&vwrl,  g_WRlo);
    cudaGetSymbolAddress(&vw1h,  g_W1hi);
    cudaGetSymbolAddress(&vw1l,  g_W1lo);

    // ---- head: 3 launches; fps=3, gather=4, ballq3=5 (profiled) ----
    wsplit_kernel<<<(384*256+255)/256,256>>>(s1_w1,(__nv_bfloat16*)vw1h,(__nv_bfloat16*)vw1l,
        384, 195, 384, 256);                                                     // 0
    cudaMemcpyAsync(o_p, p, 98304*sizeof(float), cudaMemcpyDeviceToDevice, 0);   // 1
    cudaMemcpyAsync(o_f, f, 98304*sizeof(float), cudaMemcpyDeviceToDevice, 0);   // 2

    // ---------- stage 0: N=8192 -> M=2048, C=3, O=192 (Mpad 256), H=48 ----------
    {
        int N=8192, M=2048, C=3;
        fps_kernel<8192,2048><<<B,1024>>>(p, (int*)vidx);                        // 3
        gather_kernel<<<dim3(M/256,B),256>>>(p,f,(int*)vidx,o_cp1,(float*)vcf,N,M,C); // 4
        ballq3_kernel<8192,16><<<dim3(M/16,B),256,8192*16>>>(p,o_cp1,(int*)vgidx,M);  // 5 <- profiled
        featbuild_kernel<<<dim3(M*32/256,B),256>>>(p,f,o_cp1,(float*)vcf,(int*)vgidx,(float*)vfeat,N,M,C);
        run_stage_gemms<96,6>(M,C,192,48,256,0,
            s0_w1,s0_a1w1,s0_a1w2,s0_w2,s0_a2w1,s0_a2w2, o_f1,
            (float*)vfeat,(float*)vX,(float*)vX2,(float*)vmr,(float*)vmr2,(float*)vp2,
            (float*)vmean,(float*)vrstd,(float*)vS,(float*)vg,
            (float*)vwl,(__nv_bfloat16*)vwrh,(__nv_bfloat16*)vwrl,
            (__nv_bfloat16*)vw1h,(__nv_bfloat16*)vw1l);
    }
    // ---------- stage 1: N=2048 -> M=512, C=192, O=384 (Mpad 384), H=96 ----------
    {
        int N=2048, M=512, C=192;
        fps_kernel<2048,512><<<B,1024>>>(o_cp1, (int*)vidx);
        gather_kernel<<<dim3(M/256,B),256>>>(o_cp1,o_f1,(int*)vidx,o_cp2,(float*)vcf,N,M,C);
        ballq3_kernel<2048,16><<<dim3(M/16,B),256,2048*16>>>(o_cp1,o_cp2,(int*)vgidx,M);
        featbuild_kernel<<<dim3(M*32/256,B),256>>>(o_cp1,o_f1,o_cp2,(float*)vcf,(int*)vgidx,(float*)vfeat,N,M,C);
        run_stage_gemms<128,8>(M,C,384,96,384,1,
            s1_w1,s1_a1w1,s1_a1w2,s1_w2,s1_a2w1,s1_a2w2, o_f2,
            (float*)vfeat,(float*)vX,(float*)vX2,(float*)vmr,(float*)vmr2,(float*)vp2,
            (float*)vmean,(float*)vrstd,(float*)vS,(float*)vg,
            (float*)vwl,(__nv_bfloat16*)vwrh,(__nv_bfloat16*)vwrl,
            (__nv_bfloat16*)vw1h,(__nv_bfloat16*)vw1l);
    }
}

// round 11
// speedup vs baseline: 1.6013x; 1.3746x over previous
#include <cuda_runtime.h>
#include <cuda_bf16.h>
#include <stdint.h>
#include <math.h>

// ===================== constants =====================
static const int B = 4;

// ===================== device scratch =====================
__device__ float g_feat[4L*195*512*32];
__device__ float g_X  [4L*192*2048*32];
__device__ float g_X2 [4L*192*2048*32];
__device__ float g_cf [4L*192*512];
__device__ float g_maxR [4L*192*2048];
__device__ float g_maxR2[4L*192*2048];
__device__ float g_P2  [4L*192*2048];
__device__ int   g_idx [4*2048];
__device__ int   g_gidx [4*2048*32];
__device__ int   g_gidx2[4*512*32];
__device__ float g_mean[4*384], g_rstd[4*384], g_S[4*384], g_g[4*384];
__device__ float g_WL[4L*384*384];
__device__ __nv_bfloat16 g_WRhi[4L*384*384], g_WRlo[4L*384*384];
__device__ __nv_bfloat16 g_W1hi[384L*256],   g_W1lo[384L*256];

// ===================== small helpers =====================
__device__ __forceinline__ float dist2f(float ax,float ay,float az,float bx,float by,float bz){
    float dx=__fsub_rn(ax,bx), dy=__fsub_rn(ay,by), dz=__fsub_rn(az,bz);
    return __fadd_rn(__fadd_rn(__fmul_rn(dx,dx),__fmul_rn(dy,dy)),__fmul_rn(dz,dz));
}
__device__ __forceinline__ uint32_t smem_u32(const void* p){
    uint32_t a; asm("{ .reg .u64 t; cvta.to.shared.u64 t, %1; cvt.u32.u64 %0, t; }":"=r"(a):"l"(p));
    return a;
}
__device__ __forceinline__ uint32_t redux_max(uint32_t v){
    uint32_t r; asm("redux.sync.max.u32 %0, %1, 0xffffffff;" : "=r"(r) : "r"(v)); return r;
}
__device__ __forceinline__ void ldsm4(uint32_t* r, uint32_t addr){
    asm volatile("ldmatrix.sync.aligned.m8n8.x4.shared.b16 {%0,%1,%2,%3}, [%4];"
        :"=r"(r[0]),"=r"(r[1]),"=r"(r[2]),"=r"(r[3]):"r"(addr));
}
__device__ __forceinline__ void ldsm4t(uint32_t* r, uint32_t addr){
    asm volatile("ldmatrix.sync.aligned.m8n8.x4.trans.shared.b16 {%0,%1,%2,%3}, [%4];"
        :"=r"(r[0]),"=r"(r[1]),"=r"(r[2]),"=r"(r[3]):"r"(addr));
}
__device__ __forceinline__ void mma16816(float* d, const uint32_t* a, const uint32_t* b){
    asm volatile("mma.sync.aligned.m16n8k16.row.col.f32.bf16.bf16.f32 "
        "{%0,%1,%2,%3}, {%4,%5,%6,%7}, {%8,%9}, {%0,%1,%2,%3};"
        : "+f"(d[0]),"+f"(d[1]),"+f"(d[2]),"+f"(d[3])
        : "r"(a[0]),"r"(a[1]),"r"(a[2]),"r"(a[3]),"r"(b[0]),"r"(b[1]));
}
__device__ __forceinline__ void bf16split(float v, __nv_bfloat16& h, __nv_bfloat16& l){
    h = __float2bfloat16_rn(v);
    l = __float2bfloat16_rn(v - __bfloat162float(h));
}

// ===================== FPS v2: redux.sync reduction, smem point broadcast, 2 barriers ====
// Squared distances are >= 0, so float bits are order-isomorphic to uint compare.
// Lowest matching lane/warp = smallest index (lanes/warps ordered by index range).
template<int N, int M>
__global__ __launch_bounds__(1024) void fps_kernel(const float* __restrict__ p, int* __restrict__ outIdx)
{
    constexpr int NPT = N/1024;
    extern __shared__ float4 spt[];
    const int b = blockIdx.x, t = threadIdx.x;
    const float* pb = p + (long)b*N*3;
    float px[NPT],py[NPT],pz[NPT],dd[NPT];
#pragma unroll
    for(int j=0;j<NPT;j++){
        int gi = t*NPT+j;
        px[j]=pb[3*gi]; py[j]=pb[3*gi+1]; pz[j]=pb[3*gi+2];
        dd[j]=1e10f;
        spt[gi] = make_float4(px[j],py[j],pz[j],0.f);
    }
    __shared__ uint32_t swv[32];
    __shared__ int      swi[32];
    __shared__ int      sBi;
    if(t==0) outIdx[(long)b*M]=0;
    float lx=pb[0], ly=pb[1], lz=pb[2];
    __syncthreads();
    int lane = t&31, w = t>>5;
    for(int s=1;s<M;s++){
        float bv=-1e30f; int bi=0;
#pragma unroll
        for(int j=0;j<NPT;j++){
            float d = dist2f(px[j],py[j],pz[j],lx,ly,lz);
            float dm = fminf(dd[j], d);
            dd[j]=dm;
            if(dm>bv){ bv=dm; bi=t*NPT+j; }
        }
        uint32_t bits = __float_as_uint(bv);          // bv >= 0 always
        uint32_t mx = redux_max(bits);
        unsigned msk = __ballot_sync(0xffffffffu, bits==mx);
        int src = __ffs(msk)-1;
        bi = __shfl_sync(0xffffffffu, bi, src);
        if(lane==0){ swv[w]=mx; swi[w]=bi; }
        __syncthreads();
        if(t<32){
            uint32_t b2=swv[t]; int i2=swi[t];
            uint32_t m2 = redux_max(b2);
            unsigned k2 = __ballot_sync(0xffffffffu, b2==m2);
            int s2 = __ffs(k2)-1;
            i2 = __shfl_sync(0xffffffffu, i2, s2);
            if(t==0){ sBi=i2; outIdx[(long)b*M+s]=i2; }
        }
        __syncthreads();
        float4 wp = spt[sBi];
        lx=wp.x; ly=wp.y; lz=wp.z;
    }
}

// ===================== gather (combined + split variants) =====================
__global__ void gather_kernel(const float* __restrict__ p, const float* __restrict__ f,
                              const int* __restrict__ idx, float* __restrict__ cp,
                              float* __restrict__ cf, int N, int M, int C)
{
    int b = blockIdx.y;
    int i = blockIdx.x*blockDim.x + threadIdx.x;
    if(i>=M) return;
    int j = idx[(long)b*M+i];
    cp[((long)b*M+i)*3+0] = p[((long)b*N+j)*3+0];
    cp[((long)b*M+i)*3+1] = p[((long)b*N+j)*3+1];
    cp[((long)b*M+i)*3+2] = p[((long)b*N+j)*3+2];
    for(int c=0;c<C;c++)
        cf[((long)b*C+c)*M+i] = f[((long)b*C+c)*N+j];
}
__global__ void gatherpos_kernel(const float* __restrict__ p, const int* __restrict__ idx,
                                 float* __restrict__ cp, int N, int M)
{
    int b = blockIdx.y;
    int i = blockIdx.x*blockDim.x + threadIdx.x;
    if(i>=M) return;
    int j = idx[(long)b*M+i];
    cp[((long)b*M+i)*3+0] = p[((long)b*N+j)*3+0];
    cp[((long)b*M+i)*3+1] = p[((long)b*N+j)*3+1];
    cp[((long)b*M+i)*3+2] = p[((long)b*N+j)*3+2];
}
__global__ void gatherfeat_kernel(const float* __restrict__ f, const int* __restrict__ idx,
                                  float* __restrict__ cf, int N, int M, int C)
{
    int b = blockIdx.y;
    int i = blockIdx.x*blockDim.x + threadIdx.x;
    if(i>=M) return;
    int j = idx[(long)b*M+i];
    for(int c=0;c<C;c++)
        cf[((long)b*C+c)*M+i] = f[((long)b*C+c)*N+j];
}

// ===================== ball query v3 =====================
template<int N, int CPB>
__global__ __launch_bounds__(256) void ballq3_kernel(
    const float* __restrict__ pts, const float* __restrict__ ctr,
    int* __restrict__ gidx, int M)
{
    extern __shared__ float4 sp[];
    int b = blockIdx.y;
    const float* pb = pts + (long)b*N*3;
    for(int j=threadIdx.x;j<N;j+=blockDim.x)
        sp[j] = make_float4(pb[3*j],pb[3*j+1],pb[3*j+2],0.f);
    __syncthreads();
    int wid = threadIdx.x>>5, lane = threadIdx.x&31;
    constexpr int CPW = CPB/8;
    int base = blockIdx.x*CPB + wid*CPW;
    const float R2 = (float)(0.1*0.1);
#pragma unroll
    for(int c=0;c<CPW;c++){
        int i = base + c;
        float cx=ctr[((long)b*M+i)*3], cy=ctr[((long)b*M+i)*3+1], cz=ctr[((long)b*M+i)*3+2];
        int* out = gidx + ((long)b*M+i)*32;
        int cnt=0, first=0;
        for(int j0=0;j0<N;j0+=128){
            bool in[4];
            unsigned m[4];
#pragma unroll
            for(int q=0;q<4;q++){
                float4 pt = sp[j0+q*32+lane];
                in[q] = dist2f(cx,cy,cz,pt.x,pt.y,pt.z) < R2;
            }
#pragma unroll
            for(int q=0;q<4;q++) m[q] = __ballot_sync(0xffffffffu, in[q]);
#pragma unroll
            for(int q=0;q<4;q++){
                if(m[q] && cnt<32){
                    if(cnt==0) first = j0+q*32 + __ffs(m[q]) - 1;
                    int pos = cnt + __popc(m[q] & ((1u<<lane)-1u));
                    if(in[q] && pos<32) out[pos] = j0+q*32+lane;
                    cnt += __popc(m[q]);
                }
            }
            if(cnt>=32) break;
        }
        if(cnt<32){
            for(int k=cnt+lane;k<32;k+=32) out[k]=first;
        }
    }
}

// ===================== feature build (fp32) =====================
__global__ void featbuild_kernel(const float* __restrict__ p, const float* __restrict__ f,
                                 const float* __restrict__ cp, const float* __restrict__ cf,
                                 const int* __restrict__ gidx, float* __restrict__ feat,
                                 int N, int M, int C)
{
    int b = blockIdx.y;
    int gi = blockIdx.x*blockDim.x + threadIdx.x;
    int i = gi>>5, kk = gi&31;
    if(i>=M) return;
    int j = gidx[((long)b*M+i)*32+kk];
    long CH = C+3;
    float dx = __fsub_rn(p[((long)b*N+j)*3+0], cp[((long)b*M+i)*3+0]);
    float dy = __fsub_rn(p[((long)b*N+j)*3+1], cp[((long)b*M+i)*3+1]);
    float dz = __fsub_rn(p[((long)b*N+j)*3+2], cp[((long)b*M+i)*3+2]);
    feat[(((long)b*CH+0)*M+i)*32+kk] = dx;
    feat[(((long)b*CH+1)*M+i)*32+kk] = dy;
    feat[(((long)b*CH+2)*M+i)*32+kk] = dz;
    const float* fb  = f  + (long)b*C*N;
    const float* cfb = cf + (long)b*C*M;
    for(int c=0;c<C;c++)
        feat[(((long)b*CH+3+c)*M+i)*32+kk] = __fsub_rn(fb[(long)c*N+j], cfb[(long)c*M+i]);
}

// ===================== FFMA SGEMM =====================
template<int BM, int MR>
__global__ __launch_bounds__(256) void sgemm2_kernel(
    const float* __restrict__ A, long aStride,
    const float* __restrict__ X, float* __restrict__ C,
    const float* __restrict__ bias,
    const float* __restrict__ nmean, const float* __restrict__ nrstd,
    int Msz, int Ksz, int Nsz)
{
    __shared__ float As[2][16][BM];
    __shared__ float Xs[2][16][128];
    constexpr int AL = BM/16;
    int b = blockIdx.z, m0 = blockIdx.y*BM, n0 = blockIdx.x*128;
    const float* Ab = A + (long)b*aStride;
    const float* Xb = X + (long)b*(long)Ksz*Nsz;
    const float* mp = nmean ? nmean + (long)b*Ksz : nullptr;
    const float* rp = nrstd ? nrstd + (long)b*Ksz : nullptr;
    int t = threadIdx.x, tx = t&15, ty = t>>4;
    float acc[MR][8];
#pragma unroll
    for(int r=0;r<MR;r++)
#pragma unroll
        for(int c=0;c<8;c++) acc[r][c]=0.f;
    float  aR[AL];
    float4 xR[2];
    int nk = (Ksz+15)>>4;
    auto LOAD = [&](int k0){
#pragma unroll
        for(int i=0;i<AL;i++){
            int e=t+i*256, m=e%BM, k=e/BM;
            aR[i] = (k0+k<Ksz) ? Ab[(long)(m0+m)*Ksz + k0+k] : 0.f;
        }
#pragma unroll
        for(int j=0;j<2;j++){
            int e=t+j*256, k=e>>5, n4=e&31;
            if(k0+k<Ksz){
                float4 v = *(const float4*)(Xb + (long)(k0+k)*Nsz + n0 + n4*4);
                if(mp){
                    float mn=mp[k0+k], rs=rp[k0+k];
                    v.x=fmaxf((v.x-mn)*rs,0.f); v.y=fmaxf((v.y-mn)*rs,0.f);
                    v.z=fmaxf((v.z-mn)*rs,0.f); v.w=fmaxf((v.w-mn)*rs,0.f);
                }
                xR[j]=v;
            } else xR[j]=make_float4(0.f,0.f,0.f,0.f);
        }
    };
    auto STORE = [&](int buf){
#pragma unroll
        for(int i=0;i<AL;i++){ int e=t+i*256; As[buf][e/BM][e%BM]=aR[i]; }
#pragma unroll
        for(int j=0;j<2;j++){ int e=t+j*256; *(float4*)&Xs[buf][e>>5][(e&31)*4] = xR[j]; }
    };
    auto COMP = [&](int buf){
#pragma unroll
        for(int kk=0;kk<16;kk++){
            float a[MR];
#pragma unroll
            for(int r=0;r<MR;r++) a[r]=As[buf][kk][ty*MR+r];
            float4 b0 = *(float4*)&Xs[buf][kk][tx*8];
            float4 b1 = *(float4*)&Xs[buf][kk][tx*8+4];
            float bb[8] = {b0.x,b0.y,b0.z,b0.w,b1.x,b1.y,b1.z,b1.w};
#pragma unroll
            for(int r=0;r<MR;r++)
#pragma unroll
                for(int c=0;c<8;c++) acc[r][c] += a[r]*bb[c];
        }
    };
    LOAD(0); STORE(0); __syncthreads();
    for(int kt=0;kt<nk;kt++){
        int cur=kt&1;
        if(kt+1<nk) LOAD((kt+1)*16);
        COMP(cur);
        if(kt+1<nk){ STORE(cur^1); __syncthreads(); }
    }
#pragma unroll
    for(int r=0;r<MR;r++){
        int row=m0+ty*MR+r, col=n0+tx*8;
        float o[8];
#pragma unroll
        for(int c=0;c<8;c++) o[c]=acc[r][c];
        if(bias){
            const float* bb = bias + ((long)b*Msz+row)*(Nsz>>5);
#pragma unroll
            for(int c=0;c<8;c++) o[c] += bb[(col+c)>>5];
        }
        *(float4*)&C[((long)b*Msz+row)*(long)Nsz+col]   = make_float4(o[0],o[1],o[2],o[3]);
        *(float4*)&C[((long)b*Msz+row)*(long)Nsz+col+4] = make_float4(o[4],o[5],o[6],o[7]);
    }
}

// ===================== mma.sync bf16 GEMM (fused norm+split B build) =====================
__global__ __launch_bounds__(256) void hmma_kernel(
    const __nv_bfloat16* __restrict__ Ahi, const __nv_bfloat16* __restrict__ Alo,
    long aStride, int Kpad,
    const float* __restrict__ X, const float* __restrict__ nmean, const float* __restrict__ nrstd,
    const float* __restrict__ bias, float* __restrict__ Cout,
    int Msz, int Ksz, int Nsz)
{
    extern __shared__ char sm[];
    const uint32_t oAhi=0, oAlo=16384, oBhi=32768, oBlo=49152;
    uint32_t sbase = smem_u32(sm);

    int t = threadIdx.x, lane = t&31, w = t>>5;
    int wm = (w&1)*64, wn = (w>>1)*32;
    int bz = blockIdx.z, m0 = blockIdx.y*128, n0 = blockIdx.x*128;
    const __nv_bfloat16* Ah = Ahi + (long)bz*aStride;
    const __nv_bfloat16* Al = Alo + (long)bz*aStride;
    const float* Xb = X + (long)bz*(long)Ksz*Nsz;

    float acc[4][4][4];
#pragma unroll
    for(int i=0;i<4;i++)
#pragma unroll
        for(int j=0;j<4;j++)
#pragma unroll
            for(int q=0;q<4;q++) acc[i][j][q]=0.f;

    int ar = t>>1, ah = t&1;
    int bk = t>>2, bn = (t&3)*32;

    int nch = Kpad/64;
    for(int c=0;c<nch;c++){
        int k0 = c*64;
        {
            const uint4* gh = (const uint4*)(Ah + (long)(m0+ar)*Kpad + k0 + ah*32);
            const uint4* gl = (const uint4*)(Al + (long)(m0+ar)*Kpad + k0 + ah*32);
#pragma unroll
            for(int q=0;q<4;q++){
                uint32_t off = (uint32_t)ar*128u + (uint32_t)ah*64u + (uint32_t)q*16u;
                uint32_t sw = off ^ ((off>>3)&0x70u);
                *(uint4*)(sm + oAhi + sw) = gh[q];
                *(uint4*)(sm + oAlo + sw) = gl[q];
            }
        }
        {
            int kg = k0 + bk;
            bool valid = (kg < Ksz);
            float mn=0.f, rs=1.f;
            bool doact = (nmean != nullptr);
            if(doact && valid){ mn = nmean[(long)bz*Ksz+kg]; rs = nrstd[(long)bz*Ksz+kg]; }
            const float4* xr = (const float4*)(Xb + (long)kg*Nsz + n0 + bn);
#pragma unroll
            for(int q=0;q<4;q++){
                float xv[8];
                if(valid){
                    float4 v0 = xr[q*2], v1 = xr[q*2+1];
                    xv[0]=v0.x; xv[1]=v0.y; xv[2]=v0.z; xv[3]=v0.w;
                    xv[4]=v1.x; xv[5]=v1.y; xv[6]=v1.z; xv[7]=v1.w;
                    if(doact){
#pragma unroll
                        for(int j=0;j<8;j++) xv[j]=fmaxf((xv[j]-mn)*rs,0.f);
                    }
                } else {
#pragma unroll
                    for(int j=0;j<8;j++) xv[j]=0.f;
                }
                uint32_t hw[4], lw[4];
#pragma unroll
                for(int pq=0;pq<4;pq++){
                    float a=xv[pq*2], b2=xv[pq*2+1];
                    __nv_bfloat16 ha,la,hb,lb;
                    bf16split(a,ha,la); bf16split(b2,hb,lb);
                    __nv_bfloat162 hp=__halves2bfloat162(ha,hb);
                    __nv_bfloat162 lp=__halves2bfloat162(la,lb);
                    hw[pq]=*(uint32_t*)&hp;
                    lw[pq]=*(uint32_t*)&lp;
                }
                uint32_t off = (uint32_t)bk*256u + (uint32_t)bn*2u + (uint32_t)q*16u;
                uint32_t sw = off ^ ((off>>4)&0xF0u);
                *(uint4*)(sm + oBhi + sw) = make_uint4(hw[0],hw[1],hw[2],hw[3]);
                *(uint4*)(sm + oBlo + sw) = make_uint4(lw[0],lw[1],lw[2],lw[3]);
            }
        }
        __syncthreads();
#pragma unroll
        for(int kk=0;kk<4;kk++){
            uint32_t afh[4][4], afl[4][4];
#pragma unroll
            for(int mi=0;mi<4;mi++){
                uint32_t off = (uint32_t)(wm+mi*16+(lane&15))*128u + (uint32_t)kk*32u + (uint32_t)(lane>>4)*16u;
                uint32_t sw = off ^ ((off>>3)&0x70u);
                ldsm4(afh[mi], sbase + oAhi + sw);
                ldsm4(afl[mi], sbase + oAlo + sw);
            }
            uint32_t bfh[2][4], bfl[2][4];
#pragma unroll
            for(int nj=0;nj<2;nj++){
                uint32_t off = (uint32_t)(kk*16+(lane&15))*256u + (uint32_t)(wn+nj*16+(lane>>4)*8)*2u;
                uint32_t sw = off ^ ((off>>4)&0xF0u);
                ldsm4t(bfh[nj], sbase + oBhi + sw);
                ldsm4t(bfl[nj], sbase + oBlo + sw);
            }
#pragma unroll
            for(int mi=0;mi<4;mi++){
#pragma unroll
                for(int n8=0;n8<4;n8++){
                    const uint32_t* bh = &bfh[n8>>1][(n8&1)*2];
                    const uint32_t* bl = &bfl[n8>>1][(n8&1)*2];
                    mma16816(acc[mi][n8], afh[mi], bh);
                    mma16816(acc[mi][n8], afh[mi], bl);
                    mma16816(acc[mi][n8], afl[mi], bh);
                }
            }
        }
        __syncthreads();
    }

    int rbase = m0 + wm + (lane>>2);
    int cbase = n0 + wn + (lane&3)*2;
    int bcol = (n0 + wn) >> 5;
#pragma unroll
    for(int mi=0;mi<4;mi++){
        int r1 = rbase + mi*16;
        int r2 = r1 + 8;
        float bv1=0.f, bv2=0.f;
        if(bias){
            if(r1<Msz) bv1 = bias[((long)bz*Msz+r1)*(Nsz>>5) + bcol];
            if(r2<Msz) bv2 = bias[((long)bz*Msz+r2)*(Nsz>>5) + bcol];
        }
#pragma unroll
        for(int n8=0;n8<4;n8++){
            int col = cbase + n8*8;
            if(r1<Msz){
                float2 v = make_float2(acc[mi][n8][0]+bv1, acc[mi][n8][1]+bv1);
                *(float2*)&Cout[((long)bz*Msz+r1)*(long)Nsz+col] = v;
            }
            if(r2<Msz){
                float2 v = make_float2(acc[mi][n8][2]+bv2, acc[mi][n8][3]+bv2);
                *(float2*)&Cout[((long)bz*Msz+r2)*(long)Nsz+col] = v;
            }
        }
    }
}

// ===================== reductions =====================
__device__ __forceinline__ void blockReduce2(float& a, float& bsum){
    __shared__ float sa[32], sb[32];
    unsigned mm=0xffffffffu;
    for(int o=16;o;o>>=1){ a+=__shfl_down_sync(mm,a,o); bsum+=__shfl_down_sync(mm,bsum,o); }
    int w=threadIdx.x>>5, l=threadIdx.x&31;
    if(l==0){ sa[w]=a; sb[w]=bsum; }
    __syncthreads();
    int nw=(blockDim.x+31)>>5;
    if(threadIdx.x<32){
        a    = (threadIdx.x<nw)?sa[threadIdx.x]:0.f;
        bsum = (threadIdx.x<nw)?sb[threadIdx.x]:0.f;
        for(int o=16;o;o>>=1){ a+=__shfl_down_sync(mm,a,o); bsum+=__shfl_down_sync(mm,bsum,o); }
    }
}

__global__ void stats2_kernel(const float* __restrict__ X, float* __restrict__ mean,
                              float* __restrict__ rstd, float* __restrict__ maxRaw,
                              float* __restrict__ S, int M)
{
    __shared__ float bc[2];
    int bo = blockIdx.x;
    const float* xb = X + (long)bo*M*32;
    float s=0.f, s2=0.f;
    for(int i=threadIdx.x;i<M;i+=blockDim.x){
        const float4* row = (const float4*)(xb + (long)i*32);
        float mx=-1e30f;
#pragma unroll
        for(int q=0;q<8;q++){
            float4 v = row[q];
            s  += v.x+v.y+v.z+v.w;
            s2 += v.x*v.x+v.y*v.y+v.z*v.z+v.w*v.w;
            mx = fmaxf(mx, fmaxf(fmaxf(v.x,v.y), fmaxf(v.z,v.w)));
        }
        maxRaw[(long)bo*M+i]=mx;
    }
    blockReduce2(s,s2);
    if(threadIdx.x==0){
        float Cnt = (float)(M*32);
        float mn = s/Cnt;
        float var = s2/Cnt - mn*mn;
        float rs = rsqrtf(var+1e-5f);
        mean[bo]=mn; rstd[bo]=rs;
        bc[0]=mn; bc[1]=rs;
    }
    __syncthreads();
    float mn = bc[0], rs = bc[1];
    const float4* xv = (const float4*)xb;
    float sr=0.f;
    for(int i=threadIdx.x;i<M*8;i+=blockDim.x){
        float4 v = xv[i];
        sr += fmaxf((v.x-mn)*rs,0.f)+fmaxf((v.y-mn)*rs,0.f)
            + fmaxf((v.z-mn)*rs,0.f)+fmaxf((v.w-mn)*rs,0.f);
    }
    float d=0.f;
    blockReduce2(sr,d);
    if(threadIdx.x==0) S[bo]=sr;
}

__global__ void attn_kernel(const float* __restrict__ S, const float* __restrict__ w1,
                            const float* __restrict__ w2, float* __restrict__ g,
                            int O, int H, int Cnt)
{
    int b = blockIdx.x, t = threadIdx.x;
    __shared__ float ss[384], hh[96];
    if(t<O) ss[t] = S[(long)b*O+t] / (float)Cnt;
    __syncthreads();
    if(t<H){
        float a=0.f;
        for(int o=0;o<O;o++) a += w1[(long)t*O+o]*ss[o];
        hh[t]=fmaxf(a,0.f);
    }
    __syncthreads();
    if(t<O){
        float a=0.f;
        for(int j=0;j<H;j++) a += w2[(long)t*H+j]*hh[j];
        g[(long)b*O+t] = 1.f/(1.f+expf(-a));
    }
}

__global__ void wprep_kernel(const float* __restrict__ w2, const float* __restrict__ g,
                             float* __restrict__ WL, __nv_bfloat16* __restrict__ WRhi,
                             __nv_bfloat16* __restrict__ WRlo, int O, int Mpad)
{
    int b = blockIdx.y;
    int e = blockIdx.x*blockDim.x + threadIdx.x;
    if(e>=Mpad*O) return;
    int o=e/O, c=e%O;
    float vr = 0.f;
    if(o<O){
        float gg = g[(long)b*O+c];
        WL[(long)b*O*O + (long)o*O + c] = __fmul_rn(w2[(long)o*2*O + c], gg);
        vr = __fmul_rn(w2[(long)o*2*O + O + c], gg);
    }
    __nv_bfloat16 h,l; bf16split(vr,h,l);
    WRhi[(long)b*Mpad*O+e] = h;
    WRlo[(long)b*Mpad*O+e] = l;
}

__global__ void wsplit_kernel(const float* __restrict__ w, __nv_bfloat16* __restrict__ hi,
                              __nv_bfloat16* __restrict__ lo, int O, int K, int Mpad, int Kpad)
{
    int e = blockIdx.x*blockDim.x + threadIdx.x;
    if(e>=Mpad*Kpad) return;
    int r=e/Kpad, c=e%Kpad;
    float v = (r<O && c<K) ? w[(long)r*K+c] : 0.f;
    __nv_bfloat16 h,l; bf16split(v,h,l);
    hi[e]=h; lo[e]=l;
}

__global__ void final_kernel(const float* __restrict__ maxRaw2, const float* __restrict__ mean,
                             const float* __restrict__ rstd, const float* __restrict__ g,
                             float* __restrict__ out, long total, int Mctr)
{
    long e = (long)blockIdx.x*blockDim.x + threadIdx.x;
    if(e>=total) return;
    long bo = e/Mctr;
    float y = fmaxf((maxRaw2[e]-mean[bo])*rstd[bo], 0.f);
    out[e] = __fmul_rn(g[bo], y);
}

// ===================== host-side drivers =====================
static const int HM_SMEM = 65536;

template<int BM, int MR>
static void run_stage_gemms(int M, int C, int O, int H, int Mpad, int stage,
                      const float* w1, const float* a1w1, const float* a1w2,
                      const float* w2, const float* a2w1, const float* a2w2,
                      float* f_out,
                      float* feat, float* X, float* X2,
                      float* maxR, float* maxR2, float* P2,
                      float* mean, float* rstd, float* S, float* gAtt,
                      float* WL, __nv_bfloat16* WRhi, __nv_bfloat16* WRlo,
                      __nv_bfloat16* W1hi, __nv_bfloat16* W1lo)
{
    int NN = M*32;
    if(stage==0){
        sgemm2_kernel<BM,MR><<<dim3(NN/128,O/BM,B),256>>>(w1,0,feat,X,nullptr,nullptr,nullptr,O,C+3,NN);
    } else {
        hmma_kernel<<<dim3(NN/128,Mpad/128,B),256,HM_SMEM>>>(
            W1hi, W1lo, 0, 256, feat, nullptr, nullptr, nullptr, X, O, C+3, NN);
    }
    stats2_kernel<<<B*O,256>>>(X, mean, rstd, maxR, S, M);
    attn_kernel<<<B,384>>>(S, a1w1, a1w2, gAtt, O, H, NN);
    wprep_kernel<<<dim3((Mpad*O+255)/256,B),256>>>(w2, gAtt, WL, WRhi, WRlo, O, Mpad);
    sgemm2_kernel<BM,MR><<<dim3(M/128,O/BM,B),256>>>(WL,(long)O*O,maxR,P2,nullptr,mean,rstd,O,O,M);
    hmma_kernel<<<dim3(NN/128,Mpad/128,B),256,HM_SMEM>>>(
        WRhi, WRlo, (long)Mpad*O, O, X, mean, rstd, P2, X2, O, O, NN);
    stats2_kernel<<<B*O,256>>>(X2, mean, rstd, maxR2, S, M);
    attn_kernel<<<B,384>>>(S, a2w1, a2w2, gAtt, O, H, NN);
    final_kernel<<<(int)(((long)B*O*M+255)/256),256>>>(maxR2, mean, rstd, gAtt, f_out, (long)B*O*M, M);
}

extern "C" void kernel_launch(void* const* d_in, const int* in_sizes, int n_in,
                              void* d_out, int out_size)
{
    const float* p      = (const float*)d_in[0];
    const float* f      = (const float*)d_in[1];
    const float* s0_w1  = (const float*)d_in[2];
    const float* s0_a1w1= (const float*)d_in[3];
    const float* s0_a1w2= (const float*)d_in[4];
    const float* s0_w2  = (const float*)d_in[5];
    const float* s0_a2w1= (const float*)d_in[6];
    const float* s0_a2w2= (const float*)d_in[7];
    const float* s1_w1  = (const float*)d_in[8];
    const float* s1_a1w1= (const float*)d_in[9];
    const float* s1_a1w2= (const float*)d_in[10];
    const float* s1_w2  = (const float*)d_in[11];
    const float* s1_a2w1= (const float*)d_in[12];
    const float* s1_a2w2= (const float*)d_in[13];

    float* out   = (float*)d_out;
    float* o_p   = out;
    float* o_cp1 = out + 98304;
    float* o_cp2 = out + 122880;
    float* o_f   = out + 129024;
    float* o_f1  = out + 227328;
    float* o_f2  = out + 1800192;

    static cudaStream_t s2 = nullptr;
    static cudaEvent_t evFork = nullptr, evJoin = nullptr;
    if(!s2){
        cudaStreamCreate(&s2);
        cudaEventCreateWithFlags(&evFork, cudaEventDisableTiming);
        cudaEventCreateWithFlags(&evJoin, cudaEventDisableTiming);
        cudaFuncSetAttribute(fps_kernel<8192,2048>, cudaFuncAttributeMaxDynamicSharedMemorySize, 8192*16);
        cudaFuncSetAttribute(ballq3_kernel<8192,16>, cudaFuncAttributeMaxDynamicSharedMemorySize, 8192*16);
        cudaFuncSetAttribute(hmma_kernel, cudaFuncAttributeMaxDynamicSharedMemorySize, HM_SMEM);
    }

    void *vfeat,*vX,*vX2,*vcf,*vmr,*vmr2,*vp2,*vidx,*vgidx,*vgidx2,*vmean,*vrstd,*vS,*vg,*vwl,*vwrh,*vwrl,*vw1h,*vw1l;
    cudaGetSymbolAddress(&vfeat, g_feat);
    cudaGetSymbolAddress(&vX,    g_X);
    cudaGetSymbolAddress(&vX2,   g_X2);
    cudaGetSymbolAddress(&vcf,   g_cf);
    cudaGetSymbolAddress(&vmr,   g_maxR);
    cudaGetSymbolAddress(&vmr2,  g_maxR2);
    cudaGetSymbolAddress(&vp2,   g_P2);
    cudaGetSymbolAddress(&vidx,  g_idx);
    cudaGetSymbolAddress(&vgidx, g_gidx);
    cudaGetSymbolAddress(&vgidx2,g_gidx2);
    cudaGetSymbolAddress(&vmean, g_mean);
    cudaGetSymbolAddress(&vrstd, g_rstd);
    cudaGetSymbolAddress(&vS,    g_S);
    cudaGetSymbolAddress(&vg,    g_g);
    cudaGetSymbolAddress(&vwl,   g_WL);
    cudaGetSymbolAddress(&vwrh,  g_WRhi);
    cudaGetSymbolAddress(&vwrl,  g_WRlo);
    cudaGetSymbolAddress(&vw1h,  g_W1hi);
    cudaGetSymbolAddress(&vw1l,  g_W1lo);

    // ---- head: 5 launches; fps0 = ncu launch #5 ----
    wsplit_kernel<<<(384*256+255)/256,256>>>(s1_w1,(__nv_bfloat16*)vw1h,(__nv_bfloat16*)vw1l,
        384, 195, 384, 256);                                                     // 0
    cudaMemcpyAsync(o_p,         p,         49152*sizeof(float), cudaMemcpyDeviceToDevice, 0); // 1
    cudaMemcpyAsync(o_p + 49152, p + 49152, 49152*sizeof(float), cudaMemcpyDeviceToDevice, 0); // 2
    cudaMemcpyAsync(o_f,         f,         49152*sizeof(float), cudaMemcpyDeviceToDevice, 0); // 3
    cudaMemcpyAsync(o_f + 49152, f + 49152, 49152*sizeof(float), cudaMemcpyDeviceToDevice, 0); // 4

    // ---------- stage 0: N=8192 -> M=2048, C=3, O=192 (Mpad 256), H=48 ----------
    {
        int N=8192, M=2048, C=3;
        fps_kernel<8192,2048><<<B,1024,8192*16>>>(p, (int*)vidx);                // 5 <- profiled
        gather_kernel<<<dim3(M/256,B),256>>>(p,f,(int*)vidx,o_cp1,(float*)vcf,N,M,C);

        // ---- fork: stage-1 geometry (needs only o_cp1) runs concurrent with stage-0 GEMMs ----
        cudaEventRecord(evFork, 0);
        cudaStreamWaitEvent(s2, evFork, 0);
        fps_kernel<2048,512><<<B,1024,2048*16,s2>>>(o_cp1, (int*)vidx);
        gatherpos_kernel<<<dim3(512/256,B),256,0,s2>>>(o_cp1,(int*)vidx,o_cp2,2048,512);
        ballq3_kernel<2048,16><<<dim3(512/16,B),256,2048*16,s2>>>(o_cp1,o_cp2,(int*)vgidx2,512);
        cudaEventRecord(evJoin, s2);

        ballq3_kernel<8192,16><<<dim3(M/16,B),256,8192*16>>>(p,o_cp1,(int*)vgidx,M);
        featbuild_kernel<<<dim3(M*32/256,B),256>>>(p,f,o_cp1,(float*)vcf,(int*)vgidx,(float*)vfeat,N,M,C);
        run_stage_gemms<96,6>(M,C,192,48,256,0,
            s0_w1,s0_a1w1,s0_a1w2,s0_w2,s0_a2w1,s0_a2w2, o_f1,
            (float*)vfeat,(float*)vX,(float*)vX2,(float*)vmr,(float*)vmr2,(float*)vp2,
            (float*)vmean,(float*)vrstd,(float*)vS,(float*)vg,
            (float*)vwl,(__nv_bfloat16*)vwrh,(__nv_bfloat16*)vwrl,
            (__nv_bfloat16*)vw1h,(__nv_bfloat16*)vw1l);
    }
    // ---------- stage 1: N=2048 -> M=512, C=192, O=384 (Mpad 384), H=96 ----------
    {
        int N=2048, M=512, C=192;
        cudaStreamWaitEvent(0, evJoin, 0);
        gatherfeat_kernel<<<dim3(M/256,B),256>>>(o_f1,(int*)vidx,(float*)vcf,N,M,C);
        featbuild_kernel<<<dim3(M*32/256,B),256>>>(o_cp1,o_f1,o_cp2,(float*)vcf,(int*)vgidx2,(float*)vfeat,N,M,C);
        run_stage_gemms<128,8>(M,C,384,96,384,1,
            s1_w1,s1_a1w1,s1_a1w2,s1_w2,s1_a2w1,s1_a2w2, o_f2,
            (float*)vfeat,(float*)vX,(float*)vX2,(float*)vmr,(float*)vmr2,(float*)vp2,
            (float*)vmean,(float*)vrstd,(float*)vS,(float*)vg,
            (float*)vwl,(__nv_bfloat16*)vwrh,(__nv_bfloat16*)vwrl,
            (__nv_bfloat16*)vw1h,(__nv_bfloat16*)vw1l);
    }
}

// round 15
// speedup vs baseline: 1.6378x; 1.0228x over previous
#include <cuda_runtime.h>
#include <cuda_bf16.h>
#include <stdint.h>
#include <math.h>

// ===================== constants =====================
static const int B = 4;

// ===================== device scratch =====================
__device__ float g_feat[4L*195*512*32];
__device__ float g_X  [4L*192*2048*32];
__device__ float g_X2 [4L*192*2048*32];
__device__ float g_cf [4L*192*512];
__device__ float g_maxR [4L*192*2048];
__device__ float g_maxR2[4L*192*2048];
__device__ float g_P2  [4L*192*2048];
__device__ int   g_idx [4*2048];
__device__ int   g_idx1[4*512];
__device__ int   g_gidx [4*2048*32];
__device__ int   g_gidx2[4*512*32];
__device__ float g_dd  [4L*8192];
__device__ float g_mean[4*384], g_rstd[4*384], g_S[4*384], g_g[4*384];
__device__ float g_WL[4L*384*384];
__device__ __nv_bfloat16 g_WRhi[4L*384*384], g_WRlo[4L*384*384];
__device__ __nv_bfloat16 g_W1hi[384L*256],   g_W1lo[384L*256];

// ===================== small helpers =====================
__device__ __forceinline__ float dist2f(float ax,float ay,float az,float bx,float by,float bz){
    float dx=__fsub_rn(ax,bx), dy=__fsub_rn(ay,by), dz=__fsub_rn(az,bz);
    return __fadd_rn(__fadd_rn(__fmul_rn(dx,dx),__fmul_rn(dy,dy)),__fmul_rn(dz,dz));
}
__device__ __forceinline__ uint32_t smem_u32(const void* p){
    uint32_t a; asm("{ .reg .u64 t; cvta.to.shared.u64 t, %1; cvt.u32.u64 %0, t; }":"=r"(a):"l"(p));
    return a;
}
__device__ __forceinline__ uint32_t redux_max(uint32_t v){
    uint32_t r; asm("redux.sync.max.u32 %0, %1, 0xffffffff;" : "=r"(r) : "r"(v)); return r;
}
__device__ __forceinline__ void ldsm4(uint32_t* r, uint32_t addr){
    asm volatile("ldmatrix.sync.aligned.m8n8.x4.shared.b16 {%0,%1,%2,%3}, [%4];"
        :"=r"(r[0]),"=r"(r[1]),"=r"(r[2]),"=r"(r[3]):"r"(addr));
}
__device__ __forceinline__ void ldsm4t(uint32_t* r, uint32_t addr){
    asm volatile("ldmatrix.sync.aligned.m8n8.x4.trans.shared.b16 {%0,%1,%2,%3}, [%4];"
        :"=r"(r[0]),"=r"(r[1]),"=r"(r[2]),"=r"(r[3]):"r"(addr));
}
__device__ __forceinline__ void mma16816(float* d, const uint32_t* a, const uint32_t* b){
    asm volatile("mma.sync.aligned.m16n8k16.row.col.f32.bf16.bf16.f32 "
        "{%0,%1,%2,%3}, {%4,%5,%6,%7}, {%8,%9}, {%0,%1,%2,%3};"
        : "+f"(d[0]),"+f"(d[1]),"+f"(d[2]),"+f"(d[3])
        : "r"(a[0]),"r"(a[1]),"r"(a[2]),"r"(a[3]),"r"(b[0]),"r"(b[1]));
}
__device__ __forceinline__ void bf16split(float v, __nv_bfloat16& h, __nv_bfloat16& l){
    h = __float2bfloat16_rn(v);
    l = __float2bfloat16_rn(v - __bfloat162float(h));
}

// ===================== FPS (chunked, redux reduction) =====================
template<int N, int M, int S0, int S1>
__global__ __launch_bounds__(1024) void fps_part(const float* __restrict__ p, int* __restrict__ outIdx,
                                                 float* __restrict__ ddG)
{
    constexpr int NPT = N/1024;
    extern __shared__ float4 spt[];
    const int b = blockIdx.x, t = threadIdx.x;
    const float* pb = p + (long)b*N*3;
    float px[NPT],py[NPT],pz[NPT],dd[NPT];
#pragma unroll
    for(int j=0;j<NPT;j++){
        int gi = t*NPT+j;
        px[j]=pb[3*gi]; py[j]=pb[3*gi+1]; pz[j]=pb[3*gi+2];
        dd[j] = (S0==1) ? 1e10f : ddG[(long)b*N + gi];
        spt[gi] = make_float4(px[j],py[j],pz[j],0.f);
    }
    __shared__ uint32_t swv[32];
    __shared__ int      swi[32];
    __shared__ int      sBi;
    float lx,ly,lz;
    __syncthreads();
    if(S0==1){
        if(t==0) outIdx[(long)b*M]=0;
        lx=pb[0]; ly=pb[1]; lz=pb[2];
    } else {
        int li = outIdx[(long)b*M + S0-1];
        float4 wp = spt[li];
        lx=wp.x; ly=wp.y; lz=wp.z;
    }
    int lane = t&31, w = t>>5;
    for(int s=S0;s<S1;s++){
        float bv=-1e30f; int bi=0;
#pragma unroll
        for(int j=0;j<NPT;j++){
            float d = dist2f(px[j],py[j],pz[j],lx,ly,lz);
            float dm = fminf(dd[j], d);
            dd[j]=dm;
            if(dm>bv){ bv=dm; bi=t*NPT+j; }
        }
        uint32_t bits = __float_as_uint(bv);
        uint32_t mx = redux_max(bits);
        unsigned msk = __ballot_sync(0xffffffffu, bits==mx);
        int src = __ffs(msk)-1;
        bi = __shfl_sync(0xffffffffu, bi, src);
        if(lane==0){ swv[w]=mx; swi[w]=bi; }
        __syncthreads();
        if(t<32){
            uint32_t b2=swv[t]; int i2=swi[t];
            uint32_t m2 = redux_max(b2);
            unsigned k2 = __ballot_sync(0xffffffffu, b2==m2);
            int s2i = __ffs(k2)-1;
            i2 = __shfl_sync(0xffffffffu, i2, s2i);
            if(t==0){ sBi=i2; outIdx[(long)b*M+s]=i2; }
        }
        __syncthreads();
        float4 wp = spt[sBi];
        lx=wp.x; ly=wp.y; lz=wp.z;
    }
    if(S1<M){
#pragma unroll
        for(int j=0;j<NPT;j++) ddG[(long)b*N + t*NPT+j] = dd[j];
    }
}

// ===================== gather (ranged) =====================
__global__ void gather_kernel(const float* __restrict__ p, const float* __restrict__ f,
                              const int* __restrict__ idx, float* __restrict__ cp,
                              float* __restrict__ cf, int N, int M, int C, int i0)
{
    int b = blockIdx.y;
    int i = i0 + blockIdx.x*blockDim.x + threadIdx.x;
    if(i>=M) return;
    int j = idx[(long)b*M+i];
    cp[((long)b*M+i)*3+0] = p[((long)b*N+j)*3+0];
    cp[((long)b*M+i)*3+1] = p[((long)b*N+j)*3+1];
    cp[((long)b*M+i)*3+2] = p[((long)b*N+j)*3+2];
    for(int c=0;c<C;c++)
        cf[((long)b*C+c)*M+i] = f[((long)b*C+c)*N+j];
}
__global__ void gatherpos_kernel(const float* __restrict__ p, const int* __restrict__ idx,
                                 float* __restrict__ cp, int N, int M)
{
    int b = blockIdx.y;
    int i = blockIdx.x*blockDim.x + threadIdx.x;
    if(i>=M) return;
    int j = idx[(long)b*M+i];
    cp[((long)b*M+i)*3+0] = p[((long)b*N+j)*3+0];
    cp[((long)b*M+i)*3+1] = p[((long)b*N+j)*3+1];
    cp[((long)b*M+i)*3+2] = p[((long)b*N+j)*3+2];
}
__global__ void gatherfeat_kernel(const float* __restrict__ f, const int* __restrict__ idx,
                                  float* __restrict__ cf, int N, int M, int C)
{
    int b = blockIdx.y;
    int i = blockIdx.x*blockDim.x + threadIdx.x;
    if(i>=M) return;
    int j = idx[(long)b*M+i];
    for(int c=0;c<C;c++)
        cf[((long)b*C+c)*M+i] = f[((long)b*C+c)*N+j];
}

// ===================== ball query v3 (ranged) =====================
template<int N, int CPB>
__global__ __launch_bounds__(256) void ballq3_kernel(
    const float* __restrict__ pts, const float* __restrict__ ctr,
    int* __restrict__ gidx, int M, int i0)
{
    extern __shared__ float4 sp[];
    int b = blockIdx.y;
    const float* pb = pts + (long)b*N*3;
    for(int j=threadIdx.x;j<N;j+=blockDim.x)
        sp[j] = make_float4(pb[3*j],pb[3*j+1],pb[3*j+2],0.f);
    __syncthreads();
    int wid = threadIdx.x>>5, lane = threadIdx.x&31;
    constexpr int CPW = CPB/8;
    int base = i0 + blockIdx.x*CPB + wid*CPW;
    const float R2 = (float)(0.1*0.1);
#pragma unroll
    for(int c=0;c<CPW;c++){
        int i = base + c;
        float cx=ctr[((long)b*M+i)*3], cy=ctr[((long)b*M+i)*3+1], cz=ctr[((long)b*M+i)*3+2];
        int* out = gidx + ((long)b*M+i)*32;
        int cnt=0, first=0;
        for(int j0=0;j0<N;j0+=128){
            bool in[4];
            unsigned m[4];
#pragma unroll
            for(int q=0;q<4;q++){
                float4 pt = sp[j0+q*32+lane];
                in[q] = dist2f(cx,cy,cz,pt.x,pt.y,pt.z) < R2;
            }
#pragma unroll
            for(int q=0;q<4;q++) m[q] = __ballot_sync(0xffffffffu, in[q]);
#pragma unroll
            for(int q=0;q<4;q++){
                if(m[q] && cnt<32){
                    if(cnt==0) first = j0+q*32 + __ffs(m[q]) - 1;
                    int pos = cnt + __popc(m[q] & ((1u<<lane)-1u));
                    if(in[q] && pos<32) out[pos] = j0+q*32+lane;
                    cnt += __popc(m[q]);
                }
            }
            if(cnt>=32) break;
        }
        if(cnt<32){
            for(int k=cnt+lane;k<32;k+=32) out[k]=first;
        }
    }
}

// ===================== feature build (ranged) =====================
__global__ void featbuild_kernel(const float* __restrict__ p, const float* __restrict__ f,
                                 const float* __restrict__ cp, const float* __restrict__ cf,
                                 const int* __restrict__ gidx, float* __restrict__ feat,
                                 int N, int M, int C, int i0)
{
    int b = blockIdx.y;
    int gi = blockIdx.x*blockDim.x + threadIdx.x;
    int i = i0 + (gi>>5), kk = gi&31;
    if(i>=M) return;
    int j = gidx[((long)b*M+i)*32+kk];
    long CH = C+3;
    float dx = __fsub_rn(p[((long)b*N+j)*3+0], cp[((long)b*M+i)*3+0]);
    float dy = __fsub_rn(p[((long)b*N+j)*3+1], cp[((long)b*M+i)*3+1]);
    float dz = __fsub_rn(p[((long)b*N+j)*3+2], cp[((long)b*M+i)*3+2]);
    feat[(((long)b*CH+0)*M+i)*32+kk] = dx;
    feat[(((long)b*CH+1)*M+i)*32+kk] = dy;
    feat[(((long)b*CH+2)*M+i)*32+kk] = dz;
    const float* fb  = f  + (long)b*C*N;
    const float* cfb = cf + (long)b*C*M;
    for(int c=0;c<C;c++)
        feat[(((long)b*CH+3+c)*M+i)*32+kk] = __fsub_rn(fb[(long)c*N+j], cfb[(long)c*M+i]);
}

// ===================== FFMA SGEMM (n-offset capable) =====================
template<int BM, int MR>
__global__ __launch_bounds__(256) void sgemm2_kernel(
    const float* __restrict__ A, long aStride,
    const float* __restrict__ X, float* __restrict__ C,
    const float* __restrict__ bias,
    const float* __restrict__ nmean, const float* __restrict__ nrstd,
    int Msz, int Ksz, int Nsz, int nOff)
{
    __shared__ float As[2][16][BM];
    __shared__ float Xs[2][16][128];
    constexpr int AL = BM/16;
    int b = blockIdx.z, m0 = blockIdx.y*BM, n0 = blockIdx.x*128 + nOff;
    const float* Ab = A + (long)b*aStride;
    const float* Xb = X + (long)b*(long)Ksz*Nsz;
    const float* mp = nmean ? nmean + (long)b*Ksz : nullptr;
    const float* rp = nrstd ? nrstd + (long)b*Ksz : nullptr;
    int t = threadIdx.x, tx = t&15, ty = t>>4;
    float acc[MR][8];
#pragma unroll
    for(int r=0;r<MR;r++)
#pragma unroll
        for(int c=0;c<8;c++) acc[r][c]=0.f;
    float  aR[AL];
    float4 xR[2];
    int nk = (Ksz+15)>>4;
    auto LOAD = [&](int k0){
#pragma unroll
        for(int i=0;i<AL;i++){
            int e=t+i*256, m=e%BM, k=e/BM;
            aR[i] = (k0+k<Ksz) ? Ab[(long)(m0+m)*Ksz + k0+k] : 0.f;
        }
#pragma unroll
        for(int j=0;j<2;j++){
            int e=t+j*256, k=e>>5, n4=e&31;
            if(k0+k<Ksz){
                float4 v = *(const float4*)(Xb + (long)(k0+k)*Nsz + n0 + n4*4);
                if(mp){
                    float mn=mp[k0+k], rs=rp[k0+k];
                    v.x=fmaxf((v.x-mn)*rs,0.f); v.y=fmaxf((v.y-mn)*rs,0.f);
                    v.z=fmaxf((v.z-mn)*rs,0.f); v.w=fmaxf((v.w-mn)*rs,0.f);
                }
                xR[j]=v;
            } else xR[j]=make_float4(0.f,0.f,0.f,0.f);
        }
    };
    auto STORE = [&](int buf){
#pragma unroll
        for(int i=0;i<AL;i++){ int e=t+i*256; As[buf][e/BM][e%BM]=aR[i]; }
#pragma unroll
        for(int j=0;j<2;j++){ int e=t+j*256; *(float4*)&Xs[buf][e>>5][(e&31)*4] = xR[j]; }
    };
    auto COMP = [&](int buf){
#pragma unroll
        for(int kk=0;kk<16;kk++){
            float a[MR];
#pragma unroll
            for(int r=0;r<MR;r++) a[r]=As[buf][kk][ty*MR+r];
            float4 b0 = *(float4*)&Xs[buf][kk][tx*8];
            float4 b1 = *(float4*)&Xs[buf][kk][tx*8+4];
            float bb[8] = {b0.x,b0.y,b0.z,b0.w,b1.x,b1.y,b1.z,b1.w};
#pragma unroll
            for(int r=0;r<MR;r++)
#pragma unroll
                for(int c=0;c<8;c++) acc[r][c] += a[r]*bb[c];
        }
    };
    LOAD(0); STORE(0); __syncthreads();
    for(int kt=0;kt<nk;kt++){
        int cur=kt&1;
        if(kt+1<nk) LOAD((kt+1)*16);
        COMP(cur);
        if(kt+1<nk){ STORE(cur^1); __syncthreads(); }
    }
#pragma unroll
    for(int r=0;r<MR;r++){
        int row=m0+ty*MR+r, col=n0+tx*8;
        float o[8];
#pragma unroll
        for(int c=0;c<8;c++) o[c]=acc[r][c];
        if(bias){
            const float* bb = bias + ((long)b*Msz+row)*(Nsz>>5);
#pragma unroll
            for(int c=0;c<8;c++) o[c] += bb[(col+c)>>5];
        }
        *(float4*)&C[((long)b*Msz+row)*(long)Nsz+col]   = make_float4(o[0],o[1],o[2],o[3]);
        *(float4*)&C[((long)b*Msz+row)*(long)Nsz+col+4] = make_float4(o[4],o[5],o[6],o[7]);
    }
}

// ===================== mma.sync bf16 GEMM =====================
__global__ __launch_bounds__(256) void hmma_kernel(
    const __nv_bfloat16* __restrict__ Ahi, const __nv_bfloat16* __restrict__ Alo,
    long aStride, int Kpad,
    const float* __restrict__ X, const float* __restrict__ nmean, const float* __restrict__ nrstd,
    const float* __restrict__ bias, float* __restrict__ Cout,
    int Msz, int Ksz, int Nsz)
{
    extern __shared__ char sm[];
    const uint32_t oAhi=0, oAlo=16384, oBhi=32768, oBlo=49152;
    uint32_t sbase = smem_u32(sm);

    int t = threadIdx.x, lane = t&31, w = t>>5;
    int wm = (w&1)*64, wn = (w>>1)*32;
    int bz = blockIdx.z, m0 = blockIdx.y*128, n0 = blockIdx.x*128;
    const __nv_bfloat16* Ah = Ahi + (long)bz*aStride;
    const __nv_bfloat16* Al = Alo + (long)bz*aStride;
    const float* Xb = X + (long)bz*(long)Ksz*Nsz;

    float acc[4][4][4];
#pragma unroll
    for(int i=0;i<4;i++)
#pragma unroll
        for(int j=0;j<4;j++)
#pragma unroll
            for(int q=0;q<4;q++) acc[i][j][q]=0.f;

    int ar = t>>1, ah = t&1;
    int bk = t>>2, bn = (t&3)*32;

    int nch = Kpad/64;
    for(int c=0;c<nch;c++){
        int k0 = c*64;
        {
            const uint4* gh = (const uint4*)(Ah + (long)(m0+ar)*Kpad + k0 + ah*32);
            const uint4* gl = (const uint4*)(Al + (long)(m0+ar)*Kpad + k0 + ah*32);
#pragma unroll
            for(int q=0;q<4;q++){
                uint32_t off = (uint32_t)ar*128u + (uint32_t)ah*64u + (uint32_t)q*16u;
                uint32_t sw = off ^ ((off>>3)&0x70u);
                *(uint4*)(sm + oAhi + sw) = gh[q];
                *(uint4*)(sm + oAlo + sw) = gl[q];
            }
        }
        {
            int kg = k0 + bk;
            bool valid = (kg < Ksz);
            float mn=0.f, rs=1.f;
            bool doact = (nmean != nullptr);
            if(doact && valid){ mn = nmean[(long)bz*Ksz+kg]; rs = nrstd[(long)bz*Ksz+kg]; }
            const float4* xr = (const float4*)(Xb + (long)kg*Nsz + n0 + bn);
#pragma unroll
            for(int q=0;q<4;q++){
                float xv[8];
                if(valid){
                    float4 v0 = xr[q*2], v1 = xr[q*2+1];
                    xv[0]=v0.x; xv[1]=v0.y; xv[2]=v0.z; xv[3]=v0.w;
                    xv[4]=v1.x; xv[5]=v1.y; xv[6]=v1.z; xv[7]=v1.w;
                    if(doact){
#pragma unroll
                        for(int j=0;j<8;j++) xv[j]=fmaxf((xv[j]-mn)*rs,0.f);
                    }
                } else {
#pragma unroll
                    for(int j=0;j<8;j++) xv[j]=0.f;
                }
                uint32_t hw[4], lw[4];
#pragma unroll
                for(int pq=0;pq<4;pq++){
                    float a=xv[pq*2], b2=xv[pq*2+1];
                    __nv_bfloat16 ha,la,hb,lb;
                    bf16split(a,ha,la); bf16split(b2,hb,lb);
                    __nv_bfloat162 hp=__halves2bfloat162(ha,hb);
                    __nv_bfloat162 lp=__halves2bfloat162(la,lb);
                    hw[pq]=*(uint32_t*)&hp;
                    lw[pq]=*(uint32_t*)&lp;
                }
                uint32_t off = (uint32_t)bk*256u + (uint32_t)bn*2u + (uint32_t)q*16u;
                uint32_t sw = off ^ ((off>>4)&0xF0u);
                *(uint4*)(sm + oBhi + sw) = make_uint4(hw[0],hw[1],hw[2],hw[3]);
                *(uint4*)(sm + oBlo + sw) = make_uint4(lw[0],lw[1],lw[2],lw[3]);
            }
        }
        __syncthreads();
#pragma unroll
        for(int kk=0;kk<4;kk++){
            uint32_t afh[4][4], afl[4][4];
#pragma unroll
            for(int mi=0;mi<4;mi++){
                uint32_t off = (uint32_t)(wm+mi*16+(lane&15))*128u + (uint32_t)kk*32u + (uint32_t)(lane>>4)*16u;
                uint32_t sw = off ^ ((off>>3)&0x70u);
                ldsm4(afh[mi], sbase + oAhi + sw);
                ldsm4(afl[mi], sbase + oAlo + sw);
            }
            uint32_t bfh[2][4], bfl[2][4];
#pragma unroll
            for(int nj=0;nj<2;nj++){
                uint32_t off = (uint32_t)(kk*16+(lane&15))*256u + (uint32_t)(wn+nj*16+(lane>>4)*8)*2u;
                uint32_t sw = off ^ ((off>>4)&0xF0u);
                ldsm4t(bfh[nj], sbase + oBhi + sw);
                ldsm4t(bfl[nj], sbase + oBlo + sw);
            }
#pragma unroll
            for(int mi=0;mi<4;mi++){
#pragma unroll
                for(int n8=0;n8<4;n8++){
                    const uint32_t* bh = &bfh[n8>>1][(n8&1)*2];
                    const uint32_t* bl = &bfl[n8>>1][(n8&1)*2];
                    mma16816(acc[mi][n8], afh[mi], bh);
                    mma16816(acc[mi][n8], afh[mi], bl);
                    mma16816(acc[mi][n8], afl[mi], bh);
                }
            }
        }
        __syncthreads();
    }

    int rbase = m0 + wm + (lane>>2);
    int cbase = n0 + wn + (lane&3)*2;
    int bcol = (n0 + wn) >> 5;
#pragma unroll
    for(int mi=0;mi<4;mi++){
        int r1 = rbase + mi*16;
        int r2 = r1 + 8;
        float bv1=0.f, bv2=0.f;
        if(bias){
            if(r1<Msz) bv1 = bias[((long)bz*Msz+r1)*(Nsz>>5) + bcol];
            if(r2<Msz) bv2 = bias[((long)bz*Msz+r2)*(Nsz>>5) + bcol];
        }
#pragma unroll
        for(int n8=0;n8<4;n8++){
            int col = cbase + n8*8;
            if(r1<Msz){
                float2 v = make_float2(acc[mi][n8][0]+bv1, acc[mi][n8][1]+bv1);
                *(float2*)&Cout[((long)bz*Msz+r1)*(long)Nsz+col] = v;
            }
            if(r2<Msz){
                float2 v = make_float2(acc[mi][n8][2]+bv2, acc[mi][n8][3]+bv2);
                *(float2*)&Cout[((long)bz*Msz+r2)*(long)Nsz+col] = v;
            }
        }
    }
}

// ===================== reductions =====================
__device__ __forceinline__ void blockReduce2(float& a, float& bsum){
    __shared__ float sa[32], sb[32];
    unsigned mm=0xffffffffu;
    for(int o=16;o;o>>=1){ a+=__shfl_down_sync(mm,a,o); bsum+=__shfl_down_sync(mm,bsum,o); }
    int w=threadIdx.x>>5, l=threadIdx.x&31;
    if(l==0){ sa[w]=a; sb[w]=bsum; }
    __syncthreads();
    int nw=(blockDim.x+31)>>5;
    if(threadIdx.x<32){
        a    = (threadIdx.x<nw)?sa[threadIdx.x]:0.f;
        bsum = (threadIdx.x<nw)?sb[threadIdx.x]:0.f;
        for(int o=16;o;o>>=1){ a+=__shfl_down_sync(mm,a,o); bsum+=__shfl_down_sync(mm,bsum,o); }
    }
}

__global__ void stats2_kernel(const float* __restrict__ X, float* __restrict__ mean,
                              float* __restrict__ rstd, float* __restrict__ maxRaw,
                              float* __restrict__ S, int M)
{
    __shared__ float bc[2];
    int bo = blockIdx.x;
    const float* xb = X + (long)bo*M*32;
    float s=0.f, s2=0.f;
    for(int i=threadIdx.x;i<M;i+=blockDim.x){
        const float4* row = (const float4*)(xb + (long)i*32);
        float mx=-1e30f;
#pragma unroll
        for(int q=0;q<8;q++){
            float4 v = row[q];
            s  += v.x+v.y+v.z+v.w;
            s2 += v.x*v.x+v.y*v.y+v.z*v.z+v.w*v.w;
            mx = fmaxf(mx, fmaxf(fmaxf(v.x,v.y), fmaxf(v.z,v.w)));
        }
        maxRaw[(long)bo*M+i]=mx;
    }
    blockReduce2(s,s2);
    if(threadIdx.x==0){
        float Cnt = (float)(M*32);
        float mn = s/Cnt;
        float var = s2/Cnt - mn*mn;
        float rs = rsqrtf(var+1e-5f);
        mean[bo]=mn; rstd[bo]=rs;
        bc[0]=mn; bc[1]=rs;
    }
    __syncthreads();
    float mn = bc[0], rs = bc[1];
    const float4* xv = (const float4*)xb;
    float sr=0.f;
    for(int i=threadIdx.x;i<M*8;i+=blockDim.x){
        float4 v = xv[i];
        sr += fmaxf((v.x-mn)*rs,0.f)+fmaxf((v.y-mn)*rs,0.f)
            + fmaxf((v.z-mn)*rs,0.f)+fmaxf((v.w-mn)*rs,0.f);
    }
    float d=0.f;
    blockReduce2(sr,d);
    if(threadIdx.x==0) S[bo]=sr;
}

__global__ void attn_kernel(const float* __restrict__ S, const float* __restrict__ w1,
                            const float* __restrict__ w2, float* __restrict__ g,
                            int O, int H, int Cnt)
{
    int b = blockIdx.x, t = threadIdx.x;
    __shared__ float ss[384], hh[96];
    if(t<O) ss[t] = S[(long)b*O+t] / (float)Cnt;
    __syncthreads();
    if(t<H){
        float a=0.f;
        for(int o=0;o<O;o++) a += w1[(long)t*O+o]*ss[o];
        hh[t]=fmaxf(a,0.f);
    }
    __syncthreads();
    if(t<O){
        float a=0.f;
        for(int j=0;j<H;j++) a += w2[(long)t*H+j]*hh[j];
        g[(long)b*O+t] = 1.f/(1.f+expf(-a));
    }
}

__global__ void wprep_kernel(const float* __restrict__ w2, const float* __restrict__ g,
                             float* __restrict__ WL, __nv_bfloat16* __restrict__ WRhi,
                             __nv_bfloat16* __restrict__ WRlo, int O, int Mpad)
{
    int b = blockIdx.y;
    int e = blockIdx.x*blockDim.x + threadIdx.x;
    if(e>=Mpad*O) return;
    int o=e/O, c=e%O;
    float vr = 0.f;
    if(o<O){
        float gg = g[(long)b*O+c];
        WL[(long)b*O*O + (long)o*O + c] = __fmul_rn(w2[(long)o*2*O + c], gg);
        vr = __fmul_rn(w2[(long)o*2*O + O + c], gg);
    }
    __nv_bfloat16 h,l; bf16split(vr,h,l);
    WRhi[(long)b*Mpad*O+e] = h;
    WRlo[(long)b*Mpad*O+e] = l;
}

__global__ void wsplit_kernel(const float* __restrict__ w, __nv_bfloat16* __restrict__ hi,
                              __nv_bfloat16* __restrict__ lo, int O, int K, int Mpad, int Kpad)
{
    int e = blockIdx.x*blockDim.x + threadIdx.x;
    if(e>=Mpad*Kpad) return;
    int r=e/Kpad, c=e%Kpad;
    float v = (r<O && c<K) ? w[(long)r*K+c] : 0.f;
    __nv_bfloat16 h,l; bf16split(v,h,l);
    hi[e]=h; lo[e]=l;
}

__global__ void final_kernel(const float* __restrict__ maxRaw2, const float* __restrict__ mean,
                             const float* __restrict__ rstd, const float* __restrict__ g,
                             float* __restrict__ out, long total, int Mctr)
{
    long e = (long)blockIdx.x*blockDim.x + threadIdx.x;
    if(e>=total) return;
    long bo = e/Mctr;
    float y = fmaxf((maxRaw2[e]-mean[bo])*rstd[bo], 0.f);
    out[e] = __fmul_rn(g[bo], y);
}

// ===================== host-side drivers =====================
static const int HM_SMEM = 65536;

extern "C" void kernel_launch(void* const* d_in, const int* in_sizes, int n_in,
                              void* d_out, int out_size)
{
    const float* p      = (const float*)d_in[0];
    const float* f      = (const float*)d_in[1];
    const float* s0_w1  = (const float*)d_in[2];
    const float* s0_a1w1= (const float*)d_in[3];
    const float* s0_a1w2= (const float*)d_in[4];
    const float* s0_w2  = (const float*)d_in[5];
    const float* s0_a2w1= (const float*)d_in[6];
    const float* s0_a2w2= (const float*)d_in[7];
    const float* s1_w1  = (const float*)d_in[8];
    const float* s1_a1w1= (const float*)d_in[9];
    const float* s1_a1w2= (const float*)d_in[10];
    const float* s1_w2  = (const float*)d_in[11];
    const float* s1_a2w1= (const float*)d_in[12];
    const float* s1_a2w2= (const float*)d_in[13];

    float* out   = (float*)d_out;
    float* o_p   = out;
    float* o_cp1 = out + 98304;
    float* o_cp2 = out + 122880;
    float* o_f   = out + 129024;
    float* o_f1  = out + 227328;
    float* o_f2  = out + 1800192;

    static cudaStream_t s2 = nullptr, s3 = nullptr;
    static cudaEvent_t evRoot=nullptr, evA=nullptr, evG0=nullptr, evG1=nullptr, evS3=nullptr, evJoin=nullptr, evHead=nullptr;
    if(!s2){
        cudaStreamCreate(&s2);
        cudaStreamCreate(&s3);
        cudaEventCreateWithFlags(&evRoot,cudaEventDisableTiming);
        cudaEventCreateWithFlags(&evA,   cudaEventDisableTiming);
        cudaEventCreateWithFlags(&evG0,  cudaEventDisableTiming);
        cudaEventCreateWithFlags(&evG1,  cudaEventDisableTiming);
        cudaEventCreateWithFlags(&evS3,  cudaEventDisableTiming);
        cudaEventCreateWithFlags(&evJoin,cudaEventDisableTiming);
        cudaEventCreateWithFlags(&evHead,cudaEventDisableTiming);
        cudaFuncSetAttribute(fps_part<8192,2048,1,1024>,    cudaFuncAttributeMaxDynamicSharedMemorySize, 8192*16);
        cudaFuncSetAttribute(fps_part<8192,2048,1024,2048>, cudaFuncAttributeMaxDynamicSharedMemorySize, 8192*16);
        cudaFuncSetAttribute(ballq3_kernel<8192,16>, cudaFuncAttributeMaxDynamicSharedMemorySize, 8192*16);
        cudaFuncSetAttribute(hmma_kernel, cudaFuncAttributeMaxDynamicSharedMemorySize, HM_SMEM);
    }

    void *vfeat,*vX,*vX2,*vcf,*vmr,*vmr2,*vp2,*vidx,*vidx1,*vgidx,*vgidx2,*vdd,
         *vmean,*vrstd,*vS,*vg,*vwl,*vwrh,*vwrl,*vw1h,*vw1l;
    cudaGetSymbolAddress(&vfeat, g_feat);
    cudaGetSymbolAddress(&vX,    g_X);
    cudaGetSymbolAddress(&vX2,   g_X2);
    cudaGetSymbolAddress(&vcf,   g_cf);
    cudaGetSymbolAddress(&vmr,   g_maxR);
    cudaGetSymbolAddress(&vmr2,  g_maxR2);
    cudaGetSymbolAddress(&vp2,   g_P2);
    cudaGetSymbolAddress(&vidx,  g_idx);
    cudaGetSymbolAddress(&vidx1, g_idx1);
    cudaGetSymbolAddress(&vgidx, g_gidx);
    cudaGetSymbolAddress(&vgidx2,g_gidx2);
    cudaGetSymbolAddress(&vdd,   g_dd);
    cudaGetSymbolAddress(&vmean, g_mean);
    cudaGetSymbolAddress(&vrstd, g_rstd);
    cudaGetSymbolAddress(&vS,    g_S);
    cudaGetSymbolAddress(&vg,    g_g);
    cudaGetSymbolAddress(&vwl,   g_WL);
    cudaGetSymbolAddress(&vwrh,  g_WRhi);
    cudaGetSymbolAddress(&vwrl,  g_WRlo);
    cudaGetSymbolAddress(&vw1h,  g_W1hi);
    cudaGetSymbolAddress(&vw1l,  g_W1lo);

    float* Xp=(float*)vX; float* X2p=(float*)vX2;
    float* mean=(float*)vmean; float* rstd=(float*)vrstd;
    float* Sp=(float*)vS; float* gA=(float*)vg;

    // ---- root fork: REQUIRED so s2/s3 work is part of the capture graph ----
    cudaEventRecord(evRoot, 0);
    cudaStreamWaitEvent(s2, evRoot, 0);

    // ---- head on s2 (overlaps fps chunk A) ----
    wsplit_kernel<<<(384*256+255)/256,256,0,s2>>>(s1_w1,(__nv_bfloat16*)vw1h,(__nv_bfloat16*)vw1l,
        384, 195, 384, 256);
    cudaMemcpyAsync(o_p,         p,         49152*sizeof(float), cudaMemcpyDeviceToDevice, s2);
    cudaMemcpyAsync(o_p + 49152, p + 49152, 49152*sizeof(float), cudaMemcpyDeviceToDevice, s2);
    cudaMemcpyAsync(o_f,         f,         49152*sizeof(float), cudaMemcpyDeviceToDevice, s2);
    cudaMemcpyAsync(o_f + 49152, f + 49152, 49152*sizeof(float), cudaMemcpyDeviceToDevice, s2);
    cudaEventRecord(evHead, s2);

    // ---------- stage 0: N=8192 -> M=2048, C=3, O=192 (Mpad 256), H=48 ----------
    int N0=8192, M0=2048, C0=3, O0=192, H0=48, Mp0=256, NN0=M0*32;
    fps_part<8192,2048,1,1024><<<B,1024,8192*16>>>(p, (int*)vidx, (float*)vdd);
    cudaEventRecord(evA, 0);
    fps_part<8192,2048,1024,2048><<<B,1024,8192*16>>>(p, (int*)vidx, (float*)vdd);

    // ---- s3: first-half pipeline overlapping fps chunk B ----
    cudaStreamWaitEvent(s3, evA, 0);
    gather_kernel<<<dim3(1024/256,B),256,0,s3>>>(p,f,(int*)vidx,o_cp1,(float*)vcf,N0,M0,C0,0);
    cudaEventRecord(evG0, s3);
    ballq3_kernel<8192,16><<<dim3(1024/16,B),256,8192*16,s3>>>(p,o_cp1,(int*)vgidx,M0,0);
    featbuild_kernel<<<dim3(1024*32/256,B),256,0,s3>>>(p,f,o_cp1,(float*)vcf,(int*)vgidx,(float*)vfeat,N0,M0,C0,0);
    sgemm2_kernel<96,6><<<dim3(1024*32/128,O0/96,B),256,0,s3>>>(s0_w1,0,(float*)vfeat,Xp,
        nullptr,nullptr,nullptr,O0,C0+3,NN0,0);
    cudaEventRecord(evS3, s3);

    // ---- s0: second half ----
    gather_kernel<<<dim3(1024/256,B),256>>>(p,f,(int*)vidx,o_cp1,(float*)vcf,N0,M0,C0,1024);
    cudaEventRecord(evG1, 0);
    ballq3_kernel<8192,16><<<dim3(1024/16,B),256,8192*16>>>(p,o_cp1,(int*)vgidx,M0,1024);
    featbuild_kernel<<<dim3(1024*32/256,B),256>>>(p,f,o_cp1,(float*)vcf,(int*)vgidx,(float*)vfeat,N0,M0,C0,1024);
    sgemm2_kernel<96,6><<<dim3(1024*32/128,O0/96,B),256>>>(s0_w1,0,(float*)vfeat,Xp,
        nullptr,nullptr,nullptr,O0,C0+3,NN0,32768);

    // ---- s2: stage-1 geometry fork (needs full o_cp1) ----
    cudaStreamWaitEvent(s2, evG0, 0);
    cudaStreamWaitEvent(s2, evG1, 0);
    fps_part<2048,512,1,512><<<B,1024,2048*16,s2>>>(o_cp1, (int*)vidx1, (float*)vdd);
    gatherpos_kernel<<<dim3(512/256,B),256,0,s2>>>(o_cp1,(int*)vidx1,o_cp2,2048,512);
    ballq3_kernel<2048,16><<<dim3(512/16,B),256,2048*16,s2>>>(o_cp1,o_cp2,(int*)vgidx2,512,0);
    cudaEventRecord(evJoin, s2);

    // ---- s0: stage-0 GEMM chain (wait for s3 half) ----
    cudaStreamWaitEvent(0, evS3, 0);
    stats2_kernel<<<B*O0,256>>>(Xp, mean, rstd, (float*)vmr, Sp, M0);
    attn_kernel<<<B,384>>>(Sp, s0_a1w1, s0_a1w2, gA, O0, H0, NN0);
    wprep_kernel<<<dim3((Mp0*O0+255)/256,B),256>>>(s0_w2, gA, (float*)vwl,
        (__nv_bfloat16*)vwrh,(__nv_bfloat16*)vwrl, O0, Mp0);
    sgemm2_kernel<96,6><<<dim3(M0/128,O0/96,B),256>>>((float*)vwl,(long)O0*O0,(float*)vmr,(float*)vp2,
        nullptr,mean,rstd,O0,O0,M0,0);
    hmma_kernel<<<dim3(NN0/128,Mp0/128,B),256,HM_SMEM>>>(
        (__nv_bfloat16*)vwrh,(__nv_bfloat16*)vwrl,(long)Mp0*O0,O0,
        Xp,mean,rstd,(float*)vp2,X2p,O0,O0,NN0);
    stats2_kernel<<<B*O0,256>>>(X2p, mean, rstd, (float*)vmr2, Sp, M0);
    attn_kernel<<<B,384>>>(Sp, s0_a2w1, s0_a2w2, gA, O0, H0, NN0);
    final_kernel<<<(int)(((long)B*O0*M0+255)/256),256>>>((float*)vmr2, mean, rstd, gA, o_f1, (long)B*O0*M0, M0);

    // ---------- stage 1: N=2048 -> M=512, C=192, O=384 (Mpad 384), H=96 ----------
    {
        int N=2048, M=512, C=192, O=384, H=96, Mpad=384, NN=M*32;
        cudaStreamWaitEvent(0, evJoin, 0);
        cudaStreamWaitEvent(0, evHead, 0);   // wsplit (W1hi/lo) + memcpys joined
        gatherfeat_kernel<<<dim3(M/256,B),256>>>(o_f1,(int*)vidx1,(float*)vcf,N,M,C);
        featbuild_kernel<<<dim3(M*32/256,B),256>>>(o_cp1,o_f1,o_cp2,(float*)vcf,(int*)vgidx2,(float*)vfeat,N,M,C,0);
        hmma_kernel<<<dim3(NN/128,Mpad/128,B),256,HM_SMEM>>>(
            (__nv_bfloat16*)vw1h,(__nv_bfloat16*)vw1l,0,256,
            (float*)vfeat,nullptr,nullptr,nullptr,Xp,O,C+3,NN);
        stats2_kernel<<<B*O,256>>>(Xp, mean, rstd, (float*)vmr, Sp, M);
        attn_kernel<<<B,384>>>(Sp, s1_a1w1, s1_a1w2, gA, O, H, NN);
        wprep_kernel<<<dim3((Mpad*O+255)/256,B),256>>>(s1_w2, gA, (float*)vwl,
            (__nv_bfloat16*)vwrh,(__nv_bfloat16*)vwrl, O, Mpad);
        sgemm2_kernel<128,8><<<dim3(M/128,O/128,B),256>>>((float*)vwl,(long)O*O,(float*)vmr,(float*)vp2,
            nullptr,mean,rstd,O,O,M,0);
        hmma_kernel<<<dim3(NN/128,Mpad/128,B),256,HM_SMEM>>>(
            (__nv_bfloat16*)vwrh,(__nv_bfloat16*)vwrl,(long)Mpad*O,O,
            Xp,mean,rstd,(float*)vp2,X2p,O,O,NN);
        stats2_kernel<<<B*O,256>>>(X2p, mean, rstd, (float*)vmr2, Sp, M);
        attn_kernel<<<B,384>>>(Sp, s1_a2w1, s1_a2w2, gA, O, H, NN);
        final_kernel<<<(int)(((long)B*O*M+255)/256),256>>>((float*)vmr2, mean, rstd, gA, o_f2, (long)B*O*M, M);
    }
}

// round 16
// speedup vs baseline: 1.6433x; 1.0034x over previous
#include <cuda_runtime.h>
#include <cuda_bf16.h>
#include <stdint.h>
#include <math.h>

// ===================== constants =====================
static const int B = 4;

// ===================== device scratch =====================
__device__ float g_feat[4L*195*512*32];
__device__ float g_X  [4L*192*2048*32];
__device__ float g_X2 [4L*192*2048*32];
__device__ float g_cf [4L*192*512];
__device__ float g_maxR [4L*192*2048];
__device__ float g_maxR2[4L*192*2048];
__device__ float g_P2  [4L*192*2048];
__device__ int   g_idx [4*2048];
__device__ int   g_idx1[4*512];
__device__ int   g_gidx [4*2048*32];
__device__ int   g_gidx2[4*512*32];
__device__ float g_dd  [4L*8192];
__device__ float g_mean[4*384], g_rstd[4*384], g_S[4*384], g_g[4*384];
__device__ float g_WL[4L*384*384];
__device__ __nv_bfloat16 g_WRhi[4L*384*384], g_WRlo[4L*384*384];
__device__ __nv_bfloat16 g_W1hi[384L*256],   g_W1lo[384L*256];

// ===================== small helpers =====================
__device__ __forceinline__ float dist2f(float ax,float ay,float az,float bx,float by,float bz){
    float dx=__fsub_rn(ax,bx), dy=__fsub_rn(ay,by), dz=__fsub_rn(az,bz);
    return __fadd_rn(__fadd_rn(__fmul_rn(dx,dx),__fmul_rn(dy,dy)),__fmul_rn(dz,dz));
}
__device__ __forceinline__ uint32_t smem_u32(const void* p){
    uint32_t a; asm("{ .reg .u64 t; cvta.to.shared.u64 t, %1; cvt.u32.u64 %0, t; }":"=r"(a):"l"(p));
    return a;
}
__device__ __forceinline__ uint32_t redux_max(uint32_t v){
    uint32_t r; asm("redux.sync.max.u32 %0, %1, 0xffffffff;" : "=r"(r) : "r"(v)); return r;
}
__device__ __forceinline__ void ldsm4(uint32_t* r, uint32_t addr){
    asm volatile("ldmatrix.sync.aligned.m8n8.x4.shared.b16 {%0,%1,%2,%3}, [%4];"
        :"=r"(r[0]),"=r"(r[1]),"=r"(r[2]),"=r"(r[3]):"r"(addr));
}
__device__ __forceinline__ void ldsm4t(uint32_t* r, uint32_t addr){
    asm volatile("ldmatrix.sync.aligned.m8n8.x4.trans.shared.b16 {%0,%1,%2,%3}, [%4];"
        :"=r"(r[0]),"=r"(r[1]),"=r"(r[2]),"=r"(r[3]):"r"(addr));
}
__device__ __forceinline__ void mma16816(float* d, const uint32_t* a, const uint32_t* b){
    asm volatile("mma.sync.aligned.m16n8k16.row.col.f32.bf16.bf16.f32 "
        "{%0,%1,%2,%3}, {%4,%5,%6,%7}, {%8,%9}, {%0,%1,%2,%3};"
        : "+f"(d[0]),"+f"(d[1]),"+f"(d[2]),"+f"(d[3])
        : "r"(a[0]),"r"(a[1]),"r"(a[2]),"r"(a[3]),"r"(b[0]),"r"(b[1]));
}
__device__ __forceinline__ void bf16split(float v, __nv_bfloat16& h, __nv_bfloat16& l){
    h = __float2bfloat16_rn(v);
    l = __float2bfloat16_rn(v - __bfloat162float(h));
}

// ===================== FPS (chunked, redux reduction) =====================
template<int N, int M, int S0, int S1>
__global__ __launch_bounds__(1024) void fps_part(const float* __restrict__ p, int* __restrict__ outIdx,
                                                 float* __restrict__ ddG)
{
    constexpr int NPT = N/1024;
    extern __shared__ float4 spt[];
    const int b = blockIdx.x, t = threadIdx.x;
    const float* pb = p + (long)b*N*3;
    float px[NPT],py[NPT],pz[NPT],dd[NPT];
#pragma unroll
    for(int j=0;j<NPT;j++){
        int gi = t*NPT+j;
        px[j]=pb[3*gi]; py[j]=pb[3*gi+1]; pz[j]=pb[3*gi+2];
        dd[j] = (S0==1) ? 1e10f : ddG[(long)b*N + gi];
        spt[gi] = make_float4(px[j],py[j],pz[j],0.f);
    }
    __shared__ uint32_t swv[32];
    __shared__ int      swi[32];
    __shared__ int      sBi;
    float lx,ly,lz;
    __syncthreads();
    if(S0==1){
        if(t==0) outIdx[(long)b*M]=0;
        lx=pb[0]; ly=pb[1]; lz=pb[2];
    } else {
        int li = outIdx[(long)b*M + S0-1];
        float4 wp = spt[li];
        lx=wp.x; ly=wp.y; lz=wp.z;
    }
    int lane = t&31, w = t>>5;
    for(int s=S0;s<S1;s++){
        float bv=-1e30f; int bi=0;
#pragma unroll
        for(int j=0;j<NPT;j++){
            float d = dist2f(px[j],py[j],pz[j],lx,ly,lz);
            float dm = fminf(dd[j], d);
            dd[j]=dm;
            if(dm>bv){ bv=dm; bi=t*NPT+j; }
        }
        uint32_t bits = __float_as_uint(bv);
        uint32_t mx = redux_max(bits);
        unsigned msk = __ballot_sync(0xffffffffu, bits==mx);
        int src = __ffs(msk)-1;
        bi = __shfl_sync(0xffffffffu, bi, src);
        if(lane==0){ swv[w]=mx; swi[w]=bi; }
        __syncthreads();
        if(t<32){
            uint32_t b2=swv[t]; int i2=swi[t];
            uint32_t m2 = redux_max(b2);
            unsigned k2 = __ballot_sync(0xffffffffu, b2==m2);
            int s2i = __ffs(k2)-1;
            i2 = __shfl_sync(0xffffffffu, i2, s2i);
            if(t==0){ sBi=i2; outIdx[(long)b*M+s]=i2; }
        }
        __syncthreads();
        float4 wp = spt[sBi];
        lx=wp.x; ly=wp.y; lz=wp.z;
    }
    if(S1<M){
#pragma unroll
        for(int j=0;j<NPT;j++) ddG[(long)b*N + t*NPT+j] = dd[j];
    }
}

// ===================== gather (ranged) =====================
__global__ void gather_kernel(const float* __restrict__ p, const float* __restrict__ f,
                              const int* __restrict__ idx, float* __restrict__ cp,
                              float* __restrict__ cf, int N, int M, int C, int i0)
{
    int b = blockIdx.y;
    int i = i0 + blockIdx.x*blockDim.x + threadIdx.x;
    if(i>=M) return;
    int j = idx[(long)b*M+i];
    cp[((long)b*M+i)*3+0] = p[((long)b*N+j)*3+0];
    cp[((long)b*M+i)*3+1] = p[((long)b*N+j)*3+1];
    cp[((long)b*M+i)*3+2] = p[((long)b*N+j)*3+2];
    for(int c=0;c<C;c++)
        cf[((long)b*C+c)*M+i] = f[((long)b*C+c)*N+j];
}
__global__ void gatherpos_kernel(const float* __restrict__ p, const int* __restrict__ idx,
                                 float* __restrict__ cp, int N, int M)
{
    int b = blockIdx.y;
    int i = blockIdx.x*blockDim.x + threadIdx.x;
    if(i>=M) return;
    int j = idx[(long)b*M+i];
    cp[((long)b*M+i)*3+0] = p[((long)b*N+j)*3+0];
    cp[((long)b*M+i)*3+1] = p[((long)b*N+j)*3+1];
    cp[((long)b*M+i)*3+2] = p[((long)b*N+j)*3+2];
}
__global__ void gatherfeat_kernel(const float* __restrict__ f, const int* __restrict__ idx,
                                  float* __restrict__ cf, int N, int M, int C)
{
    int b = blockIdx.y;
    int i = blockIdx.x*blockDim.x + threadIdx.x;
    if(i>=M) return;
    int j = idx[(long)b*M+i];
    for(int c=0;c<C;c++)
        cf[((long)b*C+c)*M+i] = f[((long)b*C+c)*N+j];
}

// ===================== ball query v3 (ranged) =====================
template<int N, int CPB>
__global__ __launch_bounds__(256) void ballq3_kernel(
    const float* __restrict__ pts, const float* __restrict__ ctr,
    int* __restrict__ gidx, int M, int i0)
{
    extern __shared__ float4 sp[];
    int b = blockIdx.y;
    const float* pb = pts + (long)b*N*3;
    for(int j=threadIdx.x;j<N;j+=blockDim.x)
        sp[j] = make_float4(pb[3*j],pb[3*j+1],pb[3*j+2],0.f);
    __syncthreads();
    int wid = threadIdx.x>>5, lane = threadIdx.x&31;
    constexpr int CPW = CPB/8;
    int base = i0 + blockIdx.x*CPB + wid*CPW;
    const float R2 = (float)(0.1*0.1);
#pragma unroll
    for(int c=0;c<CPW;c++){
        int i = base + c;
        float cx=ctr[((long)b*M+i)*3], cy=ctr[((long)b*M+i)*3+1], cz=ctr[((long)b*M+i)*3+2];
        int* out = gidx + ((long)b*M+i)*32;
        int cnt=0, first=0;
        for(int j0=0;j0<N;j0+=128){
            bool in[4];
            unsigned m[4];
#pragma unroll
            for(int q=0;q<4;q++){
                float4 pt = sp[j0+q*32+lane];
                in[q] = dist2f(cx,cy,cz,pt.x,pt.y,pt.z) < R2;
            }
#pragma unroll
            for(int q=0;q<4;q++) m[q] = __ballot_sync(0xffffffffu, in[q]);
#pragma unroll
            for(int q=0;q<4;q++){
                if(m[q] && cnt<32){
                    if(cnt==0) first = j0+q*32 + __ffs(m[q]) - 1;
                    int pos = cnt + __popc(m[q] & ((1u<<lane)-1u));
                    if(in[q] && pos<32) out[pos] = j0+q*32+lane;
                    cnt += __popc(m[q]);
                }
            }
            if(cnt>=32) break;
        }
        if(cnt<32){
            for(int k=cnt+lane;k<32;k+=32) out[k]=first;
        }
    }
}

// ===================== feature build (ranged) =====================
__global__ void featbuild_kernel(const float* __restrict__ p, const float* __restrict__ f,
                                 const float* __restrict__ cp, const float* __restrict__ cf,
                                 const int* __restrict__ gidx, float* __restrict__ feat,
                                 int N, int M, int C, int i0)
{
    int b = blockIdx.y;
    int gi = blockIdx.x*blockDim.x + threadIdx.x;
    int i = i0 + (gi>>5), kk = gi&31;
    if(i>=M) return;
    int j = gidx[((long)b*M+i)*32+kk];
    long CH = C+3;
    float dx = __fsub_rn(p[((long)b*N+j)*3+0], cp[((long)b*M+i)*3+0]);
    float dy = __fsub_rn(p[((long)b*N+j)*3+1], cp[((long)b*M+i)*3+1]);
    float dz = __fsub_rn(p[((long)b*N+j)*3+2], cp[((long)b*M+i)*3+2]);
    feat[(((long)b*CH+0)*M+i)*32+kk] = dx;
    feat[(((long)b*CH+1)*M+i)*32+kk] = dy;
    feat[(((long)b*CH+2)*M+i)*32+kk] = dz;
    const float* fb  = f  + (long)b*C*N;
    const float* cfb = cf + (long)b*C*M;
    for(int c=0;c<C;c++)
        feat[(((long)b*CH+3+c)*M+i)*32+kk] = __fsub_rn(fb[(long)c*N+j], cfb[(long)c*M+i]);
}

// ===================== FFMA SGEMM (n-offset capable) =====================
template<int BM, int MR>
__global__ __launch_bounds__(256) void sgemm2_kernel(
    const float* __restrict__ A, long aStride,
    const float* __restrict__ X, float* __restrict__ C,
    const float* __restrict__ bias,
    const float* __restrict__ nmean, const float* __restrict__ nrstd,
    int Msz, int Ksz, int Nsz, int nOff)
{
    __shared__ float As[2][16][BM];
    __shared__ float Xs[2][16][128];
    constexpr int AL = BM/16;
    int b = blockIdx.z, m0 = blockIdx.y*BM, n0 = blockIdx.x*128 + nOff;
    const float* Ab = A + (long)b*aStride;
    const float* Xb = X + (long)b*(long)Ksz*Nsz;
    const float* mp = nmean ? nmean + (long)b*Ksz : nullptr;
    const float* rp = nrstd ? nrstd + (long)b*Ksz : nullptr;
    int t = threadIdx.x, tx = t&15, ty = t>>4;
    float acc[MR][8];
#pragma unroll
    for(int r=0;r<MR;r++)
#pragma unroll
        for(int c=0;c<8;c++) acc[r][c]=0.f;
    float  aR[AL];
    float4 xR[2];
    int nk = (Ksz+15)>>4;
    auto LOAD = [&](int k0){
#pragma unroll
        for(int i=0;i<AL;i++){
            int e=t+i*256, m=e%BM, k=e/BM;
            aR[i] = (k0+k<Ksz) ? Ab[(long)(m0+m)*Ksz + k0+k] : 0.f;
        }
#pragma unroll
        for(int j=0;j<2;j++){
            int e=t+j*256, k=e>>5, n4=e&31;
            if(k0+k<Ksz){
                float4 v = *(const float4*)(Xb + (long)(k0+k)*Nsz + n0 + n4*4);
                if(mp){
                    float mn=mp[k0+k], rs=rp[k0+k];
                    v.x=fmaxf((v.x-mn)*rs,0.f); v.y=fmaxf((v.y-mn)*rs,0.f);
                    v.z=fmaxf((v.z-mn)*rs,0.f); v.w=fmaxf((v.w-mn)*rs,0.f);
                }
                xR[j]=v;
            } else xR[j]=make_float4(0.f,0.f,0.f,0.f);
        }
    };
    auto STORE = [&](int buf){
#pragma unroll
        for(int i=0;i<AL;i++){ int e=t+i*256; As[buf][e/BM][e%BM]=aR[i]; }
#pragma unroll
        for(int j=0;j<2;j++){ int e=t+j*256; *(float4*)&Xs[buf][e>>5][(e&31)*4] = xR[j]; }
    };
    auto COMP = [&](int buf){
#pragma unroll
        for(int kk=0;kk<16;kk++){
            float a[MR];
#pragma unroll
            for(int r=0;r<MR;r++) a[r]=As[buf][kk][ty*MR+r];
            float4 b0 = *(float4*)&Xs[buf][kk][tx*8];
            float4 b1 = *(float4*)&Xs[buf][kk][tx*8+4];
            float bb[8] = {b0.x,b0.y,b0.z,b0.w,b1.x,b1.y,b1.z,b1.w};
#pragma unroll
            for(int r=0;r<MR;r++)
#pragma unroll
                for(int c=0;c<8;c++) acc[r][c] += a[r]*bb[c];
        }
    };
    LOAD(0); STORE(0); __syncthreads();
    for(int kt=0;kt<nk;kt++){
        int cur=kt&1;
        if(kt+1<nk) LOAD((kt+1)*16);
        COMP(cur);
        if(kt+1<nk){ STORE(cur^1); __syncthreads(); }
    }
#pragma unroll
    for(int r=0;r<MR;r++){
        int row=m0+ty*MR+r, col=n0+tx*8;
        float o[8];
#pragma unroll
        for(int c=0;c<8;c++) o[c]=acc[r][c];
        if(bias){
            const float* bb = bias + ((long)b*Msz+row)*(Nsz>>5);
#pragma unroll
            for(int c=0;c<8;c++) o[c] += bb[(col+c)>>5];
        }
        *(float4*)&C[((long)b*Msz+row)*(long)Nsz+col]   = make_float4(o[0],o[1],o[2],o[3]);
        *(float4*)&C[((long)b*Msz+row)*(long)Nsz+col+4] = make_float4(o[4],o[5],o[6],o[7]);
    }
}

// ===================== mma.sync bf16 GEMM =====================
__global__ __launch_bounds__(256) void hmma_kernel(
    const __nv_bfloat16* __restrict__ Ahi, const __nv_bfloat16* __restrict__ Alo,
    long aStride, int Kpad,
    const float* __restrict__ X, const float* __restrict__ nmean, const float* __restrict__ nrstd,
    const float* __restrict__ bias, float* __restrict__ Cout,
    int Msz, int Ksz, int Nsz)
{
    extern __shared__ char sm[];
    const uint32_t oAhi=0, oAlo=16384, oBhi=32768, oBlo=49152;
    uint32_t sbase = smem_u32(sm);

    int t = threadIdx.x, lane = t&31, w = t>>5;
    int wm = (w&1)*64, wn = (w>>1)*32;
    int bz = blockIdx.z, m0 = blockIdx.y*128, n0 = blockIdx.x*128;
    const __nv_bfloat16* Ah = Ahi + (long)bz*aStride;
    const __nv_bfloat16* Al = Alo + (long)bz*aStride;
    const float* Xb = X + (long)bz*(long)Ksz*Nsz;

    float acc[4][4][4];
#pragma unroll
    for(int i=0;i<4;i++)
#pragma unroll
        for(int j=0;j<4;j++)
#pragma unroll
            for(int q=0;q<4;q++) acc[i][j][q]=0.f;

    int ar = t>>1, ah = t&1;
    int bk = t>>2, bn = (t&3)*32;

    int nch = Kpad/64;
    for(int c=0;c<nch;c++){
        int k0 = c*64;
        {
            const uint4* gh = (const uint4*)(Ah + (long)(m0+ar)*Kpad + k0 + ah*32);
            const uint4* gl = (const uint4*)(Al + (long)(m0+ar)*Kpad + k0 + ah*32);
#pragma unroll
            for(int q=0;q<4;q++){
                uint32_t off = (uint32_t)ar*128u + (uint32_t)ah*64u + (uint32_t)q*16u;
                uint32_t sw = off ^ ((off>>3)&0x70u);
                *(uint4*)(sm + oAhi + sw) = gh[q];
                *(uint4*)(sm + oAlo + sw) = gl[q];
            }
        }
        {
            int kg = k0 + bk;
            bool valid = (kg < Ksz);
            float mn=0.f, rs=1.f;
            bool doact = (nmean != nullptr);
            if(doact && valid){ mn = nmean[(long)bz*Ksz+kg]; rs = nrstd[(long)bz*Ksz+kg]; }
            const float4* xr = (const float4*)(Xb + (long)kg*Nsz + n0 + bn);
#pragma unroll
            for(int q=0;q<4;q++){
                float xv[8];
                if(valid){
                    float4 v0 = xr[q*2], v1 = xr[q*2+1];
                    xv[0]=v0.x; xv[1]=v0.y; xv[2]=v0.z; xv[3]=v0.w;
                    xv[4]=v1.x; xv[5]=v1.y; xv[6]=v1.z; xv[7]=v1.w;
                    if(doact){
#pragma unroll
                        for(int j=0;j<8;j++) xv[j]=fmaxf((xv[j]-mn)*rs,0.f);
                    }
                } else {
#pragma unroll
                    for(int j=0;j<8;j++) xv[j]=0.f;
                }
                uint32_t hw[4], lw[4];
#pragma unroll
                for(int pq=0;pq<4;pq++){
                    float a=xv[pq*2], b2=xv[pq*2+1];
                    __nv_bfloat16 ha,la,hb,lb;
                    bf16split(a,ha,la); bf16split(b2,hb,lb);
                    __nv_bfloat162 hp=__halves2bfloat162(ha,hb);
                    __nv_bfloat162 lp=__halves2bfloat162(la,lb);
                    hw[pq]=*(uint32_t*)&hp;
                    lw[pq]=*(uint32_t*)&lp;
                }
                uint32_t off = (uint32_t)bk*256u + (uint32_t)bn*2u + (uint32_t)q*16u;
                uint32_t sw = off ^ ((off>>4)&0xF0u);
                *(uint4*)(sm + oBhi + sw) = make_uint4(hw[0],hw[1],hw[2],hw[3]);
                *(uint4*)(sm + oBlo + sw) = make_uint4(lw[0],lw[1],lw[2],lw[3]);
            }
        }
        __syncthreads();
#pragma unroll
        for(int kk=0;kk<4;kk++){
            uint32_t afh[4][4], afl[4][4];
#pragma unroll
            for(int mi=0;mi<4;mi++){
                uint32_t off = (uint32_t)(wm+mi*16+(lane&15))*128u + (uint32_t)kk*32u + (uint32_t)(lane>>4)*16u;
                uint32_t sw = off ^ ((off>>3)&0x70u);
                ldsm4(afh[mi], sbase + oAhi + sw);
                ldsm4(afl[mi], sbase + oAlo + sw);
            }
            uint32_t bfh[2][4], bfl[2][4];
#pragma unroll
            for(int nj=0;nj<2;nj++){
                uint32_t off = (uint32_t)(kk*16+(lane&15))*256u + (uint32_t)(wn+nj*16+(lane>>4)*8)*2u;
                uint32_t sw = off ^ ((off>>4)&0xF0u);
                ldsm4t(bfh[nj], sbase + oBhi + sw);
                ldsm4t(bfl[nj], sbase + oBlo + sw);
            }
#pragma unroll
            for(int mi=0;mi<4;mi++){
#pragma unroll
                for(int n8=0;n8<4;n8++){
                    const uint32_t* bh = &bfh[n8>>1][(n8&1)*2];
                    const uint32_t* bl = &bfl[n8>>1][(n8&1)*2];
                    mma16816(acc[mi][n8], afh[mi], bh);
                    mma16816(acc[mi][n8], afh[mi], bl);
                    mma16816(acc[mi][n8], afl[mi], bh);
                }
            }
        }
        __syncthreads();
    }

    int rbase = m0 + wm + (lane>>2);
    int cbase = n0 + wn + (lane&3)*2;
    int bcol = (n0 + wn) >> 5;
#pragma unroll
    for(int mi=0;mi<4;mi++){
        int r1 = rbase + mi*16;
        int r2 = r1 + 8;
        float bv1=0.f, bv2=0.f;
        if(bias){
            if(r1<Msz) bv1 = bias[((long)bz*Msz+r1)*(Nsz>>5) + bcol];
            if(r2<Msz) bv2 = bias[((long)bz*Msz+r2)*(Nsz>>5) + bcol];
        }
#pragma unroll
        for(int n8=0;n8<4;n8++){
            int col = cbase + n8*8;
            if(r1<Msz){
                float2 v = make_float2(acc[mi][n8][0]+bv1, acc[mi][n8][1]+bv1);
                *(float2*)&Cout[((long)bz*Msz+r1)*(long)Nsz+col] = v;
            }
            if(r2<Msz){
                float2 v = make_float2(acc[mi][n8][2]+bv2, acc[mi][n8][3]+bv2);
                *(float2*)&Cout[((long)bz*Msz+r2)*(long)Nsz+col] = v;
            }
        }
    }
}

// ===================== reductions =====================
__device__ __forceinline__ void blockReduce2(float& a, float& bsum){
    __shared__ float sa[32], sb[32];
    unsigned mm=0xffffffffu;
    for(int o=16;o;o>>=1){ a+=__shfl_down_sync(mm,a,o); bsum+=__shfl_down_sync(mm,bsum,o); }
    int w=threadIdx.x>>5, l=threadIdx.x&31;
    if(l==0){ sa[w]=a; sb[w]=bsum; }
    __syncthreads();
    int nw=(blockDim.x+31)>>5;
    if(threadIdx.x<32){
        a    = (threadIdx.x<nw)?sa[threadIdx.x]:0.f;
        bsum = (threadIdx.x<nw)?sb[threadIdx.x]:0.f;
        for(int o=16;o;o>>=1){ a+=__shfl_down_sync(mm,a,o); bsum+=__shfl_down_sync(mm,bsum,o); }
    }
}

__global__ void stats2_kernel(const float* __restrict__ X, float* __restrict__ mean,
                              float* __restrict__ rstd, float* __restrict__ maxRaw,
                              float* __restrict__ S, int M)
{
    __shared__ float bc[2];
    int bo = blockIdx.x;
    const float* xb = X + (long)bo*M*32;
    float s=0.f, s2=0.f;
    for(int i=threadIdx.x;i<M;i+=blockDim.x){
        const float4* row = (const float4*)(xb + (long)i*32);
        float mx=-1e30f;
#pragma unroll
        for(int q=0;q<8;q++){
            float4 v = row[q];
            s  += v.x+v.y+v.z+v.w;
            s2 += v.x*v.x+v.y*v.y+v.z*v.z+v.w*v.w;
            mx = fmaxf(mx, fmaxf(fmaxf(v.x,v.y), fmaxf(v.z,v.w)));
        }
        maxRaw[(long)bo*M+i]=mx;
    }
    blockReduce2(s,s2);
    if(threadIdx.x==0){
        float Cnt = (float)(M*32);
        float mn = s/Cnt;
        float var = s2/Cnt - mn*mn;
        float rs = rsqrtf(var+1e-5f);
        mean[bo]=mn; rstd[bo]=rs;
        bc[0]=mn; bc[1]=rs;
    }
    __syncthreads();
    float mn = bc[0], rs = bc[1];
    const float4* xv = (const float4*)xb;
    float sr=0.f;
    for(int i=threadIdx.x;i<M*8;i+=blockDim.x){
        float4 v = xv[i];
        sr += fmaxf((v.x-mn)*rs,0.f)+fmaxf((v.y-mn)*rs,0.f)
            + fmaxf((v.z-mn)*rs,0.f)+fmaxf((v.w-mn)*rs,0.f);
    }
    float d=0.f;
    blockReduce2(sr,d);
    if(threadIdx.x==0) S[bo]=sr;
}

__global__ void attn_kernel(const float* __restrict__ S, const float* __restrict__ w1,
                            const float* __restrict__ w2, float* __restrict__ g,
                            int O, int H, int Cnt)
{
    int b = blockIdx.x, t = threadIdx.x;
    __shared__ float ss[384], hh[96];
    if(t<O) ss[t] = S[(long)b*O+t] / (float)Cnt;
    __syncthreads();
    if(t<H){
        float a=0.f;
        for(int o=0;o<O;o++) a += w1[(long)t*O+o]*ss[o];
        hh[t]=fmaxf(a,0.f);
    }
    __syncthreads();
    if(t<O){
        float a=0.f;
        for(int j=0;j<H;j++) a += w2[(long)t*H+j]*hh[j];
        g[(long)b*O+t] = 1.f/(1.f+expf(-a));
    }
}

__global__ void wprep_kernel(const float* __restrict__ w2, const float* __restrict__ g,
                             float* __restrict__ WL, __nv_bfloat16* __restrict__ WRhi,
                             __nv_bfloat16* __restrict__ WRlo, int O, int Mpad)
{
    int b = blockIdx.y;
    int e = blockIdx.x*blockDim.x + threadIdx.x;
    if(e>=Mpad*O) return;
    int o=e/O, c=e%O;
    float vr = 0.f;
    if(o<O){
        float gg = g[(long)b*O+c];
        WL[(long)b*O*O + (long)o*O + c] = __fmul_rn(w2[(long)o*2*O + c], gg);
        vr = __fmul_rn(w2[(long)o*2*O + O + c], gg);
    }
    __nv_bfloat16 h,l; bf16split(vr,h,l);
    WRhi[(long)b*Mpad*O+e] = h;
    WRlo[(long)b*Mpad*O+e] = l;
}

__global__ void wsplit_kernel(const float* __restrict__ w, __nv_bfloat16* __restrict__ hi,
                              __nv_bfloat16* __restrict__ lo, int O, int K, int Mpad, int Kpad)
{
    int e = blockIdx.x*blockDim.x + threadIdx.x;
    if(e>=Mpad*Kpad) return;
    int r=e/Kpad, c=e%Kpad;
    float v = (r<O && c<K) ? w[(long)r*K+c] : 0.f;
    __nv_bfloat16 h,l; bf16split(v,h,l);
    hi[e]=h; lo[e]=l;
}

__global__ void final_kernel(const float* __restrict__ maxRaw2, const float* __restrict__ mean,
                             const float* __restrict__ rstd, const float* __restrict__ g,
                             float* __restrict__ out, long total, int Mctr)
{
    long e = (long)blockIdx.x*blockDim.x + threadIdx.x;
    if(e>=total) return;
    long bo = e/Mctr;
    float y = fmaxf((maxRaw2[e]-mean[bo])*rstd[bo], 0.f);
    out[e] = __fmul_rn(g[bo], y);
}

// ===================== host-side drivers =====================
static const int HM_SMEM = 65536;

extern "C" void kernel_launch(void* const* d_in, const int* in_sizes, int n_in,
                              void* d_out, int out_size)
{
    const float* p      = (const float*)d_in[0];
    const float* f      = (const float*)d_in[1];
    const float* s0_w1  = (const float*)d_in[2];
    const float* s0_a1w1= (const float*)d_in[3];
    const float* s0_a1w2= (const float*)d_in[4];
    const float* s0_w2  = (const float*)d_in[5];
    const float* s0_a2w1= (const float*)d_in[6];
    const float* s0_a2w2= (const float*)d_in[7];
    const float* s1_w1  = (const float*)d_in[8];
    const float* s1_a1w1= (const float*)d_in[9];
    const float* s1_a1w2= (const float*)d_in[10];
    const float* s1_w2  = (const float*)d_in[11];
    const float* s1_a2w1= (const float*)d_in[12];
    const float* s1_a2w2= (const float*)d_in[13];

    float* out   = (float*)d_out;
    float* o_p   = out;
    float* o_cp1 = out + 98304;
    float* o_cp2 = out + 122880;
    float* o_f   = out + 129024;
    float* o_f1  = out + 227328;
    float* o_f2  = out + 1800192;

    static cudaStream_t s2 = nullptr, s3 = nullptr;
    static cudaEvent_t evRoot=nullptr, evA=nullptr, evG0=nullptr, evG1=nullptr, evS3=nullptr, evJoin=nullptr, evHead=nullptr;
    if(!s2){
        cudaStreamCreate(&s2);
        cudaStreamCreate(&s3);
        cudaEventCreateWithFlags(&evRoot,cudaEventDisableTiming);
        cudaEventCreateWithFlags(&evA,   cudaEventDisableTiming);
        cudaEventCreateWithFlags(&evG0,  cudaEventDisableTiming);
        cudaEventCreateWithFlags(&evG1,  cudaEventDisableTiming);
        cudaEventCreateWithFlags(&evS3,  cudaEventDisableTiming);
        cudaEventCreateWithFlags(&evJoin,cudaEventDisableTiming);
        cudaEventCreateWithFlags(&evHead,cudaEventDisableTiming);
        cudaFuncSetAttribute(fps_part<8192,2048,1,1024>,    cudaFuncAttributeMaxDynamicSharedMemorySize, 8192*16);
        cudaFuncSetAttribute(fps_part<8192,2048,1024,2048>, cudaFuncAttributeMaxDynamicSharedMemorySize, 8192*16);
        cudaFuncSetAttribute(ballq3_kernel<8192,16>, cudaFuncAttributeMaxDynamicSharedMemorySize, 8192*16);
        cudaFuncSetAttribute(hmma_kernel, cudaFuncAttributeMaxDynamicSharedMemorySize, HM_SMEM);
    }

    void *vfeat,*vX,*vX2,*vcf,*vmr,*vmr2,*vp2,*vidx,*vidx1,*vgidx,*vgidx2,*vdd,
         *vmean,*vrstd,*vS,*vg,*vwl,*vwrh,*vwrl,*vw1h,*vw1l;
    cudaGetSymbolAddress(&vfeat, g_feat);
    cudaGetSymbolAddress(&vX,    g_X);
    cudaGetSymbolAddress(&vX2,   g_X2);
    cudaGetSymbolAddress(&vcf,   g_cf);
    cudaGetSymbolAddress(&vmr,   g_maxR);
    cudaGetSymbolAddress(&vmr2,  g_maxR2);
    cudaGetSymbolAddress(&vp2,   g_P2);
    cudaGetSymbolAddress(&vidx,  g_idx);
    cudaGetSymbolAddress(&vidx1, g_idx1);
    cudaGetSymbolAddress(&vgidx, g_gidx);
    cudaGetSymbolAddress(&vgidx2,g_gidx2);
    cudaGetSymbolAddress(&vdd,   g_dd);
    cudaGetSymbolAddress(&vmean, g_mean);
    cudaGetSymbolAddress(&vrstd, g_rstd);
    cudaGetSymbolAddress(&vS,    g_S);
    cudaGetSymbolAddress(&vg,    g_g);
    cudaGetSymbolAddress(&vwl,   g_WL);
    cudaGetSymbolAddress(&vwrh,  g_WRhi);
    cudaGetSymbolAddress(&vwrl,  g_WRlo);
    cudaGetSymbolAddress(&vw1h,  g_W1hi);
    cudaGetSymbolAddress(&vw1l,  g_W1lo);

    float* Xp=(float*)vX; float* X2p=(float*)vX2;
    float* mean=(float*)vmean; float* rstd=(float*)vrstd;
    float* Sp=(float*)vS; float* gA=(float*)vg;

    // ---- root fork: REQUIRED so s2/s3 work is part of the capture graph ----
    cudaEventRecord(evRoot, 0);
    cudaStreamWaitEvent(s2, evRoot, 0);

    // ---- head on s2 (overlaps fps chunk A) ----
    wsplit_kernel<<<(384*256+255)/256,256,0,s2>>>(s1_w1,(__nv_bfloat16*)vw1h,(__nv_bfloat16*)vw1l,
        384, 195, 384, 256);
    cudaMemcpyAsync(o_p,         p,         49152*sizeof(float), cudaMemcpyDeviceToDevice, s2);
    cudaMemcpyAsync(o_p + 49152, p + 49152, 49152*sizeof(float), cudaMemcpyDeviceToDevice, s2);
    cudaMemcpyAsync(o_f,         f,         49152*sizeof(float), cudaMemcpyDeviceToDevice, s2);
    cudaMemcpyAsync(o_f + 49152, f + 49152, 49152*sizeof(float), cudaMemcpyDeviceToDevice, s2);
    cudaEventRecord(evHead, s2);

    // ---------- stage 0: N=8192 -> M=2048, C=3, O=192 (Mpad 256), H=48 ----------
    int N0=8192, M0=2048, C0=3, O0=192, H0=48, Mp0=256, NN0=M0*32;
    fps_part<8192,2048,1,1024><<<B,1024,8192*16>>>(p, (int*)vidx, (float*)vdd);
    cudaEventRecord(evA, 0);
    fps_part<8192,2048,1024,2048><<<B,1024,8192*16>>>(p, (int*)vidx, (float*)vdd);

    // ---- s3: first-half pipeline overlapping fps chunk B ----
    cudaStreamWaitEvent(s3, evA, 0);
    gather_kernel<<<dim3(1024/256,B),256,0,s3>>>(p,f,(int*)vidx,o_cp1,(float*)vcf,N0,M0,C0,0);
    cudaEventRecord(evG0, s3);
    ballq3_kernel<8192,16><<<dim3(1024/16,B),256,8192*16,s3>>>(p,o_cp1,(int*)vgidx,M0,0);
    featbuild_kernel<<<dim3(1024*32/256,B),256,0,s3>>>(p,f,o_cp1,(float*)vcf,(int*)vgidx,(float*)vfeat,N0,M0,C0,0);
    sgemm2_kernel<96,6><<<dim3(1024*32/128,O0/96,B),256,0,s3>>>(s0_w1,0,(float*)vfeat,Xp,
        nullptr,nullptr,nullptr,O0,C0+3,NN0,0);
    cudaEventRecord(evS3, s3);

    // ---- s0: second half ----
    gather_kernel<<<dim3(1024/256,B),256>>>(p,f,(int*)vidx,o_cp1,(float*)vcf,N0,M0,C0,1024);
    cudaEventRecord(evG1, 0);
    ballq3_kernel<8192,16><<<dim3(1024/16,B),256,8192*16>>>(p,o_cp1,(int*)vgidx,M0,1024);
    featbuild_kernel<<<dim3(1024*32/256,B),256>>>(p,f,o_cp1,(float*)vcf,(int*)vgidx,(float*)vfeat,N0,M0,C0,1024);
    sgemm2_kernel<96,6><<<dim3(1024*32/128,O0/96,B),256>>>(s0_w1,0,(float*)vfeat,Xp,
        nullptr,nullptr,nullptr,O0,C0+3,NN0,32768);

    // ---- s2: stage-1 geometry fork (needs full o_cp1) ----
    cudaStreamWaitEvent(s2, evG0, 0);
    cudaStreamWaitEvent(s2, evG1, 0);
    fps_part<2048,512,1,512><<<B,1024,2048*16,s2>>>(o_cp1, (int*)vidx1, (float*)vdd);
    gatherpos_kernel<<<dim3(512/256,B),256,0,s2>>>(o_cp1,(int*)vidx1,o_cp2,2048,512);
    ballq3_kernel<2048,16><<<dim3(512/16,B),256,2048*16,s2>>>(o_cp1,o_cp2,(int*)vgidx2,512,0);
    cudaEventRecord(evJoin, s2);

    // ---- s0: stage-0 GEMM chain (wait for s3 half) ----
    cudaStreamWaitEvent(0, evS3, 0);
    stats2_kernel<<<B*O0,256>>>(Xp, mean, rstd, (float*)vmr, Sp, M0);
    attn_kernel<<<B,384>>>(Sp, s0_a1w1, s0_a1w2, gA, O0, H0, NN0);
    wprep_kernel<<<dim3((Mp0*O0+255)/256,B),256>>>(s0_w2, gA, (float*)vwl,
        (__nv_bfloat16*)vwrh,(__nv_bfloat16*)vwrl, O0, Mp0);
    sgemm2_kernel<96,6><<<dim3(M0/128,O0/96,B),256>>>((float*)vwl,(long)O0*O0,(float*)vmr,(float*)vp2,
        nullptr,mean,rstd,O0,O0,M0,0);
    hmma_kernel<<<dim3(NN0/128,Mp0/128,B),256,HM_SMEM>>>(
        (__nv_bfloat16*)vwrh,(__nv_bfloat16*)vwrl,(long)Mp0*O0,O0,
        Xp,mean,rstd,(float*)vp2,X2p,O0,O0,NN0);
    stats2_kernel<<<B*O0,256>>>(X2p, mean, rstd, (float*)vmr2, Sp, M0);
    attn_kernel<<<B,384>>>(Sp, s0_a2w1, s0_a2w2, gA, O0, H0, NN0);
    final_kernel<<<(int)(((long)B*O0*M0+255)/256),256>>>((float*)vmr2, mean, rstd, gA, o_f1, (long)B*O0*M0, M0);

    // ---------- stage 1: N=2048 -> M=512, C=192, O=384 (Mpad 384), H=96 ----------
    {
        int N=2048, M=512, C=192, O=384, H=96, Mpad=384, NN=M*32;
        cudaStreamWaitEvent(0, evJoin, 0);
        cudaStreamWaitEvent(0, evHead, 0);   // wsplit (W1hi/lo) + memcpys joined
        gatherfeat_kernel<<<dim3(M/256,B),256>>>(o_f1,(int*)vidx1,(float*)vcf,N,M,C);
        featbuild_kernel<<<dim3(M*32/256,B),256>>>(o_cp1,o_f1,o_cp2,(float*)vcf,(int*)vgidx2,(float*)vfeat,N,M,C,0);
        hmma_kernel<<<dim3(NN/128,Mpad/128,B),256,HM_SMEM>>>(
            (__nv_bfloat16*)vw1h,(__nv_bfloat16*)vw1l,0,256,
            (float*)vfeat,nullptr,nullptr,nullptr,Xp,O,C+3,NN);
        stats2_kernel<<<B*O,256>>>(Xp, mean, rstd, (float*)vmr, Sp, M);
        attn_kernel<<<B,384>>>(Sp, s1_a1w1, s1_a1w2, gA, O, H, NN);
        wprep_kernel<<<dim3((Mpad*O+255)/256,B),256>>>(s1_w2, gA, (float*)vwl,
            (__nv_bfloat16*)vwrh,(__nv_bfloat16*)vwrl, O, Mpad);
        sgemm2_kernel<128,8><<<dim3(M/128,O/128,B),256>>>((float*)vwl,(long)O*O,(float*)vmr,(float*)vp2,
            nullptr,mean,rstd,O,O,M,0);
        hmma_kernel<<<dim3(NN/128,Mpad/128,B),256,HM_SMEM>>>(
            (__nv_bfloat16*)vwrh,(__nv_bfloat16*)vwrl,(long)Mpad*O,O,
            Xp,mean,rstd,(float*)vp2,X2p,O,O,NN);
        stats2_kernel<<<B*O,256>>>(X2p, mean, rstd, (float*)vmr2, Sp, M);
        attn_kernel<<<B,384>>>(Sp, s1_a2w1, s1_a2w2, gA, O, H, NN);
        final_kernel<<<(int)(((long)B*O*M+255)/256),256>>>((float*)vmr2, mean, rstd, gA, o_f2, (long)B*O*M, M);
    }
}